// round 8
// baseline (speedup 1.0000x reference)
#include <cuda_runtime.h>
#include <cuda_bf16.h>
#include <math.h>
#include <stdint.h>

// Problem constants
#define BATCH 2
#define SEQ   2048
#define NH    32
#define HD    128
#define HID   4096           // NH*HD
#define QKVN  12288          // 3*HID
#define MTOK  (BATCH*SEQ)    // 4096 tokens

// GEMM tile config (mma.sync m16n8k8 tf32, ldmatrix fragments)
#define BM 128
#define BN 256
#define BK 32
#define STAGES 3
#define TSTRIDE 36
#define A_TILE_BYTES (128 * TSTRIDE * 4)         // 18432
#define B_TILE_BYTES (256 * TSTRIDE * 4)         // 36864
#define STAGE_BYTES (A_TILE_BYTES + B_TILE_BYTES)// 55296
#define GEMM_SMEM (STAGES * STAGE_BYTES)         // 165888

// Attention smem layout
#define QS_STRIDE 132
#define VS_STRIDE 68
#define AQS_OFF 0
#define AKS_OFF (128 * QS_STRIDE * 4)
#define AVT_OFF (AKS_OFF + 64 * QS_STRIDE * 4)
#define APS_OFF (AVT_OFF + 128 * VS_STRIDE * 4)
#define ATT_SMEM (APS_OFF + 128 * VS_STRIDE * 4) // 171008

// ---------------- scratch (device globals) -------------
__device__ float g_qkv[(size_t)MTOK * QKVN];
__device__ float g_q[(size_t)MTOK * HID];
__device__ float g_k[(size_t)MTOK * HID];
__device__ float g_vt[(size_t)BATCH * NH * HD * SEQ];
__device__ float g_ctx[(size_t)MTOK * HID];
__device__ float g_hidr[(size_t)MTOK * HID];
#define WR_VQ 0
#define WR_LQ ((size_t)HID * QKVN)
#define WR_VD (2 * (size_t)HID * QKVN)
#define WR_LD (2 * (size_t)HID * QKVN + (size_t)HID * HID)
__device__ float g_wr[2 * (size_t)HID * QKVN + 2 * (size_t)HID * HID];
__device__ int   g_cnt[2];
__device__ int   g_idx[2][MTOK];

// ---------------- helpers ----------------
__device__ __forceinline__ uint32_t smem_u32(const void* p) {
    uint32_t a;
    asm("{ .reg .u64 t; cvta.to.shared.u64 t, %1; cvt.u32.u64 %0, t; }" : "=r"(a) : "l"(p));
    return a;
}
__device__ __forceinline__ void cp16(uint32_t dst, const void* src) {
    asm volatile("cp.async.cg.shared.global [%0], [%1], 16;" :: "r"(dst), "l"(src));
}
__device__ __forceinline__ void cp_commit() {
    asm volatile("cp.async.commit_group;" ::: "memory");
}
template <int N>
__device__ __forceinline__ void cp_wait() {
    asm volatile("cp.async.wait_group %0;" :: "n"(N) : "memory");
}
__device__ __forceinline__ uint32_t f2tf32(float f) {
    uint32_t r;
    asm("cvt.rna.tf32.f32 %0, %1;" : "=r"(r) : "f"(f));
    return r;
}
__device__ __forceinline__ float tf32r(float f) { return __uint_as_float(f2tf32(f)); }
__device__ __forceinline__ void mma_tf32(float* c, uint32_t a0, uint32_t a1, uint32_t a2, uint32_t a3,
                                         uint32_t b0, uint32_t b1) {
    asm volatile(
        "mma.sync.aligned.m16n8k8.row.col.f32.tf32.tf32.f32 "
        "{%0,%1,%2,%3}, {%4,%5,%6,%7}, {%8,%9}, {%0,%1,%2,%3};"
        : "+f"(c[0]), "+f"(c[1]), "+f"(c[2]), "+f"(c[3])
        : "r"(a0), "r"(a1), "r"(a2), "r"(a3), "r"(b0), "r"(b1));
}
#define LDSM4(r0, r1, r2, r3, addr)                                               \
    asm volatile("ldmatrix.sync.aligned.m8n8.x4.shared.b16 {%0,%1,%2,%3}, [%4];"   \
        : "=r"(r0), "=r"(r1), "=r"(r2), "=r"(r3) : "r"(addr))

// ---------------- pre-passes ----------------
__global__ __launch_bounds__(256)
void round_tf32_kernel(const float4* __restrict__ in, float4* __restrict__ out, int n4) {
    int i = blockIdx.x * blockDim.x + threadIdx.x;
    if (i >= n4) return;
    float4 v = in[i];
    out[i] = make_float4(tf32r(v.x), tf32r(v.y), tf32r(v.z), tf32r(v.w));
}
__global__ __launch_bounds__(256)
void trp_round_kernel(const float* __restrict__ W, float* __restrict__ Wt, int N) {
    __shared__ float t[32][33];
    int bx = blockIdx.x * 32;
    int by = blockIdx.y * 32;
    int x = threadIdx.x & 31;
    int y = threadIdx.x >> 5;
#pragma unroll
    for (int i = 0; i < 32; i += 8)
        t[y + i][x] = W[(size_t)(by + y + i) * N + bx + x];
    __syncthreads();
#pragma unroll
    for (int i = 0; i < 32; i += 8)
        Wt[(size_t)(bx + y + i) * HID + by + x] = tf32r(t[x][y + i]);
}
__global__ __launch_bounds__(256)
void vtrans_kernel(const float* __restrict__ qkv, float* __restrict__ Vt) {
    __shared__ float t[32][33];
    int bh = blockIdx.z;
    int b = bh >> 5, h = bh & 31;
    int s0 = blockIdx.x * 32;
    int d0 = blockIdx.y * 32;
    int x = threadIdx.x & 31;
    int y = threadIdx.x >> 5;
#pragma unroll
    for (int i = 0; i < 32; i += 8)
        t[y + i][x] = qkv[(size_t)(b * SEQ + s0 + y + i) * QKVN + 2 * HID + h * HD + d0 + x];
    __syncthreads();
#pragma unroll
    for (int i = 0; i < 32; i += 8)
        Vt[((size_t)bh * HD + d0 + y + i) * SEQ + s0 + x] = tf32r(t[x][y + i]);
}

// ---------------- mask / routing ----------------
__global__ void zero_cnt_kernel() {
    if (threadIdx.x < 2) g_cnt[threadIdx.x] = 0;
}
__global__ void route_kernel(const int* __restrict__ tt) {
    int idx = blockIdx.x * blockDim.x + threadIdx.x;
    if (idx >= MTOK) return;
    int s = idx & (SEQ - 1);
    int vis = (s + 1 < SEQ) && (tt[idx] == 1) && (tt[idx + 1] == 1);
    int e = vis ? 0 : 1;
    int pos = atomicAdd(&g_cnt[e], 1);
    g_idx[e][pos] = idx;
}

// ---------------- tensor-core tf32 GEMM: 128x256 tile, warp tile 64x64 ----------------
__global__ __launch_bounds__(256, 1)
void gemm_tc(const float* __restrict__ A, const float* __restrict__ Wt,
             float* __restrict__ C, int N,
             const int* __restrict__ idx, const int* __restrict__ cnt_ptr) {
    __shared__ int idx_s[BM];
    extern __shared__ char smem[];
    const uint32_t sb = smem_u32(smem);
    const int tid = threadIdx.x;
    const int wid = tid >> 5;
    const int lane = tid & 31;
    const int lm = lane >> 2;
    const int lq = lane & 3;
    const int warp_m = wid & 1;   // 0..1 -> 64 rows
    const int warp_n = wid >> 1;  // 0..3 -> 64 cols
    const int m0 = blockIdx.x * BM;
    const int n0 = blockIdx.y * BN;

    const int count = __ldg(cnt_ptr);
    if (m0 >= count) return;

    if (tid < BM) {
        int mp = m0 + tid;
        idx_s[tid] = idx[mp < count ? mp : count - 1];
    }
    __syncthreads();

    // A loader: 128 rows x 8 granules = 1024 -> 4/thread
    int a_r[4], a_c[4];
#pragma unroll
    for (int i = 0; i < 4; i++) {
        int t = tid + i * 256;
        a_r[i] = t >> 3;
        a_c[i] = t & 7;
    }
    int a_g[4];
#pragma unroll
    for (int i = 0; i < 4; i++) a_g[i] = idx_s[a_r[i]];
    // B loader: 256 rows x 8 granules = 2048 -> 8/thread
    int b_r[8], b_c[8];
#pragma unroll
    for (int i = 0; i < 8; i++) {
        int t = tid + i * 256;
        b_r[i] = t >> 3;
        b_c[i] = t & 7;
    }

    const float* Bt = Wt + (size_t)n0 * HID;

    auto load_stage = [&](int stage, int chunk) {
        uint32_t as = sb + stage * STAGE_BYTES;
        uint32_t bs = as + A_TILE_BYTES;
#pragma unroll
        for (int i = 0; i < 4; i++)
            cp16(as + a_r[i] * (TSTRIDE * 4) + a_c[i] * 16,
                 A + (size_t)a_g[i] * HID + chunk * BK + a_c[i] * 4);
#pragma unroll
        for (int i = 0; i < 8; i++)
            cp16(bs + b_r[i] * (TSTRIDE * 4) + b_c[i] * 16,
                 Bt + (size_t)b_r[i] * HID + chunk * BK + b_c[i] * 4);
    };

    const int a_row = (lane & 7) | (lane & 8);
    const int a_ko  = (lane >> 4) * 4;
    const int b_row = (lane & 7) | ((lane >> 1) & 8);
    const int b_ko  = ((lane >> 3) & 1) * 4;
    const uint32_t a_off = (warp_m * 64 + a_row) * (TSTRIDE * 4) + a_ko * 4;
    const uint32_t b_off = (warp_n * 64 + b_row) * (TSTRIDE * 4) + b_ko * 4;

    float c[4][8][4];
#pragma unroll
    for (int mt = 0; mt < 4; mt++)
#pragma unroll
        for (int nt = 0; nt < 8; nt++)
#pragma unroll
            for (int j = 0; j < 4; j++) c[mt][nt][j] = 0.f;

    const int NC = HID / BK;

    load_stage(0, 0); cp_commit();
    load_stage(1, 1); cp_commit();

    for (int ch = 0; ch < NC; ch++) {
        cp_wait<1>();
        __syncthreads();

        if (ch + 2 < NC) load_stage((ch + 2) % STAGES, ch + 2);
        cp_commit();

        const uint32_t as = sb + (ch % STAGES) * STAGE_BYTES;
        const uint32_t bs = as + A_TILE_BYTES;
        const uint32_t aL = as + a_off;
        const uint32_t bL = bs + b_off;

#pragma unroll
        for (int kk = 0; kk < BK; kk += 8) {
            uint32_t af[4][4], bf[8][2];
#pragma unroll
            for (int mt = 0; mt < 4; mt++)
                LDSM4(af[mt][0], af[mt][1], af[mt][2], af[mt][3],
                      aL + mt * 16 * (TSTRIDE * 4) + kk * 4);
#pragma unroll
            for (int pr = 0; pr < 4; pr++)
                LDSM4(bf[2 * pr][0], bf[2 * pr][1], bf[2 * pr + 1][0], bf[2 * pr + 1][1],
                      bL + pr * 16 * (TSTRIDE * 4) + kk * 4);
#pragma unroll
            for (int mt = 0; mt < 4; mt++)
#pragma unroll
                for (int nt = 0; nt < 8; nt++)
                    mma_tf32(c[mt][nt], af[mt][0], af[mt][1], af[mt][2], af[mt][3],
                             bf[nt][0], bf[nt][1]);
        }
        __syncthreads();
    }

    // epilogue: scatter to true rows; skip padding rows
#pragma unroll
    for (int mt = 0; mt < 4; mt++) {
        int r0 = warp_m * 64 + mt * 16 + lm;
        int r1 = r0 + 8;
        bool on0 = (m0 + r0 < count);
        bool on1 = (m0 + r1 < count);
        float* p0 = C + (size_t)idx_s[r0] * N + n0 + warp_n * 64;
        float* p1 = C + (size_t)idx_s[r1] * N + n0 + warp_n * 64;
#pragma unroll
        for (int nt = 0; nt < 8; nt++) {
            int col = nt * 8 + 2 * lq;
            if (on0) *(float2*)(p0 + col) = make_float2(c[mt][nt][0], c[mt][nt][1]);
            if (on1) *(float2*)(p1 + col) = make_float2(c[mt][nt][2], c[mt][nt][3]);
        }
    }
}

// ---------------- RoPE: q scaled by 1/sqrt(HD), q/k tf32-rounded ----------------
__global__ void rope_kernel(const float* __restrict__ qkv, const int* __restrict__ pos_ids,
                            float* __restrict__ q, float* __restrict__ k) {
    int idx = blockIdx.x * blockDim.x + threadIdx.x;
    if (idx >= MTOK * NH * 64) return;
    int i = idx & 63;
    int h = (idx >> 6) & 31;
    int m = idx >> 11;

    float pos = (float)pos_ids[m];
    float freq = expf(-(float)i * (9.210340371976184f / 64.f));
    float ang = pos * freq;
    float cv = cosf(ang);
    float sv = sinf(ang);
    const float scale = 0.088388347648318447f;

    const float* qs = qkv + (size_t)m * QKVN + h * HD;
    const float* ks = qs + HID;
    float q0 = qs[i], q1 = qs[i + 64];
    float k0 = ks[i], k1 = ks[i + 64];

    size_t o = (size_t)m * HID + h * HD;
    q[o + i]      = tf32r((q0 * cv - q1 * sv) * scale);
    q[o + i + 64] = tf32r((q1 * cv + q0 * sv) * scale);
    k[o + i]      = tf32r(k0 * cv - k1 * sv);
    k[o + i + 64] = tf32r(k1 * cv + k0 * sv);
}

// ---------------- tensor-core flash attention (unchanged from round 7) ----------------
__global__ __launch_bounds__(256)
void attn_mma(const float* __restrict__ Q, const float* __restrict__ Kg,
              const float* __restrict__ Vt, float* __restrict__ ctx) {
    extern __shared__ char smem[];
    const uint32_t sb = smem_u32(smem);
    const int tid = threadIdx.x;
    const int warp = tid >> 5;
    const int lane = tid & 31;
    const int lm = lane >> 2;
    const int lq = lane & 3;
    const int b = blockIdx.z;
    const int h = blockIdx.y;
    const int qi = (int)gridDim.x - 1 - (int)blockIdx.x;
    const int qb = qi * 128;

#pragma unroll
    for (int i = 0; i < 16; i++) {
        int g = tid + i * 256;
        int r = g >> 5, c = g & 31;
        cp16(sb + AQS_OFF + r * (QS_STRIDE * 4) + c * 16,
             Q + (size_t)(b * SEQ + qb + r) * HID + h * HD + c * 4);
    }
    cp_commit();

    const int a_row = lane & 15;
    const int a_ko  = (lane >> 4) * 4;
    const int b_row = (lane & 7) | ((lane >> 1) & 8);
    const int b_ko  = ((lane >> 3) & 1) * 4;
    const uint32_t qA = sb + AQS_OFF + (warp * 16 + a_row) * (QS_STRIDE * 4) + a_ko * 4;
    const uint32_t pA = sb + APS_OFF + (warp * 16 + a_row) * (VS_STRIDE * 4) + a_ko * 4;
    const uint32_t kB = sb + AKS_OFF + b_row * (QS_STRIDE * 4) + b_ko * 4;
    const uint32_t vB = sb + AVT_OFF + b_row * (VS_STRIDE * 4) + b_ko * 4;

    float o[16][4];
#pragma unroll
    for (int nt = 0; nt < 16; nt++)
#pragma unroll
        for (int j = 0; j < 4; j++) o[nt][j] = 0.f;
    float mr0 = -1e30f, mr1 = -1e30f, l0 = 0.f, l1 = 0.f;
    const int r0g = qb + warp * 16 + lm;
    const int r1g = r0g + 8;

    const int ntiles = 2 * qi + 2;
    for (int t = 0; t < ntiles; t++) {
#pragma unroll
        for (int i = 0; i < 8; i++) {
            int g = tid + i * 256;
            int r = g >> 5, c = g & 31;
            cp16(sb + AKS_OFF + r * (QS_STRIDE * 4) + c * 16,
                 Kg + (size_t)(b * SEQ + t * 64 + r) * HID + h * HD + c * 4);
        }
#pragma unroll
        for (int i = 0; i < 8; i++) {
            int g = tid + i * 256;
            int r = g >> 4, c = g & 15;
            cp16(sb + AVT_OFF + r * (VS_STRIDE * 4) + c * 16,
                 Vt + ((size_t)(b * NH + h) * HD + r) * SEQ + t * 64 + c * 4);
        }
        cp_commit();
        cp_wait<0>();
        __syncthreads();

        float s_[8][4];
#pragma unroll
        for (int nt = 0; nt < 8; nt++)
#pragma unroll
            for (int j = 0; j < 4; j++) s_[nt][j] = 0.f;

#pragma unroll
        for (int ks = 0; ks < 16; ks++) {
            uint32_t a0, a1, a2, a3;
            LDSM4(a0, a1, a2, a3, qA + ks * 32);
#pragma unroll
            for (int pr = 0; pr < 4; pr++) {
                uint32_t b0, b1, b2, b3;
                LDSM4(b0, b1, b2, b3, kB + pr * 16 * (QS_STRIDE * 4) + ks * 32);
                mma_tf32(s_[2 * pr],     a0, a1, a2, a3, b0, b1);
                mma_tf32(s_[2 * pr + 1], a0, a1, a2, a3, b2, b3);
            }
        }

        if (t >= 2 * qi) {
#pragma unroll
            for (int nt = 0; nt < 8; nt++) {
                int cb = t * 64 + nt * 8 + 2 * lq;
                if (cb > r0g)     s_[nt][0] = -1e30f;
                if (cb + 1 > r0g) s_[nt][1] = -1e30f;
                if (cb > r1g)     s_[nt][2] = -1e30f;
                if (cb + 1 > r1g) s_[nt][3] = -1e30f;
            }
        }

        float tm0 = -1e30f, tm1 = -1e30f;
#pragma unroll
        for (int nt = 0; nt < 8; nt++) {
            tm0 = fmaxf(tm0, fmaxf(s_[nt][0], s_[nt][1]));
            tm1 = fmaxf(tm1, fmaxf(s_[nt][2], s_[nt][3]));
        }
        tm0 = fmaxf(tm0, __shfl_xor_sync(0xffffffffu, tm0, 1));
        tm0 = fmaxf(tm0, __shfl_xor_sync(0xffffffffu, tm0, 2));
        tm1 = fmaxf(tm1, __shfl_xor_sync(0xffffffffu, tm1, 1));
        tm1 = fmaxf(tm1, __shfl_xor_sync(0xffffffffu, tm1, 2));
        float mn0 = fmaxf(mr0, tm0), mn1 = fmaxf(mr1, tm1);
        float c0 = __expf(mr0 - mn0), c1 = __expf(mr1 - mn1);
        float ps0 = 0.f, ps1 = 0.f;
#pragma unroll
        for (int nt = 0; nt < 8; nt++) {
            s_[nt][0] = __expf(s_[nt][0] - mn0);
            s_[nt][1] = __expf(s_[nt][1] - mn0);
            s_[nt][2] = __expf(s_[nt][2] - mn1);
            s_[nt][3] = __expf(s_[nt][3] - mn1);
            ps0 += s_[nt][0] + s_[nt][1];
            ps1 += s_[nt][2] + s_[nt][3];
        }
        l0 = l0 * c0 + ps0;
        l1 = l1 * c1 + ps1;
#pragma unroll
        for (int nt = 0; nt < 16; nt++) {
            o[nt][0] *= c0; o[nt][1] *= c0;
            o[nt][2] *= c1; o[nt][3] *= c1;
        }
        mr0 = mn0; mr1 = mn1;

#pragma unroll
        for (int nt = 0; nt < 8; nt++) {
            *(float2*)(smem + APS_OFF + (warp * 16 + lm) * (VS_STRIDE * 4) + (nt * 8 + 2 * lq) * 4)
                = make_float2(tf32r(s_[nt][0]), tf32r(s_[nt][1]));
            *(float2*)(smem + APS_OFF + (warp * 16 + lm + 8) * (VS_STRIDE * 4) + (nt * 8 + 2 * lq) * 4)
                = make_float2(tf32r(s_[nt][2]), tf32r(s_[nt][3]));
        }
        __syncwarp();

#pragma unroll
        for (int ks = 0; ks < 8; ks++) {
            uint32_t a0, a1, a2, a3;
            LDSM4(a0, a1, a2, a3, pA + ks * 32);
#pragma unroll
            for (int pr = 0; pr < 8; pr++) {
                uint32_t b0, b1, b2, b3;
                LDSM4(b0, b1, b2, b3, vB + pr * 16 * (VS_STRIDE * 4) + ks * 32);
                mma_tf32(o[2 * pr],     a0, a1, a2, a3, b0, b1);
                mma_tf32(o[2 * pr + 1], a0, a1, a2, a3, b2, b3);
            }
        }
        __syncthreads();
    }

    l0 += __shfl_xor_sync(0xffffffffu, l0, 1);
    l0 += __shfl_xor_sync(0xffffffffu, l0, 2);
    l1 += __shfl_xor_sync(0xffffffffu, l1, 1);
    l1 += __shfl_xor_sync(0xffffffffu, l1, 2);
    float i0 = 1.f / l0, i1 = 1.f / l1;

#pragma unroll
    for (int nt = 0; nt < 16; nt++) {
        int col = nt * 8 + 2 * lq;
        *(float2*)&ctx[(size_t)(b * SEQ + r0g) * HID + h * HD + col] =
            make_float2(tf32r(o[nt][0] * i0), tf32r(o[nt][1] * i0));
        *(float2*)&ctx[(size_t)(b * SEQ + r1g) * HID + h * HD + col] =
            make_float2(tf32r(o[nt][2] * i1), tf32r(o[nt][3] * i1));
    }
}

// ---------------- launch ----------------
extern "C" void kernel_launch(void* const* d_in, const int* in_sizes, int n_in,
                              void* d_out, int out_size) {
    const float* hidden = (const float*)d_in[0];
    const int*   tt     = (const int*)d_in[1];
    const int*   pos    = (const int*)d_in[2];
    const float* wvq    = (const float*)d_in[3];
    const float* wlq    = (const float*)d_in[4];
    const float* wvd    = (const float*)d_in[5];
    const float* wld    = (const float*)d_in[6];
    float* out = (float*)d_out;

    float *qkv_p, *q_p, *k_p, *vt_p, *ctx_p, *hidr_p, *wr_p;
    int *cnt_p, *idx_p;
    cudaGetSymbolAddress((void**)&qkv_p, g_qkv);
    cudaGetSymbolAddress((void**)&q_p, g_q);
    cudaGetSymbolAddress((void**)&k_p, g_k);
    cudaGetSymbolAddress((void**)&vt_p, g_vt);
    cudaGetSymbolAddress((void**)&ctx_p, g_ctx);
    cudaGetSymbolAddress((void**)&hidr_p, g_hidr);
    cudaGetSymbolAddress((void**)&wr_p, g_wr);
    cudaGetSymbolAddress((void**)&cnt_p, g_cnt);
    cudaGetSymbolAddress((void**)&idx_p, g_idx);

    const int* cnt_vis  = cnt_p;
    const int* cnt_lang = cnt_p + 1;
    const int* idx_vis  = idx_p;
    const int* idx_lang = idx_p + MTOK;

    float* wr_vq = wr_p + WR_VQ;
    float* wr_lq = wr_p + WR_LQ;
    float* wr_vd = wr_p + WR_VD;
    float* wr_ld = wr_p + WR_LD;

    cudaFuncSetAttribute(gemm_tc, cudaFuncAttributeMaxDynamicSharedMemorySize, GEMM_SMEM);
    cudaFuncSetAttribute(attn_mma, cudaFuncAttributeMaxDynamicSharedMemorySize, ATT_SMEM);

    zero_cnt_kernel<<<1, 32>>>();
    route_kernel<<<MTOK / 256, 256>>>(tt);

    {
        dim3 g1(QKVN / 32, HID / 32);
        trp_round_kernel<<<g1, 256>>>(wvq, wr_vq, QKVN);
        trp_round_kernel<<<g1, 256>>>(wlq, wr_lq, QKVN);
        dim3 g2(HID / 32, HID / 32);
        trp_round_kernel<<<g2, 256>>>(wvd, wr_vd, HID);
        trp_round_kernel<<<g2, 256>>>(wld, wr_ld, HID);
        int n4h = (int)((size_t)MTOK * HID / 4);
        round_tf32_kernel<<<(n4h + 255) / 256, 256>>>((const float4*)hidden, (float4*)hidr_p, n4h);
    }

    // QKV projection per expert over gathered rows
    {
        dim3 grid(MTOK / BM, QKVN / BN);
        gemm_tc<<<grid, 256, GEMM_SMEM>>>(hidr_p, wr_vq, qkv_p, QKVN, idx_vis, cnt_vis);
        gemm_tc<<<grid, 256, GEMM_SMEM>>>(hidr_p, wr_lq, qkv_p, QKVN, idx_lang, cnt_lang);
    }

    // RoPE + V transpose
    rope_kernel<<<(MTOK * NH * 64) / 256, 256>>>(qkv_p, pos, q_p, k_p);
    {
        dim3 gv(SEQ / 32, HD / 32, BATCH * NH);
        vtrans_kernel<<<gv, 256>>>(qkv_p, vt_p);
    }

    // Tensor-core flash attention
    {
        dim3 grid(SEQ / 128, NH, BATCH);
        attn_mma<<<grid, 256, ATT_SMEM>>>(q_p, k_p, vt_p, ctx_p);
    }

    // Dense projection per expert
    {
        dim3 grid(MTOK / BM, HID / BN);
        gemm_tc<<<grid, 256, GEMM_SMEM>>>(ctx_p, wr_vd, out, HID, idx_vis, cnt_vis);
        gemm_tc<<<grid, 256, GEMM_SMEM>>>(ctx_p, wr_ld, out, HID, idx_lang, cnt_lang);
    }
}

// round 9
// speedup vs baseline: 1.8386x; 1.8386x over previous
#include <cuda_runtime.h>
#include <cuda_fp16.h>
#include <math.h>
#include <stdint.h>

// Problem constants
#define BATCH 2
#define SEQ   2048
#define NH    32
#define HD    128
#define HID   4096           // NH*HD
#define QKVN  12288          // 3*HID
#define MTOK  (BATCH*SEQ)    // 4096 tokens

// GEMM tile config (mma.sync m16n8k16 fp16)
#define BM 128
#define BN 256
#define BK 64
#define STAGES 3
#define TROWB 144                                // bytes per smem row (64 fp16 + pad)
#define A_TILE_BYTES (128 * TROWB)               // 18432
#define B_TILE_BYTES (256 * TROWB)               // 36864
#define STAGE_BYTES (A_TILE_BYTES + B_TILE_BYTES)// 55296
#define GEMM_SMEM (STAGES * STAGE_BYTES)         // 165888

// Attention smem layout (fp16)
#define QROWB 272                                // 128 fp16 + pad
#define VROWB 144                                // 64 fp16 + pad
#define AQS_OFF 0
#define AKS_OFF (128 * QROWB)                    // 34816
#define AVT_OFF (AKS_OFF + 64 * QROWB)           // 52224
#define APS_OFF (AVT_OFF + 128 * VROWB)          // 70656
#define ATT_SMEM (APS_OFF + 128 * VROWB)         // 89088

// ---------------- scratch (device globals) -------------
__device__ float  g_qkv[(size_t)MTOK * QKVN];        // fp32 qkv projection
__device__ __half g_q[(size_t)MTOK * HID];           // roped*scale fp16
__device__ __half g_k[(size_t)MTOK * HID];           // roped fp16
__device__ __half g_vt[(size_t)BATCH * NH * HD * SEQ];// transposed V fp16
__device__ __half g_ctx[(size_t)MTOK * HID];         // attention out fp16
__device__ __half g_hidh[(size_t)MTOK * HID];        // fp16 hidden
#define WR_VQ 0
#define WR_LQ ((size_t)HID * QKVN)
#define WR_VD (2 * (size_t)HID * QKVN)
#define WR_LD (2 * (size_t)HID * QKVN + (size_t)HID * HID)
__device__ __half g_wr[2 * (size_t)HID * QKVN + 2 * (size_t)HID * HID];
__device__ int    g_cnt[2];
__device__ int    g_idx[2][MTOK];

// ---------------- helpers ----------------
__device__ __forceinline__ uint32_t smem_u32(const void* p) {
    uint32_t a;
    asm("{ .reg .u64 t; cvta.to.shared.u64 t, %1; cvt.u32.u64 %0, t; }" : "=r"(a) : "l"(p));
    return a;
}
__device__ __forceinline__ void cp16(uint32_t dst, const void* src) {
    asm volatile("cp.async.cg.shared.global [%0], [%1], 16;" :: "r"(dst), "l"(src));
}
__device__ __forceinline__ void cp_commit() {
    asm volatile("cp.async.commit_group;" ::: "memory");
}
template <int N>
__device__ __forceinline__ void cp_wait() {
    asm volatile("cp.async.wait_group %0;" :: "n"(N) : "memory");
}
__device__ __forceinline__ void mma_f16(float* c, uint32_t a0, uint32_t a1, uint32_t a2, uint32_t a3,
                                        uint32_t b0, uint32_t b1) {
    asm volatile(
        "mma.sync.aligned.m16n8k16.row.col.f32.f16.f16.f32 "
        "{%0,%1,%2,%3}, {%4,%5,%6,%7}, {%8,%9}, {%0,%1,%2,%3};"
        : "+f"(c[0]), "+f"(c[1]), "+f"(c[2]), "+f"(c[3])
        : "r"(a0), "r"(a1), "r"(a2), "r"(a3), "r"(b0), "r"(b1));
}
#define LDSM4(r0, r1, r2, r3, addr)                                               \
    asm volatile("ldmatrix.sync.aligned.m8n8.x4.shared.b16 {%0,%1,%2,%3}, [%4];"   \
        : "=r"(r0), "=r"(r1), "=r"(r2), "=r"(r3) : "r"(addr))

// ---------------- pre-passes ----------------
// fp32 -> fp16 convert (hidden)
__global__ __launch_bounds__(256)
void f2h_kernel(const float4* __restrict__ in, __half2* __restrict__ out, int n4) {
    int i = blockIdx.x * blockDim.x + threadIdx.x;
    if (i >= n4) return;
    float4 v = in[i];
    out[2 * i]     = __floats2half2_rn(v.x, v.y);
    out[2 * i + 1] = __floats2half2_rn(v.z, v.w);
}
// transpose + fp16: W[K=HID][N] -> Wt[N][HID] fp16
__global__ __launch_bounds__(256)
void trp_h_kernel(const float* __restrict__ W, __half* __restrict__ Wt, int N) {
    __shared__ float t[32][33];
    int bx = blockIdx.x * 32;
    int by = blockIdx.y * 32;
    int x = threadIdx.x & 31;
    int y = threadIdx.x >> 5;
#pragma unroll
    for (int i = 0; i < 32; i += 8)
        t[y + i][x] = W[(size_t)(by + y + i) * N + bx + x];
    __syncthreads();
#pragma unroll
    for (int i = 0; i < 32; i += 8)
        Wt[(size_t)(bx + y + i) * HID + by + x] = __float2half(t[x][y + i]);
}
// V transpose to fp16: g_vt[bh][d][s]
__global__ __launch_bounds__(256)
void vtrans_kernel(const float* __restrict__ qkv, __half* __restrict__ Vt) {
    __shared__ float t[32][33];
    int bh = blockIdx.z;
    int b = bh >> 5, h = bh & 31;
    int s0 = blockIdx.x * 32;
    int d0 = blockIdx.y * 32;
    int x = threadIdx.x & 31;
    int y = threadIdx.x >> 5;
#pragma unroll
    for (int i = 0; i < 32; i += 8)
        t[y + i][x] = qkv[(size_t)(b * SEQ + s0 + y + i) * QKVN + 2 * HID + h * HD + d0 + x];
    __syncthreads();
#pragma unroll
    for (int i = 0; i < 32; i += 8)
        Vt[((size_t)bh * HD + d0 + y + i) * SEQ + s0 + x] = __float2half(t[x][y + i]);
}

// ---------------- mask / routing ----------------
__global__ void zero_cnt_kernel() {
    if (threadIdx.x < 2) g_cnt[threadIdx.x] = 0;
}
__global__ void route_kernel(const int* __restrict__ tt) {
    int idx = blockIdx.x * blockDim.x + threadIdx.x;
    if (idx >= MTOK) return;
    int s = idx & (SEQ - 1);
    int vis = (s + 1 < SEQ) && (tt[idx] == 1) && (tt[idx + 1] == 1);
    int e = vis ? 0 : 1;
    int pos = atomicAdd(&g_cnt[e], 1);
    g_idx[e][pos] = idx;
}

// ---------------- fp16 tensor-core GEMM: 128x256 tile, warp 64x64, BK=64 ----------------
__global__ __launch_bounds__(256, 1)
void gemm_tc(const __half* __restrict__ A, const __half* __restrict__ Wt,
             float* __restrict__ C, int N,
             const int* __restrict__ idx, const int* __restrict__ cnt_ptr) {
    __shared__ int idx_s[BM];
    extern __shared__ char smem[];
    const uint32_t sb = smem_u32(smem);
    const int tid = threadIdx.x;
    const int wid = tid >> 5;
    const int lane = tid & 31;
    const int lm = lane >> 2;
    const int lq = lane & 3;
    const int warp_m = wid & 1;
    const int warp_n = wid >> 1;
    const int m0 = blockIdx.x * BM;
    const int n0 = blockIdx.y * BN;

    const int count = __ldg(cnt_ptr);
    if (m0 >= count) return;

    if (tid < BM) {
        int mp = m0 + tid;
        idx_s[tid] = idx[mp < count ? mp : count - 1];
    }
    __syncthreads();

    // A loader: 128 rows x 8 granules(16B=8 fp16) -> 4/thread
    int a_r[4], a_c[4];
#pragma unroll
    for (int i = 0; i < 4; i++) {
        int t = tid + i * 256;
        a_r[i] = t >> 3;
        a_c[i] = t & 7;
    }
    int a_g[4];
#pragma unroll
    for (int i = 0; i < 4; i++) a_g[i] = idx_s[a_r[i]];
    // B loader: 256 rows x 8 granules -> 8/thread
    int b_r[8], b_c[8];
#pragma unroll
    for (int i = 0; i < 8; i++) {
        int t = tid + i * 256;
        b_r[i] = t >> 3;
        b_c[i] = t & 7;
    }

    const __half* Bt = Wt + (size_t)n0 * HID;

    auto load_stage = [&](int stage, int chunk) {
        uint32_t as = sb + stage * STAGE_BYTES;
        uint32_t bs = as + A_TILE_BYTES;
#pragma unroll
        for (int i = 0; i < 4; i++)
            cp16(as + a_r[i] * TROWB + a_c[i] * 16,
                 A + (size_t)a_g[i] * HID + chunk * BK + a_c[i] * 8);
#pragma unroll
        for (int i = 0; i < 8; i++)
            cp16(bs + b_r[i] * TROWB + b_c[i] * 16,
                 Bt + (size_t)b_r[i] * HID + chunk * BK + b_c[i] * 8);
    };

    // fragment lane mapping (fp16 b16 native)
    const int a_row = lane & 15;
    const int a_hi  = (lane >> 4) * 16;                 // k8..15 half of 16x16 tile
    const int b_row = (lane & 7) | ((lane >> 1) & 8);
    const int b_hi  = ((lane >> 3) & 1) * 16;
    const uint32_t a_off = (warp_m * 64 + a_row) * TROWB + a_hi;
    const uint32_t b_off = (warp_n * 64 + b_row) * TROWB + b_hi;

    float c[4][8][4];
#pragma unroll
    for (int mt = 0; mt < 4; mt++)
#pragma unroll
        for (int nt = 0; nt < 8; nt++)
#pragma unroll
            for (int j = 0; j < 4; j++) c[mt][nt][j] = 0.f;

    const int NC = HID / BK;  // 64

    load_stage(0, 0); cp_commit();
    load_stage(1, 1); cp_commit();

    for (int ch = 0; ch < NC; ch++) {
        cp_wait<1>();
        __syncthreads();

        if (ch + 2 < NC) load_stage((ch + 2) % STAGES, ch + 2);
        cp_commit();

        const uint32_t as = sb + (ch % STAGES) * STAGE_BYTES;
        const uint32_t bs = as + A_TILE_BYTES;
        const uint32_t aL = as + a_off;
        const uint32_t bL = bs + b_off;

#pragma unroll
        for (int ks = 0; ks < 4; ks++) {  // 4 x k16
            uint32_t af[4][4], bf[8][2];
#pragma unroll
            for (int mt = 0; mt < 4; mt++)
                LDSM4(af[mt][0], af[mt][1], af[mt][2], af[mt][3],
                      aL + mt * 16 * TROWB + ks * 32);
#pragma unroll
            for (int pr = 0; pr < 4; pr++)
                LDSM4(bf[2 * pr][0], bf[2 * pr][1], bf[2 * pr + 1][0], bf[2 * pr + 1][1],
                      bL + pr * 16 * TROWB + ks * 32);
#pragma unroll
            for (int mt = 0; mt < 4; mt++)
#pragma unroll
                for (int nt = 0; nt < 8; nt++)
                    mma_f16(c[mt][nt], af[mt][0], af[mt][1], af[mt][2], af[mt][3],
                            bf[nt][0], bf[nt][1]);
        }
        __syncthreads();
    }

    // epilogue: scatter fp32 to true rows
#pragma unroll
    for (int mt = 0; mt < 4; mt++) {
        int r0 = warp_m * 64 + mt * 16 + lm;
        int r1 = r0 + 8;
        bool on0 = (m0 + r0 < count);
        bool on1 = (m0 + r1 < count);
        float* p0 = C + (size_t)idx_s[r0] * N + n0 + warp_n * 64;
        float* p1 = C + (size_t)idx_s[r1] * N + n0 + warp_n * 64;
#pragma unroll
        for (int nt = 0; nt < 8; nt++) {
            int col = nt * 8 + 2 * lq;
            if (on0) *(float2*)(p0 + col) = make_float2(c[mt][nt][0], c[mt][nt][1]);
            if (on1) *(float2*)(p1 + col) = make_float2(c[mt][nt][2], c[mt][nt][3]);
        }
    }
}

// ---------------- RoPE: q scaled by 1/sqrt(HD); fp16 outputs ----------------
__global__ void rope_kernel(const float* __restrict__ qkv, const int* __restrict__ pos_ids,
                            __half* __restrict__ q, __half* __restrict__ k) {
    int idx = blockIdx.x * blockDim.x + threadIdx.x;
    if (idx >= MTOK * NH * 64) return;
    int i = idx & 63;
    int h = (idx >> 6) & 31;
    int m = idx >> 11;

    float pos = (float)pos_ids[m];
    float freq = expf(-(float)i * (9.210340371976184f / 64.f));
    float ang = pos * freq;
    float cv = cosf(ang);
    float sv = sinf(ang);
    const float scale = 0.088388347648318447f;

    const float* qs = qkv + (size_t)m * QKVN + h * HD;
    const float* ks = qs + HID;
    float q0 = qs[i], q1 = qs[i + 64];
    float k0 = ks[i], k1 = ks[i + 64];

    size_t o = (size_t)m * HID + h * HD;
    q[o + i]      = __float2half((q0 * cv - q1 * sv) * scale);
    q[o + i + 64] = __float2half((q1 * cv + q0 * sv) * scale);
    k[o + i]      = __float2half(k0 * cv - k1 * sv);
    k[o + i + 64] = __float2half(k1 * cv + k0 * sv);
}

// ---------------- fp16 tensor-core flash attention ----------------
// Block: 128 q rows x 1 head; 8 warps x 16 rows; K-tile 64.
__global__ __launch_bounds__(256)
void attn_mma(const __half* __restrict__ Q, const __half* __restrict__ Kg,
              const __half* __restrict__ Vt, __half* __restrict__ ctx) {
    extern __shared__ char smem[];
    const uint32_t sb = smem_u32(smem);
    const int tid = threadIdx.x;
    const int warp = tid >> 5;
    const int lane = tid & 31;
    const int lm = lane >> 2;
    const int lq = lane & 3;
    const int b = blockIdx.z;
    const int h = blockIdx.y;
    const int qi = (int)gridDim.x - 1 - (int)blockIdx.x;
    const int qb = qi * 128;

    // Q tile: 128 rows x 128 fp16 (16 granules/row) -> 8/thread
#pragma unroll
    for (int i = 0; i < 8; i++) {
        int g = tid + i * 256;
        int r = g >> 4, c = g & 15;
        cp16(sb + AQS_OFF + r * QROWB + c * 16,
             Q + (size_t)(b * SEQ + qb + r) * HID + h * HD + c * 8);
    }
    cp_commit();

    const int a_row = lane & 15;
    const int a_hi  = (lane >> 4) * 16;
    const int b_row = (lane & 7) | ((lane >> 1) & 8);
    const int b_hi  = ((lane >> 3) & 1) * 16;
    const uint32_t qA = sb + AQS_OFF + (warp * 16 + a_row) * QROWB + a_hi;
    const uint32_t pA = sb + APS_OFF + (warp * 16 + a_row) * VROWB + a_hi;
    const uint32_t kB = sb + AKS_OFF + b_row * QROWB + b_hi;
    const uint32_t vB = sb + AVT_OFF + b_row * VROWB + b_hi;

    float o[16][4];
#pragma unroll
    for (int nt = 0; nt < 16; nt++)
#pragma unroll
        for (int j = 0; j < 4; j++) o[nt][j] = 0.f;
    float mr0 = -1e30f, mr1 = -1e30f, l0 = 0.f, l1 = 0.f;
    const int r0g = qb + warp * 16 + lm;
    const int r1g = r0g + 8;

    const int ntiles = 2 * qi + 2;
    for (int t = 0; t < ntiles; t++) {
        // K tile 64 x 128 fp16: 1024 granules -> 4/thread
#pragma unroll
        for (int i = 0; i < 4; i++) {
            int g = tid + i * 256;
            int r = g >> 4, c = g & 15;
            cp16(sb + AKS_OFF + r * QROWB + c * 16,
                 Kg + (size_t)(b * SEQ + t * 64 + r) * HID + h * HD + c * 8);
        }
        // Vt tile 128 x 64 fp16: 1024 granules -> 4/thread
#pragma unroll
        for (int i = 0; i < 4; i++) {
            int g = tid + i * 256;
            int r = g >> 3, c = g & 7;
            cp16(sb + AVT_OFF + r * VROWB + c * 16,
                 Vt + ((size_t)(b * NH + h) * HD + r) * SEQ + t * 64 + c * 8);
        }
        cp_commit();
        cp_wait<0>();
        __syncthreads();

        // QK scores: 16 x 64 per warp
        float s_[8][4];
#pragma unroll
        for (int nt = 0; nt < 8; nt++)
#pragma unroll
            for (int j = 0; j < 4; j++) s_[nt][j] = 0.f;

#pragma unroll
        for (int ks = 0; ks < 8; ks++) {
            uint32_t a0, a1, a2, a3;
            LDSM4(a0, a1, a2, a3, qA + ks * 32);
#pragma unroll
            for (int pr = 0; pr < 4; pr++) {
                uint32_t b0, b1, b2, b3;
                LDSM4(b0, b1, b2, b3, kB + pr * 16 * QROWB + ks * 32);
                mma_f16(s_[2 * pr],     a0, a1, a2, a3, b0, b1);
                mma_f16(s_[2 * pr + 1], a0, a1, a2, a3, b2, b3);
            }
        }

        if (t >= 2 * qi) {
#pragma unroll
            for (int nt = 0; nt < 8; nt++) {
                int cb = t * 64 + nt * 8 + 2 * lq;
                if (cb > r0g)     s_[nt][0] = -1e30f;
                if (cb + 1 > r0g) s_[nt][1] = -1e30f;
                if (cb > r1g)     s_[nt][2] = -1e30f;
                if (cb + 1 > r1g) s_[nt][3] = -1e30f;
            }
        }

        float tm0 = -1e30f, tm1 = -1e30f;
#pragma unroll
        for (int nt = 0; nt < 8; nt++) {
            tm0 = fmaxf(tm0, fmaxf(s_[nt][0], s_[nt][1]));
            tm1 = fmaxf(tm1, fmaxf(s_[nt][2], s_[nt][3]));
        }
        tm0 = fmaxf(tm0, __shfl_xor_sync(0xffffffffu, tm0, 1));
        tm0 = fmaxf(tm0, __shfl_xor_sync(0xffffffffu, tm0, 2));
        tm1 = fmaxf(tm1, __shfl_xor_sync(0xffffffffu, tm1, 1));
        tm1 = fmaxf(tm1, __shfl_xor_sync(0xffffffffu, tm1, 2));
        float mn0 = fmaxf(mr0, tm0), mn1 = fmaxf(mr1, tm1);
        float c0 = __expf(mr0 - mn0), c1 = __expf(mr1 - mn1);
        float ps0 = 0.f, ps1 = 0.f;
#pragma unroll
        for (int nt = 0; nt < 8; nt++) {
            s_[nt][0] = __expf(s_[nt][0] - mn0);
            s_[nt][1] = __expf(s_[nt][1] - mn0);
            s_[nt][2] = __expf(s_[nt][2] - mn1);
            s_[nt][3] = __expf(s_[nt][3] - mn1);
            ps0 += s_[nt][0] + s_[nt][1];
            ps1 += s_[nt][2] + s_[nt][3];
        }
        l0 = l0 * c0 + ps0;
        l1 = l1 * c1 + ps1;
#pragma unroll
        for (int nt = 0; nt < 16; nt++) {
            o[nt][0] *= c0; o[nt][1] *= c0;
            o[nt][2] *= c1; o[nt][3] *= c1;
        }
        mr0 = mn0; mr1 = mn1;

        // P -> smem fp16 (warp-private rows)
#pragma unroll
        for (int nt = 0; nt < 8; nt++) {
            *(__half2*)(smem + APS_OFF + (warp * 16 + lm) * VROWB + (nt * 8 + 2 * lq) * 2)
                = __floats2half2_rn(s_[nt][0], s_[nt][1]);
            *(__half2*)(smem + APS_OFF + (warp * 16 + lm + 8) * VROWB + (nt * 8 + 2 * lq) * 2)
                = __floats2half2_rn(s_[nt][2], s_[nt][3]);
        }
        __syncwarp();

        // PV: O[16x128] += P[16x64] * V[64x128]
#pragma unroll
        for (int ks = 0; ks < 4; ks++) {
            uint32_t a0, a1, a2, a3;
            LDSM4(a0, a1, a2, a3, pA + ks * 32);
#pragma unroll
            for (int pr = 0; pr < 8; pr++) {
                uint32_t b0, b1, b2, b3;
                LDSM4(b0, b1, b2, b3, vB + pr * 16 * VROWB + ks * 32);
                mma_f16(o[2 * pr],     a0, a1, a2, a3, b0, b1);
                mma_f16(o[2 * pr + 1], a0, a1, a2, a3, b2, b3);
            }
        }
        __syncthreads();
    }

    l0 += __shfl_xor_sync(0xffffffffu, l0, 1);
    l0 += __shfl_xor_sync(0xffffffffu, l0, 2);
    l1 += __shfl_xor_sync(0xffffffffu, l1, 1);
    l1 += __shfl_xor_sync(0xffffffffu, l1, 2);
    float i0 = 1.f / l0, i1 = 1.f / l1;

#pragma unroll
    for (int nt = 0; nt < 16; nt++) {
        int col = nt * 8 + 2 * lq;
        *(__half2*)&ctx[(size_t)(b * SEQ + r0g) * HID + h * HD + col] =
            __floats2half2_rn(o[nt][0] * i0, o[nt][1] * i0);
        *(__half2*)&ctx[(size_t)(b * SEQ + r1g) * HID + h * HD + col] =
            __floats2half2_rn(o[nt][2] * i1, o[nt][3] * i1);
    }
}

// ---------------- launch ----------------
extern "C" void kernel_launch(void* const* d_in, const int* in_sizes, int n_in,
                              void* d_out, int out_size) {
    const float* hidden = (const float*)d_in[0];
    const int*   tt     = (const int*)d_in[1];
    const int*   pos    = (const int*)d_in[2];
    const float* wvq    = (const float*)d_in[3];
    const float* wlq    = (const float*)d_in[4];
    const float* wvd    = (const float*)d_in[5];
    const float* wld    = (const float*)d_in[6];
    float* out = (float*)d_out;

    float* qkv_p;
    __half *q_p, *k_p, *vt_p, *ctx_p, *hidh_p, *wr_p;
    int *cnt_p, *idx_p;
    cudaGetSymbolAddress((void**)&qkv_p, g_qkv);
    cudaGetSymbolAddress((void**)&q_p, g_q);
    cudaGetSymbolAddress((void**)&k_p, g_k);
    cudaGetSymbolAddress((void**)&vt_p, g_vt);
    cudaGetSymbolAddress((void**)&ctx_p, g_ctx);
    cudaGetSymbolAddress((void**)&hidh_p, g_hidh);
    cudaGetSymbolAddress((void**)&wr_p, g_wr);
    cudaGetSymbolAddress((void**)&cnt_p, g_cnt);
    cudaGetSymbolAddress((void**)&idx_p, g_idx);

    const int* cnt_vis  = cnt_p;
    const int* cnt_lang = cnt_p + 1;
    const int* idx_vis  = idx_p;
    const int* idx_lang = idx_p + MTOK;

    __half* wr_vq = wr_p + WR_VQ;
    __half* wr_lq = wr_p + WR_LQ;
    __half* wr_vd = wr_p + WR_VD;
    __half* wr_ld = wr_p + WR_LD;

    cudaFuncSetAttribute(gemm_tc, cudaFuncAttributeMaxDynamicSharedMemorySize, GEMM_SMEM);
    cudaFuncSetAttribute(attn_mma, cudaFuncAttributeMaxDynamicSharedMemorySize, ATT_SMEM);

    zero_cnt_kernel<<<1, 32>>>();
    route_kernel<<<MTOK / 256, 256>>>(tt);

    // pre-pass: weights -> fp16 transposed, hidden -> fp16
    {
        dim3 g1(QKVN / 32, HID / 32);
        trp_h_kernel<<<g1, 256>>>(wvq, wr_vq, QKVN);
        trp_h_kernel<<<g1, 256>>>(wlq, wr_lq, QKVN);
        dim3 g2(HID / 32, HID / 32);
        trp_h_kernel<<<g2, 256>>>(wvd, wr_vd, HID);
        trp_h_kernel<<<g2, 256>>>(wld, wr_ld, HID);
        int n4h = (int)((size_t)MTOK * HID / 4);
        f2h_kernel<<<(n4h + 255) / 256, 256>>>((const float4*)hidden, (__half2*)hidh_p, n4h);
    }

    // QKV projection per expert over gathered rows
    {
        dim3 grid(MTOK / BM, QKVN / BN);
        gemm_tc<<<grid, 256, GEMM_SMEM>>>(hidh_p, wr_vq, qkv_p, QKVN, idx_vis, cnt_vis);
        gemm_tc<<<grid, 256, GEMM_SMEM>>>(hidh_p, wr_lq, qkv_p, QKVN, idx_lang, cnt_lang);
    }

    // RoPE + V transpose (fp16 outputs)
    rope_kernel<<<(MTOK * NH * 64) / 256, 256>>>(qkv_p, pos, q_p, k_p);
    {
        dim3 gv(SEQ / 32, HD / 32, BATCH * NH);
        vtrans_kernel<<<gv, 256>>>(qkv_p, vt_p);
    }

    // fp16 tensor-core flash attention (writes fp16 ctx)
    {
        dim3 grid(SEQ / 128, NH, BATCH);
        attn_mma<<<grid, 256, ATT_SMEM>>>(q_p, k_p, vt_p, ctx_p);
    }

    // Dense projection per expert (fp16 A from attention)
    {
        dim3 grid(MTOK / BM, HID / BN);
        gemm_tc<<<grid, 256, GEMM_SMEM>>>(ctx_p, wr_vd, out, HID, idx_vis, cnt_vis);
        gemm_tc<<<grid, 256, GEMM_SMEM>>>(ctx_p, wr_ld, out, HID, idx_lang, cnt_lang);
    }
}

// round 10
// speedup vs baseline: 1.8852x; 1.0253x over previous
#include <cuda_runtime.h>
#include <cuda_fp16.h>
#include <math.h>
#include <stdint.h>

// Problem constants
#define BATCH 2
#define SEQ   2048
#define NH    32
#define HD    128
#define HID   4096           // NH*HD
#define QKVN  12288          // 3*HID
#define MTOK  (BATCH*SEQ)    // 4096 tokens

// GEMM tile config (mma.sync m16n8k16 fp16; A ldmatrix, B ldmatrix.trans)
#define BM 128
#define BN 256
#define BK 64
#define STAGES 3
#define AROWB 144                                // A smem row: 64 fp16 + pad
#define BROWB 528                                // B smem row: 256 fp16 + pad (33x16B)
#define A_TILE_BYTES (128 * AROWB)               // 18432
#define B_TILE_BYTES (64 * BROWB)                // 33792
#define STAGE_BYTES (A_TILE_BYTES + B_TILE_BYTES)// 52224
#define GEMM_SMEM (STAGES * STAGE_BYTES)         // 156672

// Attention smem layout (fp16, double-buffered K/V)
#define QROWB 272                                // 128 fp16 + pad
#define VROWB 144                                // 64 fp16 + pad
#define AQS_OFF 0
#define KV_STAGE (64 * QROWB + 128 * VROWB)      // 35840 (K tile + V tile)
#define AKV0_OFF (128 * QROWB)                   // 34816
#define AKV1_OFF (AKV0_OFF + KV_STAGE)           // 70656
#define APS_OFF (AKV1_OFF + KV_STAGE)            // 106496
#define ATT_SMEM (APS_OFF + 128 * VROWB)         // 124928

// ---------------- scratch (device globals) -------------
__device__ __half g_qkv[(size_t)MTOK * QKVN];        // fp16 qkv projection
__device__ __half g_q[(size_t)MTOK * HID];
__device__ __half g_k[(size_t)MTOK * HID];
__device__ __half g_vt[(size_t)BATCH * NH * HD * SEQ];
__device__ __half g_ctx[(size_t)MTOK * HID];
__device__ __half g_hidh[(size_t)MTOK * HID];
// fp16 weights, NATIVE [K][N] layout (no transpose)
#define WR_VQ 0
#define WR_LQ ((size_t)HID * QKVN)
#define WR_VD (2 * (size_t)HID * QKVN)
#define WR_LD (2 * (size_t)HID * QKVN + (size_t)HID * HID)
__device__ __half g_wr[2 * (size_t)HID * QKVN + 2 * (size_t)HID * HID];
__device__ int    g_cnt[2];
__device__ int    g_idx[2][MTOK];

// ---------------- helpers ----------------
__device__ __forceinline__ uint32_t smem_u32(const void* p) {
    uint32_t a;
    asm("{ .reg .u64 t; cvta.to.shared.u64 t, %1; cvt.u32.u64 %0, t; }" : "=r"(a) : "l"(p));
    return a;
}
__device__ __forceinline__ void cp16(uint32_t dst, const void* src) {
    asm volatile("cp.async.cg.shared.global [%0], [%1], 16;" :: "r"(dst), "l"(src));
}
__device__ __forceinline__ void cp_commit() {
    asm volatile("cp.async.commit_group;" ::: "memory");
}
template <int N>
__device__ __forceinline__ void cp_wait() {
    asm volatile("cp.async.wait_group %0;" :: "n"(N) : "memory");
}
__device__ __forceinline__ void mma_f16(float* c, uint32_t a0, uint32_t a1, uint32_t a2, uint32_t a3,
                                        uint32_t b0, uint32_t b1) {
    asm volatile(
        "mma.sync.aligned.m16n8k16.row.col.f32.f16.f16.f32 "
        "{%0,%1,%2,%3}, {%4,%5,%6,%7}, {%8,%9}, {%0,%1,%2,%3};"
        : "+f"(c[0]), "+f"(c[1]), "+f"(c[2]), "+f"(c[3])
        : "r"(a0), "r"(a1), "r"(a2), "r"(a3), "r"(b0), "r"(b1));
}
#define LDSM4(r0, r1, r2, r3, addr)                                               \
    asm volatile("ldmatrix.sync.aligned.m8n8.x4.shared.b16 {%0,%1,%2,%3}, [%4];"   \
        : "=r"(r0), "=r"(r1), "=r"(r2), "=r"(r3) : "r"(addr))
#define LDSM4T(r0, r1, r2, r3, addr)                                              \
    asm volatile("ldmatrix.sync.aligned.m8n8.x4.trans.shared.b16 {%0,%1,%2,%3}, [%4];" \
        : "=r"(r0), "=r"(r1), "=r"(r2), "=r"(r3) : "r"(addr))

__device__ __forceinline__ void store2(float* p, float a, float b) {
    *(float2*)p = make_float2(a, b);
}
__device__ __forceinline__ void store2(__half* p, float a, float b) {
    *(__half2*)p = __floats2half2_rn(a, b);
}

// ---------------- pre-pass: fp32 -> fp16 (coalesced, no transpose) ----------------
__global__ __launch_bounds__(256)
void f2h_kernel(const float4* __restrict__ in, __half2* __restrict__ out, int n4) {
    int i = blockIdx.x * blockDim.x + threadIdx.x;
    if (i >= n4) return;
    float4 v = in[i];
    out[2 * i]     = __floats2half2_rn(v.x, v.y);
    out[2 * i + 1] = __floats2half2_rn(v.z, v.w);
}

// V transpose to fp16: g_vt[bh][d][s] from fp16 qkv
__global__ __launch_bounds__(256)
void vtrans_kernel(const __half* __restrict__ qkv, __half* __restrict__ Vt) {
    __shared__ float t[32][33];
    int bh = blockIdx.z;
    int b = bh >> 5, h = bh & 31;
    int s0 = blockIdx.x * 32;
    int d0 = blockIdx.y * 32;
    int x = threadIdx.x & 31;
    int y = threadIdx.x >> 5;
#pragma unroll
    for (int i = 0; i < 32; i += 8)
        t[y + i][x] = __half2float(qkv[(size_t)(b * SEQ + s0 + y + i) * QKVN + 2 * HID + h * HD + d0 + x]);
    __syncthreads();
#pragma unroll
    for (int i = 0; i < 32; i += 8)
        Vt[((size_t)bh * HD + d0 + y + i) * SEQ + s0 + x] = __float2half(t[x][y + i]);
}

// ---------------- mask / routing ----------------
__global__ void zero_cnt_kernel() {
    if (threadIdx.x < 2) g_cnt[threadIdx.x] = 0;
}
__global__ void route_kernel(const int* __restrict__ tt) {
    int idx = blockIdx.x * blockDim.x + threadIdx.x;
    if (idx >= MTOK) return;
    int s = idx & (SEQ - 1);
    int vis = (s + 1 < SEQ) && (tt[idx] == 1) && (tt[idx + 1] == 1);
    int e = vis ? 0 : 1;
    int pos = atomicAdd(&g_cnt[e], 1);
    g_idx[e][pos] = idx;
}

// ---------------- fp16 tensor-core GEMM, B in native [K][N] via ldmatrix.trans ----------------
template <typename CT>
__global__ __launch_bounds__(256, 1)
void gemm_tc(const __half* __restrict__ A, const __half* __restrict__ W,
             CT* __restrict__ C, int N,
             const int* __restrict__ idx, const int* __restrict__ cnt_ptr) {
    __shared__ int idx_s[BM];
    extern __shared__ char smem[];
    const uint32_t sb = smem_u32(smem);
    const int tid = threadIdx.x;
    const int wid = tid >> 5;
    const int lane = tid & 31;
    const int lm = lane >> 2;
    const int lq = lane & 3;
    const int warp_m = wid & 1;
    const int warp_n = wid >> 1;
    const int m0 = blockIdx.x * BM;
    const int n0 = blockIdx.y * BN;

    const int count = __ldg(cnt_ptr);
    if (m0 >= count) return;

    if (tid < BM) {
        int mp = m0 + tid;
        idx_s[tid] = idx[mp < count ? mp : count - 1];
    }
    __syncthreads();

    // A loader: 128 rows x 8 granules -> 4/thread
    int a_r[4], a_c[4];
#pragma unroll
    for (int i = 0; i < 4; i++) {
        int t = tid + i * 256;
        a_r[i] = t >> 3;
        a_c[i] = t & 7;
    }
    int a_g[4];
#pragma unroll
    for (int i = 0; i < 4; i++) a_g[i] = idx_s[a_r[i]];
    // B loader: 64 k-rows x 32 granules(16B = 8 fp16 of N) -> 8/thread
    int b_r[8], b_c[8];
#pragma unroll
    for (int i = 0; i < 8; i++) {
        int t = tid + i * 256;
        b_r[i] = t >> 5;
        b_c[i] = t & 31;
    }

    auto load_stage = [&](int stage, int chunk) {
        uint32_t as = sb + stage * STAGE_BYTES;
        uint32_t bs = as + A_TILE_BYTES;
#pragma unroll
        for (int i = 0; i < 4; i++)
            cp16(as + a_r[i] * AROWB + a_c[i] * 16,
                 A + (size_t)a_g[i] * HID + chunk * BK + a_c[i] * 8);
#pragma unroll
        for (int i = 0; i < 8; i++)
            cp16(bs + b_r[i] * BROWB + b_c[i] * 16,
                 W + (size_t)(chunk * BK + b_r[i]) * N + n0 + b_c[i] * 8);
    };

    // fragment lane mappings
    const uint32_t a_off = (warp_m * 64 + (lane & 15)) * AROWB + (lane >> 4) * 16;
    // B trans: k-row = lane&15, n-halfsel = lane>>4 (16B), warp col base = warp_n*64 fp16
    const uint32_t b_off = (lane & 15) * BROWB + (lane >> 4) * 16 + warp_n * 128;

    float c[4][8][4];
#pragma unroll
    for (int mt = 0; mt < 4; mt++)
#pragma unroll
        for (int nt = 0; nt < 8; nt++)
#pragma unroll
            for (int j = 0; j < 4; j++) c[mt][nt][j] = 0.f;

    const int NC = HID / BK;  // 64

    load_stage(0, 0); cp_commit();
    load_stage(1, 1); cp_commit();

    for (int ch = 0; ch < NC; ch++) {
        cp_wait<1>();
        __syncthreads();

        if (ch + 2 < NC) load_stage((ch + 2) % STAGES, ch + 2);
        cp_commit();

        const uint32_t as = sb + (ch % STAGES) * STAGE_BYTES;
        const uint32_t bs = as + A_TILE_BYTES;
        const uint32_t aL = as + a_off;
        const uint32_t bL = bs + b_off;

#pragma unroll
        for (int ks = 0; ks < 4; ks++) {  // 4 x k16
            uint32_t af[4][4], bf[8][2];
#pragma unroll
            for (int mt = 0; mt < 4; mt++)
                LDSM4(af[mt][0], af[mt][1], af[mt][2], af[mt][3],
                      aL + mt * 16 * AROWB + ks * 32);
#pragma unroll
            for (int pr = 0; pr < 4; pr++)
                LDSM4T(bf[2 * pr][0], bf[2 * pr][1], bf[2 * pr + 1][0], bf[2 * pr + 1][1],
                       bL + ks * 16 * BROWB + pr * 32);
#pragma unroll
            for (int mt = 0; mt < 4; mt++)
#pragma unroll
                for (int nt = 0; nt < 8; nt++)
                    mma_f16(c[mt][nt], af[mt][0], af[mt][1], af[mt][2], af[mt][3],
                            bf[nt][0], bf[nt][1]);
        }
        __syncthreads();
    }

    // epilogue: scatter to true rows
#pragma unroll
    for (int mt = 0; mt < 4; mt++) {
        int r0 = warp_m * 64 + mt * 16 + lm;
        int r1 = r0 + 8;
        bool on0 = (m0 + r0 < count);
        bool on1 = (m0 + r1 < count);
        CT* p0 = C + (size_t)idx_s[r0] * N + n0 + warp_n * 64;
        CT* p1 = C + (size_t)idx_s[r1] * N + n0 + warp_n * 64;
#pragma unroll
        for (int nt = 0; nt < 8; nt++) {
            int col = nt * 8 + 2 * lq;
            if (on0) store2(p0 + col, c[mt][nt][0], c[mt][nt][1]);
            if (on1) store2(p1 + col, c[mt][nt][2], c[mt][nt][3]);
        }
    }
}

// ---------------- RoPE: reads fp16 qkv, writes fp16 q (scaled) / k ----------------
__global__ void rope_kernel(const __half* __restrict__ qkv, const int* __restrict__ pos_ids,
                            __half* __restrict__ q, __half* __restrict__ k) {
    int idx = blockIdx.x * blockDim.x + threadIdx.x;
    if (idx >= MTOK * NH * 64) return;
    int i = idx & 63;
    int h = (idx >> 6) & 31;
    int m = idx >> 11;

    float pos = (float)pos_ids[m];
    float freq = expf(-(float)i * (9.210340371976184f / 64.f));
    float ang = pos * freq;
    float cv = cosf(ang);
    float sv = sinf(ang);
    const float scale = 0.088388347648318447f;

    const __half* qs = qkv + (size_t)m * QKVN + h * HD;
    const __half* ks = qs + HID;
    float q0 = __half2float(qs[i]), q1 = __half2float(qs[i + 64]);
    float k0 = __half2float(ks[i]), k1 = __half2float(ks[i + 64]);

    size_t o = (size_t)m * HID + h * HD;
    q[o + i]      = __float2half((q0 * cv - q1 * sv) * scale);
    q[o + i + 64] = __float2half((q1 * cv + q0 * sv) * scale);
    k[o + i]      = __float2half(k0 * cv - k1 * sv);
    k[o + i + 64] = __float2half(k1 * cv + k0 * sv);
}

// ---------------- fp16 flash attention, double-buffered K/V ----------------
__global__ __launch_bounds__(256)
void attn_mma(const __half* __restrict__ Q, const __half* __restrict__ Kg,
              const __half* __restrict__ Vt, __half* __restrict__ ctx) {
    extern __shared__ char smem[];
    const uint32_t sb = smem_u32(smem);
    const int tid = threadIdx.x;
    const int warp = tid >> 5;
    const int lane = tid & 31;
    const int lm = lane >> 2;
    const int lq = lane & 3;
    const int b = blockIdx.z;
    const int h = blockIdx.y;
    const int qi = (int)gridDim.x - 1 - (int)blockIdx.x;
    const int qb = qi * 128;

    const uint32_t kvb[2] = {sb + AKV0_OFF, sb + AKV1_OFF};

    auto load_tile = [&](int t, int buf) {
        uint32_t kb = kvb[buf];
        uint32_t vb = kvb[buf] + 64 * QROWB;
#pragma unroll
        for (int i = 0; i < 4; i++) {
            int g = tid + i * 256;
            int r = g >> 4, c = g & 15;
            cp16(kb + r * QROWB + c * 16,
                 Kg + (size_t)(b * SEQ + t * 64 + r) * HID + h * HD + c * 8);
        }
#pragma unroll
        for (int i = 0; i < 4; i++) {
            int g = tid + i * 256;
            int r = g >> 3, c = g & 7;
            cp16(vb + r * VROWB + c * 16,
                 Vt + ((size_t)(b * NH + h) * HD + r) * SEQ + t * 64 + c * 8);
        }
    };

    // group0: Q tile + KV tile 0
#pragma unroll
    for (int i = 0; i < 8; i++) {
        int g = tid + i * 256;
        int r = g >> 4, c = g & 15;
        cp16(sb + AQS_OFF + r * QROWB + c * 16,
             Q + (size_t)(b * SEQ + qb + r) * HID + h * HD + c * 8);
    }
    load_tile(0, 0);
    cp_commit();

    const int a_row = lane & 15;
    const int a_hi  = (lane >> 4) * 16;
    const int b_row = (lane & 7) | ((lane >> 1) & 8);
    const int b_hi  = ((lane >> 3) & 1) * 16;
    const uint32_t qA = sb + AQS_OFF + (warp * 16 + a_row) * QROWB + a_hi;
    const uint32_t pA = sb + APS_OFF + (warp * 16 + a_row) * VROWB + a_hi;
    const uint32_t kOff = b_row * QROWB + b_hi;
    const uint32_t vOff = 64 * QROWB + b_row * VROWB + b_hi;

    float o[16][4];
#pragma unroll
    for (int nt = 0; nt < 16; nt++)
#pragma unroll
        for (int j = 0; j < 4; j++) o[nt][j] = 0.f;
    float mr0 = -1e30f, mr1 = -1e30f, l0 = 0.f, l1 = 0.f;
    const int r0g = qb + warp * 16 + lm;
    const int r1g = r0g + 8;

    const int ntiles = 2 * qi + 2;
    for (int t = 0; t < ntiles; t++) {
        const int buf = t & 1;
        if (t + 1 < ntiles) {
            load_tile(t + 1, buf ^ 1);
            cp_commit();
            cp_wait<1>();
        } else {
            cp_wait<0>();
        }
        __syncthreads();

        const uint32_t kB = kvb[buf] + kOff;
        const uint32_t vB = kvb[buf] + vOff;

        // QK scores: 16 x 64 per warp
        float s_[8][4];
#pragma unroll
        for (int nt = 0; nt < 8; nt++)
#pragma unroll
            for (int j = 0; j < 4; j++) s_[nt][j] = 0.f;

#pragma unroll
        for (int ks = 0; ks < 8; ks++) {
            uint32_t a0, a1, a2, a3;
            LDSM4(a0, a1, a2, a3, qA + ks * 32);
#pragma unroll
            for (int pr = 0; pr < 4; pr++) {
                uint32_t b0, b1, b2, b3;
                LDSM4(b0, b1, b2, b3, kB + pr * 16 * QROWB + ks * 32);
                mma_f16(s_[2 * pr],     a0, a1, a2, a3, b0, b1);
                mma_f16(s_[2 * pr + 1], a0, a1, a2, a3, b2, b3);
            }
        }

        if (t >= 2 * qi) {
#pragma unroll
            for (int nt = 0; nt < 8; nt++) {
                int cb = t * 64 + nt * 8 + 2 * lq;
                if (cb > r0g)     s_[nt][0] = -1e30f;
                if (cb + 1 > r0g) s_[nt][1] = -1e30f;
                if (cb > r1g)     s_[nt][2] = -1e30f;
                if (cb + 1 > r1g) s_[nt][3] = -1e30f;
            }
        }

        float tm0 = -1e30f, tm1 = -1e30f;
#pragma unroll
        for (int nt = 0; nt < 8; nt++) {
            tm0 = fmaxf(tm0, fmaxf(s_[nt][0], s_[nt][1]));
            tm1 = fmaxf(tm1, fmaxf(s_[nt][2], s_[nt][3]));
        }
        tm0 = fmaxf(tm0, __shfl_xor_sync(0xffffffffu, tm0, 1));
        tm0 = fmaxf(tm0, __shfl_xor_sync(0xffffffffu, tm0, 2));
        tm1 = fmaxf(tm1, __shfl_xor_sync(0xffffffffu, tm1, 1));
        tm1 = fmaxf(tm1, __shfl_xor_sync(0xffffffffu, tm1, 2));
        float mn0 = fmaxf(mr0, tm0), mn1 = fmaxf(mr1, tm1);
        float c0 = __expf(mr0 - mn0), c1 = __expf(mr1 - mn1);
        float ps0 = 0.f, ps1 = 0.f;
#pragma unroll
        for (int nt = 0; nt < 8; nt++) {
            s_[nt][0] = __expf(s_[nt][0] - mn0);
            s_[nt][1] = __expf(s_[nt][1] - mn0);
            s_[nt][2] = __expf(s_[nt][2] - mn1);
            s_[nt][3] = __expf(s_[nt][3] - mn1);
            ps0 += s_[nt][0] + s_[nt][1];
            ps1 += s_[nt][2] + s_[nt][3];
        }
        l0 = l0 * c0 + ps0;
        l1 = l1 * c1 + ps1;
#pragma unroll
        for (int nt = 0; nt < 16; nt++) {
            o[nt][0] *= c0; o[nt][1] *= c0;
            o[nt][2] *= c1; o[nt][3] *= c1;
        }
        mr0 = mn0; mr1 = mn1;

        // P -> smem fp16 (warp-private rows)
#pragma unroll
        for (int nt = 0; nt < 8; nt++) {
            *(__half2*)(smem + APS_OFF + (warp * 16 + lm) * VROWB + (nt * 8 + 2 * lq) * 2)
                = __floats2half2_rn(s_[nt][0], s_[nt][1]);
            *(__half2*)(smem + APS_OFF + (warp * 16 + lm + 8) * VROWB + (nt * 8 + 2 * lq) * 2)
                = __floats2half2_rn(s_[nt][2], s_[nt][3]);
        }
        __syncwarp();

        // PV
#pragma unroll
        for (int ks = 0; ks < 4; ks++) {
            uint32_t a0, a1, a2, a3;
            LDSM4(a0, a1, a2, a3, pA + ks * 32);
#pragma unroll
            for (int pr = 0; pr < 8; pr++) {
                uint32_t b0, b1, b2, b3;
                LDSM4(b0, b1, b2, b3, vB + pr * 16 * VROWB + ks * 32);
                mma_f16(o[2 * pr],     a0, a1, a2, a3, b0, b1);
                mma_f16(o[2 * pr + 1], a0, a1, a2, a3, b2, b3);
            }
        }
        __syncthreads();
    }

    l0 += __shfl_xor_sync(0xffffffffu, l0, 1);
    l0 += __shfl_xor_sync(0xffffffffu, l0, 2);
    l1 += __shfl_xor_sync(0xffffffffu, l1, 1);
    l1 += __shfl_xor_sync(0xffffffffu, l1, 2);
    float i0 = 1.f / l0, i1 = 1.f / l1;

#pragma unroll
    for (int nt = 0; nt < 16; nt++) {
        int col = nt * 8 + 2 * lq;
        *(__half2*)&ctx[(size_t)(b * SEQ + r0g) * HID + h * HD + col] =
            __floats2half2_rn(o[nt][0] * i0, o[nt][1] * i0);
        *(__half2*)&ctx[(size_t)(b * SEQ + r1g) * HID + h * HD + col] =
            __floats2half2_rn(o[nt][2] * i1, o[nt][3] * i1);
    }
}

// ---------------- launch ----------------
extern "C" void kernel_launch(void* const* d_in, const int* in_sizes, int n_in,
                              void* d_out, int out_size) {
    const float* hidden = (const float*)d_in[0];
    const int*   tt     = (const int*)d_in[1];
    const int*   pos    = (const int*)d_in[2];
    const float* wvq    = (const float*)d_in[3];
    const float* wlq    = (const float*)d_in[4];
    const float* wvd    = (const float*)d_in[5];
    const float* wld    = (const float*)d_in[6];
    float* out = (float*)d_out;

    __half *qkv_p, *q_p, *k_p, *vt_p, *ctx_p, *hidh_p, *wr_p;
    int *cnt_p, *idx_p;
    cudaGetSymbolAddress((void**)&qkv_p, g_qkv);
    cudaGetSymbolAddress((void**)&q_p, g_q);
    cudaGetSymbolAddress((void**)&k_p, g_k);
    cudaGetSymbolAddress((void**)&vt_p, g_vt);
    cudaGetSymbolAddress((void**)&ctx_p, g_ctx);
    cudaGetSymbolAddress((void**)&hidh_p, g_hidh);
    cudaGetSymbolAddress((void**)&wr_p, g_wr);
    cudaGetSymbolAddress((void**)&cnt_p, g_cnt);
    cudaGetSymbolAddress((void**)&idx_p, g_idx);

    const int* cnt_vis  = cnt_p;
    const int* cnt_lang = cnt_p + 1;
    const int* idx_vis  = idx_p;
    const int* idx_lang = idx_p + MTOK;

    __half* wr_vq = wr_p + WR_VQ;
    __half* wr_lq = wr_p + WR_LQ;
    __half* wr_vd = wr_p + WR_VD;
    __half* wr_ld = wr_p + WR_LD;

    cudaFuncSetAttribute((const void*)&gemm_tc<__half>, cudaFuncAttributeMaxDynamicSharedMemorySize, GEMM_SMEM);
    cudaFuncSetAttribute((const void*)&gemm_tc<float>, cudaFuncAttributeMaxDynamicSharedMemorySize, GEMM_SMEM);
    cudaFuncSetAttribute(attn_mma, cudaFuncAttributeMaxDynamicSharedMemorySize, ATT_SMEM);

    zero_cnt_kernel<<<1, 32>>>();
    route_kernel<<<MTOK / 256, 256>>>(tt);

    // pre-pass: pure fp32->fp16 converts (no transposes)
    {
        int n4w = (int)((size_t)HID * QKVN / 4);
        f2h_kernel<<<(n4w + 255) / 256, 256>>>((const float4*)wvq, (__half2*)wr_vq, n4w);
        f2h_kernel<<<(n4w + 255) / 256, 256>>>((const float4*)wlq, (__half2*)wr_lq, n4w);
        int n4d = (int)((size_t)HID * HID / 4);
        f2h_kernel<<<(n4d + 255) / 256, 256>>>((const float4*)wvd, (__half2*)wr_vd, n4d);
        f2h_kernel<<<(n4d + 255) / 256, 256>>>((const float4*)wld, (__half2*)wr_ld, n4d);
        int n4h = (int)((size_t)MTOK * HID / 4);
        f2h_kernel<<<(n4h + 255) / 256, 256>>>((const float4*)hidden, (__half2*)hidh_p, n4h);
    }

    // QKV projection per expert (fp16 output)
    {
        dim3 grid(MTOK / BM, QKVN / BN);
        gemm_tc<__half><<<grid, 256, GEMM_SMEM>>>(hidh_p, wr_vq, qkv_p, QKVN, idx_vis, cnt_vis);
        gemm_tc<__half><<<grid, 256, GEMM_SMEM>>>(hidh_p, wr_lq, qkv_p, QKVN, idx_lang, cnt_lang);
    }

    // RoPE + V transpose
    rope_kernel<<<(MTOK * NH * 64) / 256, 256>>>(qkv_p, pos, q_p, k_p);
    {
        dim3 gv(SEQ / 32, HD / 32, BATCH * NH);
        vtrans_kernel<<<gv, 256>>>(qkv_p, vt_p);
    }

    // fp16 flash attention
    {
        dim3 grid(SEQ / 128, NH, BATCH);
        attn_mma<<<grid, 256, ATT_SMEM>>>(q_p, k_p, vt_p, ctx_p);
    }

    // Dense projection per expert (fp32 output)
    {
        dim3 grid(MTOK / BM, HID / BN);
        gemm_tc<float><<<grid, 256, GEMM_SMEM>>>(ctx_p, wr_vd, out, HID, idx_vis, cnt_vis);
        gemm_tc<float><<<grid, 256, GEMM_SMEM>>>(ctx_p, wr_ld, out, HID, idx_lang, cnt_lang);
    }
}

// round 11
// speedup vs baseline: 1.9263x; 1.0218x over previous
#include <cuda_runtime.h>
#include <cuda_fp16.h>
#include <math.h>
#include <stdint.h>

// Problem constants
#define BATCH 2
#define SEQ   2048
#define NH    32
#define HD    128
#define HID   4096           // NH*HD
#define QKVN  12288          // 3*HID
#define MTOK  (BATCH*SEQ)    // 4096 tokens

// GEMM tile config (mma.sync m16n8k16 fp16; A ldmatrix, B ldmatrix.trans)
#define BM 128
#define BN 256
#define BK 64
#define STAGES 4
#define AROWB 144                                // A smem row: 64 fp16 + pad
#define BROWB 528                                // B smem row: 256 fp16 + pad
#define A_TILE_BYTES (128 * AROWB)               // 18432
#define B_TILE_BYTES (64 * BROWB)                // 33792
#define STAGE_BYTES (A_TILE_BYTES + B_TILE_BYTES)// 52224
#define GEMM_SMEM (STAGES * STAGE_BYTES)         // 208896

// Attention smem layout (fp16, double-buffered K/V)
#define QROWB 272
#define VROWB 144
#define AQS_OFF 0
#define KV_STAGE (64 * QROWB + 128 * VROWB)      // 35840
#define AKV0_OFF (128 * QROWB)                   // 34816
#define AKV1_OFF (AKV0_OFF + KV_STAGE)           // 70656
#define APS_OFF (AKV1_OFF + KV_STAGE)            // 106496
#define ATT_SMEM (APS_OFF + 128 * VROWB)         // 124928

// ---------------- scratch (device globals) -------------
__device__ __half g_qkv[(size_t)MTOK * QKVN];
__device__ __half g_q[(size_t)MTOK * HID];
__device__ __half g_k[(size_t)MTOK * HID];
__device__ __half g_vt[(size_t)BATCH * NH * HD * SEQ];
__device__ __half g_ctx[(size_t)MTOK * HID];
__device__ __half g_hidh[(size_t)MTOK * HID];
#define WR_VQ 0
#define WR_LQ ((size_t)HID * QKVN)
#define WR_VD (2 * (size_t)HID * QKVN)
#define WR_LD (2 * (size_t)HID * QKVN + (size_t)HID * HID)
__device__ __half g_wr[2 * (size_t)HID * QKVN + 2 * (size_t)HID * HID];
__device__ int    g_cnt[2];
__device__ int    g_idx[2][MTOK];
__device__ int    g_idxc[MTOK + 256];            // packed combined index
__device__ int    g_seg[4];                      // {pad0, pad0+pad1, c0, c1}

// ---------------- helpers ----------------
__device__ __forceinline__ uint32_t smem_u32(const void* p) {
    uint32_t a;
    asm("{ .reg .u64 t; cvta.to.shared.u64 t, %1; cvt.u32.u64 %0, t; }" : "=r"(a) : "l"(p));
    return a;
}
__device__ __forceinline__ void cp16(uint32_t dst, const void* src) {
    asm volatile("cp.async.cg.shared.global [%0], [%1], 16;" :: "r"(dst), "l"(src));
}
__device__ __forceinline__ void cp_commit() {
    asm volatile("cp.async.commit_group;" ::: "memory");
}
template <int N>
__device__ __forceinline__ void cp_wait() {
    asm volatile("cp.async.wait_group %0;" :: "n"(N) : "memory");
}
__device__ __forceinline__ void mma_f16(float* c, uint32_t a0, uint32_t a1, uint32_t a2, uint32_t a3,
                                        uint32_t b0, uint32_t b1) {
    asm volatile(
        "mma.sync.aligned.m16n8k16.row.col.f32.f16.f16.f32 "
        "{%0,%1,%2,%3}, {%4,%5,%6,%7}, {%8,%9}, {%0,%1,%2,%3};"
        : "+f"(c[0]), "+f"(c[1]), "+f"(c[2]), "+f"(c[3])
        : "r"(a0), "r"(a1), "r"(a2), "r"(a3), "r"(b0), "r"(b1));
}
#define LDSM4(r0, r1, r2, r3, addr)                                               \
    asm volatile("ldmatrix.sync.aligned.m8n8.x4.shared.b16 {%0,%1,%2,%3}, [%4];"   \
        : "=r"(r0), "=r"(r1), "=r"(r2), "=r"(r3) : "r"(addr))
#define LDSM4T(r0, r1, r2, r3, addr)                                              \
    asm volatile("ldmatrix.sync.aligned.m8n8.x4.trans.shared.b16 {%0,%1,%2,%3}, [%4];" \
        : "=r"(r0), "=r"(r1), "=r"(r2), "=r"(r3) : "r"(addr))

__device__ __forceinline__ void store2(float* p, float a, float b) {
    *(float2*)p = make_float2(a, b);
}
__device__ __forceinline__ void store2(__half* p, float a, float b) {
    *(__half2*)p = __floats2half2_rn(a, b);
}

// ---------------- pre-pass: fp32 -> fp16 ----------------
__global__ __launch_bounds__(256)
void f2h_kernel(const float4* __restrict__ in, __half2* __restrict__ out, int n4) {
    int i = blockIdx.x * blockDim.x + threadIdx.x;
    if (i >= n4) return;
    float4 v = in[i];
    out[2 * i]     = __floats2half2_rn(v.x, v.y);
    out[2 * i + 1] = __floats2half2_rn(v.z, v.w);
}

// V transpose: g_vt[bh][d][s]
__global__ __launch_bounds__(256)
void vtrans_kernel(const __half* __restrict__ qkv, __half* __restrict__ Vt) {
    __shared__ float t[32][33];
    int bh = blockIdx.z;
    int b = bh >> 5, h = bh & 31;
    int s0 = blockIdx.x * 32;
    int d0 = blockIdx.y * 32;
    int x = threadIdx.x & 31;
    int y = threadIdx.x >> 5;
#pragma unroll
    for (int i = 0; i < 32; i += 8)
        t[y + i][x] = __half2float(qkv[(size_t)(b * SEQ + s0 + y + i) * QKVN + 2 * HID + h * HD + d0 + x]);
    __syncthreads();
#pragma unroll
    for (int i = 0; i < 32; i += 8)
        Vt[((size_t)bh * HD + d0 + y + i) * SEQ + s0 + x] = __float2half(t[x][y + i]);
}

// ---------------- mask / routing / packing ----------------
__global__ void zero_cnt_kernel() {
    if (threadIdx.x < 2) g_cnt[threadIdx.x] = 0;
}
__global__ void route_kernel(const int* __restrict__ tt) {
    int idx = blockIdx.x * blockDim.x + threadIdx.x;
    if (idx >= MTOK) return;
    int s = idx & (SEQ - 1);
    int vis = (s + 1 < SEQ) && (tt[idx] == 1) && (tt[idx + 1] == 1);
    int e = vis ? 0 : 1;
    int pos = atomicAdd(&g_cnt[e], 1);
    g_idx[e][pos] = idx;
}
// build padded combined index: [vis rows | pad | lang rows | pad]
__global__ void pack_kernel() {
    int c0 = g_cnt[0], c1 = g_cnt[1];
    int pad0 = (c0 + 127) & ~127;
    int pad1 = (c1 + 127) & ~127;
    if (threadIdx.x == 0) {
        g_seg[0] = pad0;
        g_seg[1] = pad0 + pad1;
        g_seg[2] = c0;
        g_seg[3] = c1;
    }
    for (int i = threadIdx.x; i < pad0; i += blockDim.x)
        g_idxc[i] = g_idx[0][i < c0 ? i : c0 - 1];
    for (int j = threadIdx.x; j < pad1; j += blockDim.x)
        g_idxc[pad0 + j] = g_idx[1][j < c1 ? j : c1 - 1];
}

// ---------------- merged-expert fp16 GEMM ----------------
// One launch covers both experts: blocks in [0, seg0) use Wvis, [seg0, seg1) use Wlang.
template <typename CT>
__global__ __launch_bounds__(256, 1)
void gemm_tc(const __half* __restrict__ A,
             const __half* __restrict__ Wvis, const __half* __restrict__ Wlang,
             CT* __restrict__ C, int N) {
    __shared__ int idx_s[BM];
    extern __shared__ char smem[];
    const uint32_t sb = smem_u32(smem);
    const int tid = threadIdx.x;
    const int wid = tid >> 5;
    const int lane = tid & 31;
    const int lm = lane >> 2;
    const int lq = lane & 3;
    const int warp_m = wid & 1;
    const int warp_n = wid >> 1;
    const int m0 = blockIdx.x * BM;
    const int n0 = blockIdx.y * BN;

    const int s0 = __ldg(&g_seg[0]);
    const int s1 = __ldg(&g_seg[1]);
    if (m0 >= s1) return;
    const bool is_vis = (m0 < s0);
    const __half* W = is_vis ? Wvis : Wlang;
    const int limit = is_vis ? __ldg(&g_seg[2]) : (s0 + __ldg(&g_seg[3]));

    if (tid < BM) idx_s[tid] = g_idxc[m0 + tid];
    __syncthreads();

    int a_r[4], a_c[4];
#pragma unroll
    for (int i = 0; i < 4; i++) {
        int t = tid + i * 256;
        a_r[i] = t >> 3;
        a_c[i] = t & 7;
    }
    int a_g[4];
#pragma unroll
    for (int i = 0; i < 4; i++) a_g[i] = idx_s[a_r[i]];
    int b_r[8], b_c[8];
#pragma unroll
    for (int i = 0; i < 8; i++) {
        int t = tid + i * 256;
        b_r[i] = t >> 5;
        b_c[i] = t & 31;
    }

    auto load_stage = [&](int stage, int chunk) {
        uint32_t as = sb + stage * STAGE_BYTES;
        uint32_t bs = as + A_TILE_BYTES;
#pragma unroll
        for (int i = 0; i < 4; i++)
            cp16(as + a_r[i] * AROWB + a_c[i] * 16,
                 A + (size_t)a_g[i] * HID + chunk * BK + a_c[i] * 8);
#pragma unroll
        for (int i = 0; i < 8; i++)
            cp16(bs + b_r[i] * BROWB + b_c[i] * 16,
                 W + (size_t)(chunk * BK + b_r[i]) * N + n0 + b_c[i] * 8);
    };

    const uint32_t a_off = (warp_m * 64 + (lane & 15)) * AROWB + (lane >> 4) * 16;
    const uint32_t b_off = (lane & 15) * BROWB + (lane >> 4) * 16 + warp_n * 128;

    float c[4][8][4];
#pragma unroll
    for (int mt = 0; mt < 4; mt++)
#pragma unroll
        for (int nt = 0; nt < 8; nt++)
#pragma unroll
            for (int j = 0; j < 4; j++) c[mt][nt][j] = 0.f;

    const int NC = HID / BK;  // 64

    load_stage(0, 0); cp_commit();
    load_stage(1, 1); cp_commit();
    load_stage(2, 2); cp_commit();

    for (int ch = 0; ch < NC; ch++) {
        cp_wait<2>();
        __syncthreads();

        if (ch + 3 < NC) load_stage((ch + 3) % STAGES, ch + 3);
        cp_commit();

        const uint32_t as = sb + (ch % STAGES) * STAGE_BYTES;
        const uint32_t bs = as + A_TILE_BYTES;
        const uint32_t aL = as + a_off;
        const uint32_t bL = bs + b_off;

#pragma unroll
        for (int ks = 0; ks < 4; ks++) {
            uint32_t af[4][4], bf[8][2];
#pragma unroll
            for (int mt = 0; mt < 4; mt++)
                LDSM4(af[mt][0], af[mt][1], af[mt][2], af[mt][3],
                      aL + mt * 16 * AROWB + ks * 32);
#pragma unroll
            for (int pr = 0; pr < 4; pr++)
                LDSM4T(bf[2 * pr][0], bf[2 * pr][1], bf[2 * pr + 1][0], bf[2 * pr + 1][1],
                       bL + ks * 16 * BROWB + pr * 32);
#pragma unroll
            for (int mt = 0; mt < 4; mt++)
#pragma unroll
                for (int nt = 0; nt < 8; nt++)
                    mma_f16(c[mt][nt], af[mt][0], af[mt][1], af[mt][2], af[mt][3],
                            bf[nt][0], bf[nt][1]);
        }
        __syncthreads();
    }

    // epilogue: scatter to true rows; suppress padding rows
#pragma unroll
    for (int mt = 0; mt < 4; mt++) {
        int r0 = warp_m * 64 + mt * 16 + lm;
        int r1 = r0 + 8;
        bool on0 = (m0 + r0 < limit);
        bool on1 = (m0 + r1 < limit);
        CT* p0 = C + (size_t)idx_s[r0] * N + n0 + warp_n * 64;
        CT* p1 = C + (size_t)idx_s[r1] * N + n0 + warp_n * 64;
#pragma unroll
        for (int nt = 0; nt < 8; nt++) {
            int col = nt * 8 + 2 * lq;
            if (on0) store2(p0 + col, c[mt][nt][0], c[mt][nt][1]);
            if (on1) store2(p1 + col, c[mt][nt][2], c[mt][nt][3]);
        }
    }
}

// ---------------- RoPE ----------------
__global__ void rope_kernel(const __half* __restrict__ qkv, const int* __restrict__ pos_ids,
                            __half* __restrict__ q, __half* __restrict__ k) {
    int idx = blockIdx.x * blockDim.x + threadIdx.x;
    if (idx >= MTOK * NH * 64) return;
    int i = idx & 63;
    int h = (idx >> 6) & 31;
    int m = idx >> 11;

    float pos = (float)pos_ids[m];
    float freq = expf(-(float)i * (9.210340371976184f / 64.f));
    float ang = pos * freq;
    float cv = cosf(ang);
    float sv = sinf(ang);
    const float scale = 0.088388347648318447f;

    const __half* qs = qkv + (size_t)m * QKVN + h * HD;
    const __half* ks = qs + HID;
    float q0 = __half2float(qs[i]), q1 = __half2float(qs[i + 64]);
    float k0 = __half2float(ks[i]), k1 = __half2float(ks[i + 64]);

    size_t o = (size_t)m * HID + h * HD;
    q[o + i]      = __float2half((q0 * cv - q1 * sv) * scale);
    q[o + i + 64] = __float2half((q1 * cv + q0 * sv) * scale);
    k[o + i]      = __float2half(k0 * cv - k1 * sv);
    k[o + i + 64] = __float2half(k1 * cv + k0 * sv);
}

// ---------------- fp16 flash attention, double-buffered K/V ----------------
__global__ __launch_bounds__(256)
void attn_mma(const __half* __restrict__ Q, const __half* __restrict__ Kg,
              const __half* __restrict__ Vt, __half* __restrict__ ctx) {
    extern __shared__ char smem[];
    const uint32_t sb = smem_u32(smem);
    const int tid = threadIdx.x;
    const int warp = tid >> 5;
    const int lane = tid & 31;
    const int lm = lane >> 2;
    const int lq = lane & 3;
    const int b = blockIdx.z;
    const int h = blockIdx.y;
    const int qi = (int)gridDim.x - 1 - (int)blockIdx.x;
    const int qb = qi * 128;

    const uint32_t kvb[2] = {sb + AKV0_OFF, sb + AKV1_OFF};

    auto load_tile = [&](int t, int buf) {
        uint32_t kb = kvb[buf];
        uint32_t vb = kvb[buf] + 64 * QROWB;
#pragma unroll
        for (int i = 0; i < 4; i++) {
            int g = tid + i * 256;
            int r = g >> 4, c = g & 15;
            cp16(kb + r * QROWB + c * 16,
                 Kg + (size_t)(b * SEQ + t * 64 + r) * HID + h * HD + c * 8);
        }
#pragma unroll
        for (int i = 0; i < 4; i++) {
            int g = tid + i * 256;
            int r = g >> 3, c = g & 7;
            cp16(vb + r * VROWB + c * 16,
                 Vt + ((size_t)(b * NH + h) * HD + r) * SEQ + t * 64 + c * 8);
        }
    };

#pragma unroll
    for (int i = 0; i < 8; i++) {
        int g = tid + i * 256;
        int r = g >> 4, c = g & 15;
        cp16(sb + AQS_OFF + r * QROWB + c * 16,
             Q + (size_t)(b * SEQ + qb + r) * HID + h * HD + c * 8);
    }
    load_tile(0, 0);
    cp_commit();

    const int a_row = lane & 15;
    const int a_hi  = (lane >> 4) * 16;
    const int b_row = (lane & 7) | ((lane >> 1) & 8);
    const int b_hi  = ((lane >> 3) & 1) * 16;
    const uint32_t qA = sb + AQS_OFF + (warp * 16 + a_row) * QROWB + a_hi;
    const uint32_t pA = sb + APS_OFF + (warp * 16 + a_row) * VROWB + a_hi;
    const uint32_t kOff = b_row * QROWB + b_hi;
    const uint32_t vOff = 64 * QROWB + b_row * VROWB + b_hi;

    float o[16][4];
#pragma unroll
    for (int nt = 0; nt < 16; nt++)
#pragma unroll
        for (int j = 0; j < 4; j++) o[nt][j] = 0.f;
    float mr0 = -1e30f, mr1 = -1e30f, l0 = 0.f, l1 = 0.f;
    const int r0g = qb + warp * 16 + lm;
    const int r1g = r0g + 8;

    const int ntiles = 2 * qi + 2;
    for (int t = 0; t < ntiles; t++) {
        const int buf = t & 1;
        if (t + 1 < ntiles) {
            load_tile(t + 1, buf ^ 1);
            cp_commit();
            cp_wait<1>();
        } else {
            cp_wait<0>();
        }
        __syncthreads();

        const uint32_t kB = kvb[buf] + kOff;
        const uint32_t vB = kvb[buf] + vOff;

        float s_[8][4];
#pragma unroll
        for (int nt = 0; nt < 8; nt++)
#pragma unroll
            for (int j = 0; j < 4; j++) s_[nt][j] = 0.f;

#pragma unroll
        for (int ks = 0; ks < 8; ks++) {
            uint32_t a0, a1, a2, a3;
            LDSM4(a0, a1, a2, a3, qA + ks * 32);
#pragma unroll
            for (int pr = 0; pr < 4; pr++) {
                uint32_t b0, b1, b2, b3;
                LDSM4(b0, b1, b2, b3, kB + pr * 16 * QROWB + ks * 32);
                mma_f16(s_[2 * pr],     a0, a1, a2, a3, b0, b1);
                mma_f16(s_[2 * pr + 1], a0, a1, a2, a3, b2, b3);
            }
        }

        if (t >= 2 * qi) {
#pragma unroll
            for (int nt = 0; nt < 8; nt++) {
                int cb = t * 64 + nt * 8 + 2 * lq;
                if (cb > r0g)     s_[nt][0] = -1e30f;
                if (cb + 1 > r0g) s_[nt][1] = -1e30f;
                if (cb > r1g)     s_[nt][2] = -1e30f;
                if (cb + 1 > r1g) s_[nt][3] = -1e30f;
            }
        }

        float tm0 = -1e30f, tm1 = -1e30f;
#pragma unroll
        for (int nt = 0; nt < 8; nt++) {
            tm0 = fmaxf(tm0, fmaxf(s_[nt][0], s_[nt][1]));
            tm1 = fmaxf(tm1, fmaxf(s_[nt][2], s_[nt][3]));
        }
        tm0 = fmaxf(tm0, __shfl_xor_sync(0xffffffffu, tm0, 1));
        tm0 = fmaxf(tm0, __shfl_xor_sync(0xffffffffu, tm0, 2));
        tm1 = fmaxf(tm1, __shfl_xor_sync(0xffffffffu, tm1, 1));
        tm1 = fmaxf(tm1, __shfl_xor_sync(0xffffffffu, tm1, 2));
        float mn0 = fmaxf(mr0, tm0), mn1 = fmaxf(mr1, tm1);
        float c0 = __expf(mr0 - mn0), c1 = __expf(mr1 - mn1);
        float ps0 = 0.f, ps1 = 0.f;
#pragma unroll
        for (int nt = 0; nt < 8; nt++) {
            s_[nt][0] = __expf(s_[nt][0] - mn0);
            s_[nt][1] = __expf(s_[nt][1] - mn0);
            s_[nt][2] = __expf(s_[nt][2] - mn1);
            s_[nt][3] = __expf(s_[nt][3] - mn1);
            ps0 += s_[nt][0] + s_[nt][1];
            ps1 += s_[nt][2] + s_[nt][3];
        }
        l0 = l0 * c0 + ps0;
        l1 = l1 * c1 + ps1;
#pragma unroll
        for (int nt = 0; nt < 16; nt++) {
            o[nt][0] *= c0; o[nt][1] *= c0;
            o[nt][2] *= c1; o[nt][3] *= c1;
        }
        mr0 = mn0; mr1 = mn1;

#pragma unroll
        for (int nt = 0; nt < 8; nt++) {
            *(__half2*)(smem + APS_OFF + (warp * 16 + lm) * VROWB + (nt * 8 + 2 * lq) * 2)
                = __floats2half2_rn(s_[nt][0], s_[nt][1]);
            *(__half2*)(smem + APS_OFF + (warp * 16 + lm + 8) * VROWB + (nt * 8 + 2 * lq) * 2)
                = __floats2half2_rn(s_[nt][2], s_[nt][3]);
        }
        __syncwarp();

#pragma unroll
        for (int ks = 0; ks < 4; ks++) {
            uint32_t a0, a1, a2, a3;
            LDSM4(a0, a1, a2, a3, pA + ks * 32);
#pragma unroll
            for (int pr = 0; pr < 8; pr++) {
                uint32_t b0, b1, b2, b3;
                LDSM4(b0, b1, b2, b3, vB + pr * 16 * VROWB + ks * 32);
                mma_f16(o[2 * pr],     a0, a1, a2, a3, b0, b1);
                mma_f16(o[2 * pr + 1], a0, a1, a2, a3, b2, b3);
            }
        }
        __syncthreads();
    }

    l0 += __shfl_xor_sync(0xffffffffu, l0, 1);
    l0 += __shfl_xor_sync(0xffffffffu, l0, 2);
    l1 += __shfl_xor_sync(0xffffffffu, l1, 1);
    l1 += __shfl_xor_sync(0xffffffffu, l1, 2);
    float i0 = 1.f / l0, i1 = 1.f / l1;

#pragma unroll
    for (int nt = 0; nt < 16; nt++) {
        int col = nt * 8 + 2 * lq;
        *(__half2*)&ctx[(size_t)(b * SEQ + r0g) * HID + h * HD + col] =
            __floats2half2_rn(o[nt][0] * i0, o[nt][1] * i0);
        *(__half2*)&ctx[(size_t)(b * SEQ + r1g) * HID + h * HD + col] =
            __floats2half2_rn(o[nt][2] * i1, o[nt][3] * i1);
    }
}

// ---------------- launch ----------------
extern "C" void kernel_launch(void* const* d_in, const int* in_sizes, int n_in,
                              void* d_out, int out_size) {
    const float* hidden = (const float*)d_in[0];
    const int*   tt     = (const int*)d_in[1];
    const int*   pos    = (const int*)d_in[2];
    const float* wvq    = (const float*)d_in[3];
    const float* wlq    = (const float*)d_in[4];
    const float* wvd    = (const float*)d_in[5];
    const float* wld    = (const float*)d_in[6];
    float* out = (float*)d_out;

    __half *qkv_p, *q_p, *k_p, *vt_p, *ctx_p, *hidh_p, *wr_p;
    cudaGetSymbolAddress((void**)&qkv_p, g_qkv);
    cudaGetSymbolAddress((void**)&q_p, g_q);
    cudaGetSymbolAddress((void**)&k_p, g_k);
    cudaGetSymbolAddress((void**)&vt_p, g_vt);
    cudaGetSymbolAddress((void**)&ctx_p, g_ctx);
    cudaGetSymbolAddress((void**)&hidh_p, g_hidh);
    cudaGetSymbolAddress((void**)&wr_p, g_wr);

    __half* wr_vq = wr_p + WR_VQ;
    __half* wr_lq = wr_p + WR_LQ;
    __half* wr_vd = wr_p + WR_VD;
    __half* wr_ld = wr_p + WR_LD;

    cudaFuncSetAttribute((const void*)&gemm_tc<__half>, cudaFuncAttributeMaxDynamicSharedMemorySize, GEMM_SMEM);
    cudaFuncSetAttribute((const void*)&gemm_tc<float>, cudaFuncAttributeMaxDynamicSharedMemorySize, GEMM_SMEM);
    cudaFuncSetAttribute(attn_mma, cudaFuncAttributeMaxDynamicSharedMemorySize, ATT_SMEM);

    zero_cnt_kernel<<<1, 32>>>();
    route_kernel<<<MTOK / 256, 256>>>(tt);
    pack_kernel<<<1, 256>>>();

    // pre-pass: fp32->fp16 converts
    {
        int n4w = (int)((size_t)HID * QKVN / 4);
        f2h_kernel<<<(n4w + 255) / 256, 256>>>((const float4*)wvq, (__half2*)wr_vq, n4w);
        f2h_kernel<<<(n4w + 255) / 256, 256>>>((const float4*)wlq, (__half2*)wr_lq, n4w);
        int n4d = (int)((size_t)HID * HID / 4);
        f2h_kernel<<<(n4d + 255) / 256, 256>>>((const float4*)wvd, (__half2*)wr_vd, n4d);
        f2h_kernel<<<(n4d + 255) / 256, 256>>>((const float4*)wld, (__half2*)wr_ld, n4d);
        int n4h = (int)((size_t)MTOK * HID / 4);
        f2h_kernel<<<(n4h + 255) / 256, 256>>>((const float4*)hidden, (__half2*)hidh_p, n4h);
    }

    // QKV projection: ONE merged launch over both experts
    {
        dim3 grid(MTOK / BM + 2, QKVN / BN);
        gemm_tc<__half><<<grid, 256, GEMM_SMEM>>>(hidh_p, wr_vq, wr_lq, qkv_p, QKVN);
    }

    // RoPE + V transpose
    rope_kernel<<<(MTOK * NH * 64) / 256, 256>>>(qkv_p, pos, q_p, k_p);
    {
        dim3 gv(SEQ / 32, HD / 32, BATCH * NH);
        vtrans_kernel<<<gv, 256>>>(qkv_p, vt_p);
    }

    // fp16 flash attention
    {
        dim3 grid(SEQ / 128, NH, BATCH);
        attn_mma<<<grid, 256, ATT_SMEM>>>(q_p, k_p, vt_p, ctx_p);
    }

    // Dense projection: ONE merged launch over both experts
    {
        dim3 grid(MTOK / BM + 2, HID / BN);
        gemm_tc<float><<<grid, 256, GEMM_SMEM>>>(ctx_p, wr_vd, wr_ld, out, HID);
    }
}

// round 12
// speedup vs baseline: 1.9515x; 1.0131x over previous
#include <cuda_runtime.h>
#include <cuda_fp16.h>
#include <math.h>
#include <stdint.h>

// Problem constants
#define BATCH 2
#define SEQ   2048
#define NH    32
#define HD    128
#define HID   4096           // NH*HD
#define QKVN  12288          // 3*HID
#define MTOK  (BATCH*SEQ)    // 4096 tokens

// GEMM tile config (mma.sync m16n8k16 fp16; A ldmatrix, B ldmatrix.trans)
#define BM 128
#define BN 256
#define BK 64
#define STAGES 4
#define AROWB 144
#define BROWB 528
#define A_TILE_BYTES (128 * AROWB)               // 18432
#define B_TILE_BYTES (64 * BROWB)                // 33792
#define STAGE_BYTES (A_TILE_BYTES + B_TILE_BYTES)// 52224
#define GEMM_SMEM (STAGES * STAGE_BYTES)         // 208896

// Attention smem layout (fp16, double-buffered K/V)
#define QROWB 272
#define VROWB 144
#define AQS_OFF 0
#define KV_STAGE (64 * QROWB + 128 * VROWB)      // 35840
#define AKV0_OFF (128 * QROWB)
#define AKV1_OFF (AKV0_OFF + KV_STAGE)
#define APS_OFF (AKV1_OFF + KV_STAGE)
#define ATT_SMEM (APS_OFF + 128 * VROWB)         // 124928

// f2h merged-pass segment boundaries (in float4 units)
#define F4_WQKV  12582912                         // HID*QKVN/4
#define F4_WD    4194304                          // HID*HID/4
#define F4_S0    F4_WQKV
#define F4_S1    (2 * F4_WQKV)
#define F4_S2    (F4_S1 + F4_WD)
#define F4_S3    (F4_S2 + F4_WD)
#define F4_TOT   (F4_S3 + F4_WD)                  // 37748736
#define F4_HALF  (F4_TOT / 2)                     // 18874368

// ---------------- scratch (device globals) -------------
__device__ __half g_qkv[(size_t)MTOK * QKVN];
__device__ __half g_q[(size_t)MTOK * HID];
__device__ __half g_k[(size_t)MTOK * HID];
__device__ __half g_vt[(size_t)BATCH * NH * HD * SEQ];
__device__ __half g_ctx[(size_t)MTOK * HID];
__device__ __half g_hidh[(size_t)MTOK * HID];
#define WR_VQ 0
#define WR_LQ ((size_t)HID * QKVN)
#define WR_VD (2 * (size_t)HID * QKVN)
#define WR_LD (2 * (size_t)HID * QKVN + (size_t)HID * HID)
__device__ __half g_wr[2 * (size_t)HID * QKVN + 2 * (size_t)HID * HID];
__device__ int    g_cnt[2];
__device__ int    g_idx[2][MTOK];
__device__ int    g_idxc[MTOK + 256];
__device__ int    g_seg[4];                      // {pad0, pad0+pad1, c0, c1}

// ---------------- helpers ----------------
__device__ __forceinline__ uint32_t smem_u32(const void* p) {
    uint32_t a;
    asm("{ .reg .u64 t; cvta.to.shared.u64 t, %1; cvt.u32.u64 %0, t; }" : "=r"(a) : "l"(p));
    return a;
}
__device__ __forceinline__ void cp16(uint32_t dst, const void* src) {
    asm volatile("cp.async.cg.shared.global [%0], [%1], 16;" :: "r"(dst), "l"(src));
}
__device__ __forceinline__ void cp_commit() {
    asm volatile("cp.async.commit_group;" ::: "memory");
}
template <int N>
__device__ __forceinline__ void cp_wait() {
    asm volatile("cp.async.wait_group %0;" :: "n"(N) : "memory");
}
__device__ __forceinline__ void mma_f16(float* c, uint32_t a0, uint32_t a1, uint32_t a2, uint32_t a3,
                                        uint32_t b0, uint32_t b1) {
    asm volatile(
        "mma.sync.aligned.m16n8k16.row.col.f32.f16.f16.f32 "
        "{%0,%1,%2,%3}, {%4,%5,%6,%7}, {%8,%9}, {%0,%1,%2,%3};"
        : "+f"(c[0]), "+f"(c[1]), "+f"(c[2]), "+f"(c[3])
        : "r"(a0), "r"(a1), "r"(a2), "r"(a3), "r"(b0), "r"(b1));
}
#define LDSM4(r0, r1, r2, r3, addr)                                               \
    asm volatile("ldmatrix.sync.aligned.m8n8.x4.shared.b16 {%0,%1,%2,%3}, [%4];"   \
        : "=r"(r0), "=r"(r1), "=r"(r2), "=r"(r3) : "r"(addr))
#define LDSM4T(r0, r1, r2, r3, addr)                                              \
    asm volatile("ldmatrix.sync.aligned.m8n8.x4.trans.shared.b16 {%0,%1,%2,%3}, [%4];" \
        : "=r"(r0), "=r"(r1), "=r"(r2), "=r"(r3) : "r"(addr))

__device__ __forceinline__ void store2(float* p, float a, float b) {
    *(float2*)p = make_float2(a, b);
}
__device__ __forceinline__ void store2(__half* p, float a, float b) {
    *(__half2*)p = __floats2half2_rn(a, b);
}

// ---------------- merged pre-pass: ALL fp32->fp16 converts in one kernel ----------------
// Segment map (float4 idx): [0,S0) wvq  [S0,S1) wlq  [S1,S2) wvd  [S2,S3) wld  [S3,TOT) hidden
// First 4 destinations are contiguous in g_wr; hidden goes to g_hidh.
__global__ __launch_bounds__(256)
void f2h_all(const float4* __restrict__ wvq, const float4* __restrict__ wlq,
             const float4* __restrict__ wvd, const float4* __restrict__ wld,
             const float4* __restrict__ hid) {
    int t = blockIdx.x * blockDim.x + threadIdx.x;
    if (t >= F4_HALF) return;
#pragma unroll
    for (int s = 0; s < 2; s++) {
        int i = t + s * F4_HALF;
        const float4* src;
        __half2* dst;
        if (i < F4_S1) {
            src = (i < F4_S0) ? (wvq + i) : (wlq + (i - F4_S0));
            dst = (__half2*)g_wr + 2 * (size_t)i;
        } else if (i < F4_S3) {
            src = (i < F4_S2) ? (wvd + (i - F4_S1)) : (wld + (i - F4_S2));
            dst = (__half2*)g_wr + 2 * (size_t)i;
        } else {
            src = hid + (i - F4_S3);
            dst = (__half2*)g_hidh + 2 * (size_t)(i - F4_S3);
        }
        float4 v = *src;
        dst[0] = __floats2half2_rn(v.x, v.y);
        dst[1] = __floats2half2_rn(v.z, v.w);
    }
}

// V transpose: g_vt[bh][d][s]
__global__ __launch_bounds__(256)
void vtrans_kernel(const __half* __restrict__ qkv, __half* __restrict__ Vt) {
    __shared__ float t[32][33];
    int bh = blockIdx.z;
    int b = bh >> 5, h = bh & 31;
    int s0 = blockIdx.x * 32;
    int d0 = blockIdx.y * 32;
    int x = threadIdx.x & 31;
    int y = threadIdx.x >> 5;
#pragma unroll
    for (int i = 0; i < 32; i += 8)
        t[y + i][x] = __half2float(qkv[(size_t)(b * SEQ + s0 + y + i) * QKVN + 2 * HID + h * HD + d0 + x]);
    __syncthreads();
#pragma unroll
    for (int i = 0; i < 32; i += 8)
        Vt[((size_t)bh * HD + d0 + y + i) * SEQ + s0 + x] = __float2half(t[x][y + i]);
}

// ---------------- mask / routing / packing ----------------
__global__ void zero_cnt_kernel() {
    if (threadIdx.x < 2) g_cnt[threadIdx.x] = 0;
}
__global__ void route_kernel(const int* __restrict__ tt) {
    int idx = blockIdx.x * blockDim.x + threadIdx.x;
    if (idx >= MTOK) return;
    int s = idx & (SEQ - 1);
    int vis = (s + 1 < SEQ) && (tt[idx] == 1) && (tt[idx + 1] == 1);
    int e = vis ? 0 : 1;
    int pos = atomicAdd(&g_cnt[e], 1);
    g_idx[e][pos] = idx;
}
__global__ void pack_kernel() {
    int c0 = g_cnt[0], c1 = g_cnt[1];
    int pad0 = (c0 + 127) & ~127;
    int pad1 = (c1 + 127) & ~127;
    if (threadIdx.x == 0) {
        g_seg[0] = pad0;
        g_seg[1] = pad0 + pad1;
        g_seg[2] = c0;
        g_seg[3] = c1;
    }
    for (int i = threadIdx.x; i < pad0; i += blockDim.x)
        g_idxc[i] = g_idx[0][i < c0 ? i : c0 - 1];
    for (int j = threadIdx.x; j < pad1; j += blockDim.x)
        g_idxc[pad0 + j] = g_idx[1][j < c1 ? j : c1 - 1];
}

// ---------------- merged-expert fp16 GEMM (single sync/iter) ----------------
template <typename CT>
__global__ __launch_bounds__(256, 1)
void gemm_tc(const __half* __restrict__ A,
             const __half* __restrict__ Wvis, const __half* __restrict__ Wlang,
             CT* __restrict__ C, int N) {
    __shared__ int idx_s[BM];
    extern __shared__ char smem[];
    const uint32_t sb = smem_u32(smem);
    const int tid = threadIdx.x;
    const int wid = tid >> 5;
    const int lane = tid & 31;
    const int lm = lane >> 2;
    const int lq = lane & 3;
    const int warp_m = wid & 1;
    const int warp_n = wid >> 1;
    const int m0 = blockIdx.x * BM;
    const int n0 = blockIdx.y * BN;

    const int s0 = __ldg(&g_seg[0]);
    const int s1 = __ldg(&g_seg[1]);
    if (m0 >= s1) return;
    const bool is_vis = (m0 < s0);
    const __half* W = is_vis ? Wvis : Wlang;
    const int limit = is_vis ? __ldg(&g_seg[2]) : (s0 + __ldg(&g_seg[3]));

    if (tid < BM) idx_s[tid] = g_idxc[m0 + tid];
    __syncthreads();

    int a_r[4], a_c[4];
#pragma unroll
    for (int i = 0; i < 4; i++) {
        int t = tid + i * 256;
        a_r[i] = t >> 3;
        a_c[i] = t & 7;
    }
    int a_g[4];
#pragma unroll
    for (int i = 0; i < 4; i++) a_g[i] = idx_s[a_r[i]];
    int b_r[8], b_c[8];
#pragma unroll
    for (int i = 0; i < 8; i++) {
        int t = tid + i * 256;
        b_r[i] = t >> 5;
        b_c[i] = t & 31;
    }

    auto load_stage = [&](int stage, int chunk) {
        uint32_t as = sb + stage * STAGE_BYTES;
        uint32_t bs = as + A_TILE_BYTES;
#pragma unroll
        for (int i = 0; i < 4; i++)
            cp16(as + a_r[i] * AROWB + a_c[i] * 16,
                 A + (size_t)a_g[i] * HID + chunk * BK + a_c[i] * 8);
#pragma unroll
        for (int i = 0; i < 8; i++)
            cp16(bs + b_r[i] * BROWB + b_c[i] * 16,
                 W + (size_t)(chunk * BK + b_r[i]) * N + n0 + b_c[i] * 8);
    };

    const uint32_t a_off = (warp_m * 64 + (lane & 15)) * AROWB + (lane >> 4) * 16;
    const uint32_t b_off = (lane & 15) * BROWB + (lane >> 4) * 16 + warp_n * 128;

    float c[4][8][4];
#pragma unroll
    for (int mt = 0; mt < 4; mt++)
#pragma unroll
        for (int nt = 0; nt < 8; nt++)
#pragma unroll
            for (int j = 0; j < 4; j++) c[mt][nt][j] = 0.f;

    const int NC = HID / BK;  // 64

    load_stage(0, 0); cp_commit();
    load_stage(1, 1); cp_commit();
    load_stage(2, 2); cp_commit();

    for (int ch = 0; ch < NC; ch++) {
        cp_wait<2>();
        __syncthreads();
        // Single barrier per iteration: loads below write stage (ch+3)%4,
        // whose last readers (chunk ch-1) are all past the barrier above.
        if (ch + 3 < NC) load_stage((ch + 3) % STAGES, ch + 3);
        cp_commit();

        const uint32_t as = sb + (ch % STAGES) * STAGE_BYTES;
        const uint32_t bs = as + A_TILE_BYTES;
        const uint32_t aL = as + a_off;
        const uint32_t bL = bs + b_off;

#pragma unroll
        for (int ks = 0; ks < 4; ks++) {
            uint32_t af[4][4], bf[8][2];
#pragma unroll
            for (int mt = 0; mt < 4; mt++)
                LDSM4(af[mt][0], af[mt][1], af[mt][2], af[mt][3],
                      aL + mt * 16 * AROWB + ks * 32);
#pragma unroll
            for (int pr = 0; pr < 4; pr++)
                LDSM4T(bf[2 * pr][0], bf[2 * pr][1], bf[2 * pr + 1][0], bf[2 * pr + 1][1],
                       bL + ks * 16 * BROWB + pr * 32);
#pragma unroll
            for (int mt = 0; mt < 4; mt++)
#pragma unroll
                for (int nt = 0; nt < 8; nt++)
                    mma_f16(c[mt][nt], af[mt][0], af[mt][1], af[mt][2], af[mt][3],
                            bf[nt][0], bf[nt][1]);
        }
    }

    // epilogue: scatter to true rows; suppress padding rows
#pragma unroll
    for (int mt = 0; mt < 4; mt++) {
        int r0 = warp_m * 64 + mt * 16 + lm;
        int r1 = r0 + 8;
        bool on0 = (m0 + r0 < limit);
        bool on1 = (m0 + r1 < limit);
        CT* p0 = C + (size_t)idx_s[r0] * N + n0 + warp_n * 64;
        CT* p1 = C + (size_t)idx_s[r1] * N + n0 + warp_n * 64;
#pragma unroll
        for (int nt = 0; nt < 8; nt++) {
            int col = nt * 8 + 2 * lq;
            if (on0) store2(p0 + col, c[mt][nt][0], c[mt][nt][1]);
            if (on1) store2(p1 + col, c[mt][nt][2], c[mt][nt][3]);
        }
    }
}

// ---------------- RoPE ----------------
__global__ void rope_kernel(const __half* __restrict__ qkv, const int* __restrict__ pos_ids,
                            __half* __restrict__ q, __half* __restrict__ k) {
    int idx = blockIdx.x * blockDim.x + threadIdx.x;
    if (idx >= MTOK * NH * 64) return;
    int i = idx & 63;
    int h = (idx >> 6) & 31;
    int m = idx >> 11;

    float pos = (float)pos_ids[m];
    float freq = expf(-(float)i * (9.210340371976184f / 64.f));
    float ang = pos * freq;
    float cv = cosf(ang);
    float sv = sinf(ang);
    const float scale = 0.088388347648318447f;

    const __half* qs = qkv + (size_t)m * QKVN + h * HD;
    const __half* ks = qs + HID;
    float q0 = __half2float(qs[i]), q1 = __half2float(qs[i + 64]);
    float k0 = __half2float(ks[i]), k1 = __half2float(ks[i + 64]);

    size_t o = (size_t)m * HID + h * HD;
    q[o + i]      = __float2half((q0 * cv - q1 * sv) * scale);
    q[o + i + 64] = __float2half((q1 * cv + q0 * sv) * scale);
    k[o + i]      = __float2half(k0 * cv - k1 * sv);
    k[o + i + 64] = __float2half(k1 * cv + k0 * sv);
}

// ---------------- fp16 flash attention, double-buffered K/V ----------------
__global__ __launch_bounds__(256)
void attn_mma(const __half* __restrict__ Q, const __half* __restrict__ Kg,
              const __half* __restrict__ Vt, __half* __restrict__ ctx) {
    extern __shared__ char smem[];
    const uint32_t sb = smem_u32(smem);
    const int tid = threadIdx.x;
    const int warp = tid >> 5;
    const int lane = tid & 31;
    const int lm = lane >> 2;
    const int lq = lane & 3;
    const int b = blockIdx.z;
    const int h = blockIdx.y;
    const int qi = (int)gridDim.x - 1 - (int)blockIdx.x;
    const int qb = qi * 128;

    const uint32_t kvb[2] = {sb + AKV0_OFF, sb + AKV1_OFF};

    auto load_tile = [&](int t, int buf) {
        uint32_t kb = kvb[buf];
        uint32_t vb = kvb[buf] + 64 * QROWB;
#pragma unroll
        for (int i = 0; i < 4; i++) {
            int g = tid + i * 256;
            int r = g >> 4, c = g & 15;
            cp16(kb + r * QROWB + c * 16,
                 Kg + (size_t)(b * SEQ + t * 64 + r) * HID + h * HD + c * 8);
        }
#pragma unroll
        for (int i = 0; i < 4; i++) {
            int g = tid + i * 256;
            int r = g >> 3, c = g & 7;
            cp16(vb + r * VROWB + c * 16,
                 Vt + ((size_t)(b * NH + h) * HD + r) * SEQ + t * 64 + c * 8);
        }
    };

#pragma unroll
    for (int i = 0; i < 8; i++) {
        int g = tid + i * 256;
        int r = g >> 4, c = g & 15;
        cp16(sb + AQS_OFF + r * QROWB + c * 16,
             Q + (size_t)(b * SEQ + qb + r) * HID + h * HD + c * 8);
    }
    load_tile(0, 0);
    cp_commit();

    const int a_row = lane & 15;
    const int a_hi  = (lane >> 4) * 16;
    const int b_row = (lane & 7) | ((lane >> 1) & 8);
    const int b_hi  = ((lane >> 3) & 1) * 16;
    const uint32_t qA = sb + AQS_OFF + (warp * 16 + a_row) * QROWB + a_hi;
    const uint32_t pA = sb + APS_OFF + (warp * 16 + a_row) * VROWB + a_hi;
    const uint32_t kOff = b_row * QROWB + b_hi;
    const uint32_t vOff = 64 * QROWB + b_row * VROWB + b_hi;

    float o[16][4];
#pragma unroll
    for (int nt = 0; nt < 16; nt++)
#pragma unroll
        for (int j = 0; j < 4; j++) o[nt][j] = 0.f;
    float mr0 = -1e30f, mr1 = -1e30f, l0 = 0.f, l1 = 0.f;
    const int r0g = qb + warp * 16 + lm;
    const int r1g = r0g + 8;

    const int ntiles = 2 * qi + 2;
    for (int t = 0; t < ntiles; t++) {
        const int buf = t & 1;
        if (t + 1 < ntiles) {
            load_tile(t + 1, buf ^ 1);
            cp_commit();
            cp_wait<1>();
        } else {
            cp_wait<0>();
        }
        __syncthreads();

        const uint32_t kB = kvb[buf] + kOff;
        const uint32_t vB = kvb[buf] + vOff;

        float s_[8][4];
#pragma unroll
        for (int nt = 0; nt < 8; nt++)
#pragma unroll
            for (int j = 0; j < 4; j++) s_[nt][j] = 0.f;

#pragma unroll
        for (int ks = 0; ks < 8; ks++) {
            uint32_t a0, a1, a2, a3;
            LDSM4(a0, a1, a2, a3, qA + ks * 32);
#pragma unroll
            for (int pr = 0; pr < 4; pr++) {
                uint32_t b0, b1, b2, b3;
                LDSM4(b0, b1, b2, b3, kB + pr * 16 * QROWB + ks * 32);
                mma_f16(s_[2 * pr],     a0, a1, a2, a3, b0, b1);
                mma_f16(s_[2 * pr + 1], a0, a1, a2, a3, b2, b3);
            }
        }

        if (t >= 2 * qi) {
#pragma unroll
            for (int nt = 0; nt < 8; nt++) {
                int cb = t * 64 + nt * 8 + 2 * lq;
                if (cb > r0g)     s_[nt][0] = -1e30f;
                if (cb + 1 > r0g) s_[nt][1] = -1e30f;
                if (cb > r1g)     s_[nt][2] = -1e30f;
                if (cb + 1 > r1g) s_[nt][3] = -1e30f;
            }
        }

        float tm0 = -1e30f, tm1 = -1e30f;
#pragma unroll
        for (int nt = 0; nt < 8; nt++) {
            tm0 = fmaxf(tm0, fmaxf(s_[nt][0], s_[nt][1]));
            tm1 = fmaxf(tm1, fmaxf(s_[nt][2], s_[nt][3]));
        }
        tm0 = fmaxf(tm0, __shfl_xor_sync(0xffffffffu, tm0, 1));
        tm0 = fmaxf(tm0, __shfl_xor_sync(0xffffffffu, tm0, 2));
        tm1 = fmaxf(tm1, __shfl_xor_sync(0xffffffffu, tm1, 1));
        tm1 = fmaxf(tm1, __shfl_xor_sync(0xffffffffu, tm1, 2));
        float mn0 = fmaxf(mr0, tm0), mn1 = fmaxf(mr1, tm1);
        float c0 = __expf(mr0 - mn0), c1 = __expf(mr1 - mn1);
        float ps0 = 0.f, ps1 = 0.f;
#pragma unroll
        for (int nt = 0; nt < 8; nt++) {
            s_[nt][0] = __expf(s_[nt][0] - mn0);
            s_[nt][1] = __expf(s_[nt][1] - mn0);
            s_[nt][2] = __expf(s_[nt][2] - mn1);
            s_[nt][3] = __expf(s_[nt][3] - mn1);
            ps0 += s_[nt][0] + s_[nt][1];
            ps1 += s_[nt][2] + s_[nt][3];
        }
        l0 = l0 * c0 + ps0;
        l1 = l1 * c1 + ps1;
#pragma unroll
        for (int nt = 0; nt < 16; nt++) {
            o[nt][0] *= c0; o[nt][1] *= c0;
            o[nt][2] *= c1; o[nt][3] *= c1;
        }
        mr0 = mn0; mr1 = mn1;

#pragma unroll
        for (int nt = 0; nt < 8; nt++) {
            *(__half2*)(smem + APS_OFF + (warp * 16 + lm) * VROWB + (nt * 8 + 2 * lq) * 2)
                = __floats2half2_rn(s_[nt][0], s_[nt][1]);
            *(__half2*)(smem + APS_OFF + (warp * 16 + lm + 8) * VROWB + (nt * 8 + 2 * lq) * 2)
                = __floats2half2_rn(s_[nt][2], s_[nt][3]);
        }
        __syncwarp();

#pragma unroll
        for (int ks = 0; ks < 4; ks++) {
            uint32_t a0, a1, a2, a3;
            LDSM4(a0, a1, a2, a3, pA + ks * 32);
#pragma unroll
            for (int pr = 0; pr < 8; pr++) {
                uint32_t b0, b1, b2, b3;
                LDSM4(b0, b1, b2, b3, vB + pr * 16 * VROWB + ks * 32);
                mma_f16(o[2 * pr],     a0, a1, a2, a3, b0, b1);
                mma_f16(o[2 * pr + 1], a0, a1, a2, a3, b2, b3);
            }
        }
        __syncthreads();
    }

    l0 += __shfl_xor_sync(0xffffffffu, l0, 1);
    l0 += __shfl_xor_sync(0xffffffffu, l0, 2);
    l1 += __shfl_xor_sync(0xffffffffu, l1, 1);
    l1 += __shfl_xor_sync(0xffffffffu, l1, 2);
    float i0 = 1.f / l0, i1 = 1.f / l1;

#pragma unroll
    for (int nt = 0; nt < 16; nt++) {
        int col = nt * 8 + 2 * lq;
        *(__half2*)&ctx[(size_t)(b * SEQ + r0g) * HID + h * HD + col] =
            __floats2half2_rn(o[nt][0] * i0, o[nt][1] * i0);
        *(__half2*)&ctx[(size_t)(b * SEQ + r1g) * HID + h * HD + col] =
            __floats2half2_rn(o[nt][2] * i1, o[nt][3] * i1);
    }
}

// ---------------- launch ----------------
extern "C" void kernel_launch(void* const* d_in, const int* in_sizes, int n_in,
                              void* d_out, int out_size) {
    const float* hidden = (const float*)d_in[0];
    const int*   tt     = (const int*)d_in[1];
    const int*   pos    = (const int*)d_in[2];
    const float* wvq    = (const float*)d_in[3];
    const float* wlq    = (const float*)d_in[4];
    const float* wvd    = (const float*)d_in[5];
    const float* wld    = (const float*)d_in[6];
    float* out = (float*)d_out;

    __half *qkv_p, *q_p, *k_p, *vt_p, *ctx_p, *hidh_p, *wr_p;
    cudaGetSymbolAddress((void**)&qkv_p, g_qkv);
    cudaGetSymbolAddress((void**)&q_p, g_q);
    cudaGetSymbolAddress((void**)&k_p, g_k);
    cudaGetSymbolAddress((void**)&vt_p, g_vt);
    cudaGetSymbolAddress((void**)&ctx_p, g_ctx);
    cudaGetSymbolAddress((void**)&hidh_p, g_hidh);
    cudaGetSymbolAddress((void**)&wr_p, g_wr);

    __half* wr_vq = wr_p + WR_VQ;
    __half* wr_lq = wr_p + WR_LQ;
    __half* wr_vd = wr_p + WR_VD;
    __half* wr_ld = wr_p + WR_LD;

    cudaFuncSetAttribute((const void*)&gemm_tc<__half>, cudaFuncAttributeMaxDynamicSharedMemorySize, GEMM_SMEM);
    cudaFuncSetAttribute((const void*)&gemm_tc<float>, cudaFuncAttributeMaxDynamicSharedMemorySize, GEMM_SMEM);
    cudaFuncSetAttribute(attn_mma, cudaFuncAttributeMaxDynamicSharedMemorySize, ATT_SMEM);

    zero_cnt_kernel<<<1, 32>>>();
    route_kernel<<<MTOK / 256, 256>>>(tt);
    pack_kernel<<<1, 256>>>();

    // merged fp32->fp16 pre-pass (weights + hidden) in one launch
    f2h_all<<<(F4_HALF + 255) / 256, 256>>>((const float4*)wvq, (const float4*)wlq,
                                            (const float4*)wvd, (const float4*)wld,
                                            (const float4*)hidden);

    // QKV projection: merged experts
    {
        dim3 grid(MTOK / BM + 2, QKVN / BN);
        gemm_tc<__half><<<grid, 256, GEMM_SMEM>>>(hidh_p, wr_vq, wr_lq, qkv_p, QKVN);
    }

    // RoPE + V transpose
    rope_kernel<<<(MTOK * NH * 64) / 256, 256>>>(qkv_p, pos, q_p, k_p);
    {
        dim3 gv(SEQ / 32, HD / 32, BATCH * NH);
        vtrans_kernel<<<gv, 256>>>(qkv_p, vt_p);
    }

    // fp16 flash attention
    {
        dim3 grid(SEQ / 128, NH, BATCH);
        attn_mma<<<grid, 256, ATT_SMEM>>>(q_p, k_p, vt_p, ctx_p);
    }

    // Dense projection: merged experts
    {
        dim3 grid(MTOK / BM + 2, HID / BN);
        gemm_tc<float><<<grid, 256, GEMM_SMEM>>>(ctx_p, wr_vd, wr_ld, out, HID);
    }
}

// round 13
// speedup vs baseline: 1.9518x; 1.0002x over previous
#include <cuda_runtime.h>
#include <cuda_fp16.h>
#include <math.h>
#include <stdint.h>

// Problem constants
#define BATCH 2
#define SEQ   2048
#define NH    32
#define HD    128
#define HID   4096           // NH*HD
#define QKVN  12288          // 3*HID
#define MTOK  (BATCH*SEQ)    // 4096 tokens

// GEMM tile config (mma.sync m16n8k16 fp16; A ldmatrix, B ldmatrix.trans)
#define BM 128
#define BN 256
#define BK 64
#define STAGES 4
#define AROWB 144
#define BROWB 528
#define A_TILE_BYTES (128 * AROWB)               // 18432
#define B_TILE_BYTES (64 * BROWB)                // 33792
#define STAGE_BYTES (A_TILE_BYTES + B_TILE_BYTES)// 52224
#define GEMM_SMEM (STAGES * STAGE_BYTES)         // 208896

// Attention smem layout (fp16, double-buffered K/V)
#define QROWB 272
#define VROWB 144
#define AQS_OFF 0
#define KV_STAGE (64 * QROWB + 128 * VROWB)      // 35840
#define AKV0_OFF (128 * QROWB)
#define AKV1_OFF (AKV0_OFF + KV_STAGE)
#define APS_OFF (AKV1_OFF + KV_STAGE)
#define ATT_SMEM (APS_OFF + 128 * VROWB)         // 124928

// f2h merged-pass segment boundaries (in float4 units)
#define F4_WQKV  12582912                         // HID*QKVN/4
#define F4_WD    4194304                          // HID*HID/4
#define F4_S0    F4_WQKV
#define F4_S1    (2 * F4_WQKV)
#define F4_S2    (F4_S1 + F4_WD)
#define F4_S3    (F4_S2 + F4_WD)
#define F4_TOT   (F4_S3 + F4_WD)                  // 37748736
#define F4_HALF  (F4_TOT / 2)                     // 18874368

// ---------------- scratch (device globals) -------------
__device__ __half g_qkv[(size_t)MTOK * QKVN];
__device__ __half g_q[(size_t)MTOK * HID];
__device__ __half g_k[(size_t)MTOK * HID];
__device__ __half g_vt[(size_t)BATCH * NH * HD * SEQ];
__device__ __half g_ctx[(size_t)MTOK * HID];
__device__ __half g_hidh[(size_t)MTOK * HID];
#define WR_VQ 0
#define WR_LQ ((size_t)HID * QKVN)
#define WR_VD (2 * (size_t)HID * QKVN)
#define WR_LD (2 * (size_t)HID * QKVN + (size_t)HID * HID)
__device__ __half g_wr[2 * (size_t)HID * QKVN + 2 * (size_t)HID * HID];
__device__ int    g_cnt[2];
__device__ int    g_idx[2][MTOK];
__device__ int    g_idxc[MTOK + 256];
__device__ int    g_seg[4];                      // {pad0, pad0+pad1, c0, c1}

// ---------------- helpers ----------------
__device__ __forceinline__ uint32_t smem_u32(const void* p) {
    uint32_t a;
    asm("{ .reg .u64 t; cvta.to.shared.u64 t, %1; cvt.u32.u64 %0, t; }" : "=r"(a) : "l"(p));
    return a;
}
__device__ __forceinline__ void cp16(uint32_t dst, const void* src) {
    asm volatile("cp.async.cg.shared.global [%0], [%1], 16;" :: "r"(dst), "l"(src));
}
__device__ __forceinline__ void cp_commit() {
    asm volatile("cp.async.commit_group;" ::: "memory");
}
template <int N>
__device__ __forceinline__ void cp_wait() {
    asm volatile("cp.async.wait_group %0;" :: "n"(N) : "memory");
}
__device__ __forceinline__ void mma_f16(float* c, uint32_t a0, uint32_t a1, uint32_t a2, uint32_t a3,
                                        uint32_t b0, uint32_t b1) {
    asm volatile(
        "mma.sync.aligned.m16n8k16.row.col.f32.f16.f16.f32 "
        "{%0,%1,%2,%3}, {%4,%5,%6,%7}, {%8,%9}, {%0,%1,%2,%3};"
        : "+f"(c[0]), "+f"(c[1]), "+f"(c[2]), "+f"(c[3])
        : "r"(a0), "r"(a1), "r"(a2), "r"(a3), "r"(b0), "r"(b1));
}
#define LDSM4(r0, r1, r2, r3, addr)                                               \
    asm volatile("ldmatrix.sync.aligned.m8n8.x4.shared.b16 {%0,%1,%2,%3}, [%4];"   \
        : "=r"(r0), "=r"(r1), "=r"(r2), "=r"(r3) : "r"(addr))
#define LDSM4T(r0, r1, r2, r3, addr)                                              \
    asm volatile("ldmatrix.sync.aligned.m8n8.x4.trans.shared.b16 {%0,%1,%2,%3}, [%4];" \
        : "=r"(r0), "=r"(r1), "=r"(r2), "=r"(r3) : "r"(addr))

__device__ __forceinline__ void store2(float* p, float a, float b) {
    *(float2*)p = make_float2(a, b);
}
__device__ __forceinline__ void store2(__half* p, float a, float b) {
    *(__half2*)p = __floats2half2_rn(a, b);
}

// ---------------- merged pre-pass: ALL fp32->fp16 converts in one kernel ----------------
// Segment map (float4 idx): [0,S0) wvq  [S0,S1) wlq  [S1,S2) wvd  [S2,S3) wld  [S3,TOT) hidden
// First 4 destinations are contiguous in g_wr; hidden goes to g_hidh.
__global__ __launch_bounds__(256)
void f2h_all(const float4* __restrict__ wvq, const float4* __restrict__ wlq,
             const float4* __restrict__ wvd, const float4* __restrict__ wld,
             const float4* __restrict__ hid) {
    int t = blockIdx.x * blockDim.x + threadIdx.x;
    if (t >= F4_HALF) return;
#pragma unroll
    for (int s = 0; s < 2; s++) {
        int i = t + s * F4_HALF;
        const float4* src;
        __half2* dst;
        if (i < F4_S1) {
            src = (i < F4_S0) ? (wvq + i) : (wlq + (i - F4_S0));
            dst = (__half2*)g_wr + 2 * (size_t)i;
        } else if (i < F4_S3) {
            src = (i < F4_S2) ? (wvd + (i - F4_S1)) : (wld + (i - F4_S2));
            dst = (__half2*)g_wr + 2 * (size_t)i;
        } else {
            src = hid + (i - F4_S3);
            dst = (__half2*)g_hidh + 2 * (size_t)(i - F4_S3);
        }
        float4 v = *src;
        dst[0] = __floats2half2_rn(v.x, v.y);
        dst[1] = __floats2half2_rn(v.z, v.w);
    }
}

// V transpose: g_vt[bh][d][s]
__global__ __launch_bounds__(256)
void vtrans_kernel(const __half* __restrict__ qkv, __half* __restrict__ Vt) {
    __shared__ float t[32][33];
    int bh = blockIdx.z;
    int b = bh >> 5, h = bh & 31;
    int s0 = blockIdx.x * 32;
    int d0 = blockIdx.y * 32;
    int x = threadIdx.x & 31;
    int y = threadIdx.x >> 5;
#pragma unroll
    for (int i = 0; i < 32; i += 8)
        t[y + i][x] = __half2float(qkv[(size_t)(b * SEQ + s0 + y + i) * QKVN + 2 * HID + h * HD + d0 + x]);
    __syncthreads();
#pragma unroll
    for (int i = 0; i < 32; i += 8)
        Vt[((size_t)bh * HD + d0 + y + i) * SEQ + s0 + x] = __float2half(t[x][y + i]);
}

// ---------------- mask / routing / packing ----------------
__global__ void zero_cnt_kernel() {
    if (threadIdx.x < 2) g_cnt[threadIdx.x] = 0;
}
__global__ void route_kernel(const int* __restrict__ tt) {
    int idx = blockIdx.x * blockDim.x + threadIdx.x;
    if (idx >= MTOK) return;
    int s = idx & (SEQ - 1);
    int vis = (s + 1 < SEQ) && (tt[idx] == 1) && (tt[idx + 1] == 1);
    int e = vis ? 0 : 1;
    int pos = atomicAdd(&g_cnt[e], 1);
    g_idx[e][pos] = idx;
}
__global__ void pack_kernel() {
    int c0 = g_cnt[0], c1 = g_cnt[1];
    int pad0 = (c0 + 127) & ~127;
    int pad1 = (c1 + 127) & ~127;
    if (threadIdx.x == 0) {
        g_seg[0] = pad0;
        g_seg[1] = pad0 + pad1;
        g_seg[2] = c0;
        g_seg[3] = c1;
    }
    for (int i = threadIdx.x; i < pad0; i += blockDim.x)
        g_idxc[i] = g_idx[0][i < c0 ? i : c0 - 1];
    for (int j = threadIdx.x; j < pad1; j += blockDim.x)
        g_idxc[pad0 + j] = g_idx[1][j < c1 ? j : c1 - 1];
}

// ---------------- merged-expert fp16 GEMM (single sync/iter) ----------------
template <typename CT>
__global__ __launch_bounds__(256, 1)
void gemm_tc(const __half* __restrict__ A,
             const __half* __restrict__ Wvis, const __half* __restrict__ Wlang,
             CT* __restrict__ C, int N) {
    __shared__ int idx_s[BM];
    extern __shared__ char smem[];
    const uint32_t sb = smem_u32(smem);
    const int tid = threadIdx.x;
    const int wid = tid >> 5;
    const int lane = tid & 31;
    const int lm = lane >> 2;
    const int lq = lane & 3;
    const int warp_m = wid & 1;
    const int warp_n = wid >> 1;
    const int m0 = blockIdx.x * BM;
    const int n0 = blockIdx.y * BN;

    const int s0 = __ldg(&g_seg[0]);
    const int s1 = __ldg(&g_seg[1]);
    if (m0 >= s1) return;
    const bool is_vis = (m0 < s0);
    const __half* W = is_vis ? Wvis : Wlang;
    const int limit = is_vis ? __ldg(&g_seg[2]) : (s0 + __ldg(&g_seg[3]));

    if (tid < BM) idx_s[tid] = g_idxc[m0 + tid];
    __syncthreads();

    int a_r[4], a_c[4];
#pragma unroll
    for (int i = 0; i < 4; i++) {
        int t = tid + i * 256;
        a_r[i] = t >> 3;
        a_c[i] = t & 7;
    }
    int a_g[4];
#pragma unroll
    for (int i = 0; i < 4; i++) a_g[i] = idx_s[a_r[i]];
    int b_r[8], b_c[8];
#pragma unroll
    for (int i = 0; i < 8; i++) {
        int t = tid + i * 256;
        b_r[i] = t >> 5;
        b_c[i] = t & 31;
    }

    auto load_stage = [&](int stage, int chunk) {
        uint32_t as = sb + stage * STAGE_BYTES;
        uint32_t bs = as + A_TILE_BYTES;
#pragma unroll
        for (int i = 0; i < 4; i++)
            cp16(as + a_r[i] * AROWB + a_c[i] * 16,
                 A + (size_t)a_g[i] * HID + chunk * BK + a_c[i] * 8);
#pragma unroll
        for (int i = 0; i < 8; i++)
            cp16(bs + b_r[i] * BROWB + b_c[i] * 16,
                 W + (size_t)(chunk * BK + b_r[i]) * N + n0 + b_c[i] * 8);
    };

    const uint32_t a_off = (warp_m * 64 + (lane & 15)) * AROWB + (lane >> 4) * 16;
    const uint32_t b_off = (lane & 15) * BROWB + (lane >> 4) * 16 + warp_n * 128;

    float c[4][8][4];
#pragma unroll
    for (int mt = 0; mt < 4; mt++)
#pragma unroll
        for (int nt = 0; nt < 8; nt++)
#pragma unroll
            for (int j = 0; j < 4; j++) c[mt][nt][j] = 0.f;

    const int NC = HID / BK;  // 64

    load_stage(0, 0); cp_commit();
    load_stage(1, 1); cp_commit();
    load_stage(2, 2); cp_commit();

    for (int ch = 0; ch < NC; ch++) {
        cp_wait<2>();
        __syncthreads();
        // Single barrier per iteration: loads below write stage (ch+3)%4,
        // whose last readers (chunk ch-1) are all past the barrier above.
        if (ch + 3 < NC) load_stage((ch + 3) % STAGES, ch + 3);
        cp_commit();

        const uint32_t as = sb + (ch % STAGES) * STAGE_BYTES;
        const uint32_t bs = as + A_TILE_BYTES;
        const uint32_t aL = as + a_off;
        const uint32_t bL = bs + b_off;

#pragma unroll
        for (int ks = 0; ks < 4; ks++) {
            uint32_t af[4][4], bf[8][2];
#pragma unroll
            for (int mt = 0; mt < 4; mt++)
                LDSM4(af[mt][0], af[mt][1], af[mt][2], af[mt][3],
                      aL + mt * 16 * AROWB + ks * 32);
#pragma unroll
            for (int pr = 0; pr < 4; pr++)
                LDSM4T(bf[2 * pr][0], bf[2 * pr][1], bf[2 * pr + 1][0], bf[2 * pr + 1][1],
                       bL + ks * 16 * BROWB + pr * 32);
#pragma unroll
            for (int mt = 0; mt < 4; mt++)
#pragma unroll
                for (int nt = 0; nt < 8; nt++)
                    mma_f16(c[mt][nt], af[mt][0], af[mt][1], af[mt][2], af[mt][3],
                            bf[nt][0], bf[nt][1]);
        }
    }

    // epilogue: scatter to true rows; suppress padding rows
#pragma unroll
    for (int mt = 0; mt < 4; mt++) {
        int r0 = warp_m * 64 + mt * 16 + lm;
        int r1 = r0 + 8;
        bool on0 = (m0 + r0 < limit);
        bool on1 = (m0 + r1 < limit);
        CT* p0 = C + (size_t)idx_s[r0] * N + n0 + warp_n * 64;
        CT* p1 = C + (size_t)idx_s[r1] * N + n0 + warp_n * 64;
#pragma unroll
        for (int nt = 0; nt < 8; nt++) {
            int col = nt * 8 + 2 * lq;
            if (on0) store2(p0 + col, c[mt][nt][0], c[mt][nt][1]);
            if (on1) store2(p1 + col, c[mt][nt][2], c[mt][nt][3]);
        }
    }
}

// ---------------- RoPE ----------------
__global__ void rope_kernel(const __half* __restrict__ qkv, const int* __restrict__ pos_ids,
                            __half* __restrict__ q, __half* __restrict__ k) {
    int idx = blockIdx.x * blockDim.x + threadIdx.x;
    if (idx >= MTOK * NH * 64) return;
    int i = idx & 63;
    int h = (idx >> 6) & 31;
    int m = idx >> 11;

    float pos = (float)pos_ids[m];
    float freq = expf(-(float)i * (9.210340371976184f / 64.f));
    float ang = pos * freq;
    float cv = cosf(ang);
    float sv = sinf(ang);
    const float scale = 0.088388347648318447f;

    const __half* qs = qkv + (size_t)m * QKVN + h * HD;
    const __half* ks = qs + HID;
    float q0 = __half2float(qs[i]), q1 = __half2float(qs[i + 64]);
    float k0 = __half2float(ks[i]), k1 = __half2float(ks[i + 64]);

    size_t o = (size_t)m * HID + h * HD;
    q[o + i]      = __float2half((q0 * cv - q1 * sv) * scale);
    q[o + i + 64] = __float2half((q1 * cv + q0 * sv) * scale);
    k[o + i]      = __float2half(k0 * cv - k1 * sv);
    k[o + i + 64] = __float2half(k1 * cv + k0 * sv);
}

// ---------------- fp16 flash attention, double-buffered K/V ----------------
__global__ __launch_bounds__(256)
void attn_mma(const __half* __restrict__ Q, const __half* __restrict__ Kg,
              const __half* __restrict__ Vt, __half* __restrict__ ctx) {
    extern __shared__ char smem[];
    const uint32_t sb = smem_u32(smem);
    const int tid = threadIdx.x;
    const int warp = tid >> 5;
    const int lane = tid & 31;
    const int lm = lane >> 2;
    const int lq = lane & 3;
    const int b = blockIdx.z;
    const int h = blockIdx.y;
    const int qi = (int)gridDim.x - 1 - (int)blockIdx.x;
    const int qb = qi * 128;

    const uint32_t kvb[2] = {sb + AKV0_OFF, sb + AKV1_OFF};

    auto load_tile = [&](int t, int buf) {
        uint32_t kb = kvb[buf];
        uint32_t vb = kvb[buf] + 64 * QROWB;
#pragma unroll
        for (int i = 0; i < 4; i++) {
            int g = tid + i * 256;
            int r = g >> 4, c = g & 15;
            cp16(kb + r * QROWB + c * 16,
                 Kg + (size_t)(b * SEQ + t * 64 + r) * HID + h * HD + c * 8);
        }
#pragma unroll
        for (int i = 0; i < 4; i++) {
            int g = tid + i * 256;
            int r = g >> 3, c = g & 7;
            cp16(vb + r * VROWB + c * 16,
                 Vt + ((size_t)(b * NH + h) * HD + r) * SEQ + t * 64 + c * 8);
        }
    };

#pragma unroll
    for (int i = 0; i < 8; i++) {
        int g = tid + i * 256;
        int r = g >> 4, c = g & 15;
        cp16(sb + AQS_OFF + r * QROWB + c * 16,
             Q + (size_t)(b * SEQ + qb + r) * HID + h * HD + c * 8);
    }
    load_tile(0, 0);
    cp_commit();

    const int a_row = lane & 15;
    const int a_hi  = (lane >> 4) * 16;
    const int b_row = (lane & 7) | ((lane >> 1) & 8);
    const int b_hi  = ((lane >> 3) & 1) * 16;
    const uint32_t qA = sb + AQS_OFF + (warp * 16 + a_row) * QROWB + a_hi;
    const uint32_t pA = sb + APS_OFF + (warp * 16 + a_row) * VROWB + a_hi;
    const uint32_t kOff = b_row * QROWB + b_hi;
    const uint32_t vOff = 64 * QROWB + b_row * VROWB + b_hi;

    float o[16][4];
#pragma unroll
    for (int nt = 0; nt < 16; nt++)
#pragma unroll
        for (int j = 0; j < 4; j++) o[nt][j] = 0.f;
    float mr0 = -1e30f, mr1 = -1e30f, l0 = 0.f, l1 = 0.f;
    const int r0g = qb + warp * 16 + lm;
    const int r1g = r0g + 8;

    const int ntiles = 2 * qi + 2;
    for (int t = 0; t < ntiles; t++) {
        const int buf = t & 1;
        if (t + 1 < ntiles) {
            load_tile(t + 1, buf ^ 1);
            cp_commit();
            cp_wait<1>();
        } else {
            cp_wait<0>();
        }
        __syncthreads();

        const uint32_t kB = kvb[buf] + kOff;
        const uint32_t vB = kvb[buf] + vOff;

        float s_[8][4];
#pragma unroll
        for (int nt = 0; nt < 8; nt++)
#pragma unroll
            for (int j = 0; j < 4; j++) s_[nt][j] = 0.f;

#pragma unroll
        for (int ks = 0; ks < 8; ks++) {
            uint32_t a0, a1, a2, a3;
            LDSM4(a0, a1, a2, a3, qA + ks * 32);
#pragma unroll
            for (int pr = 0; pr < 4; pr++) {
                uint32_t b0, b1, b2, b3;
                LDSM4(b0, b1, b2, b3, kB + pr * 16 * QROWB + ks * 32);
                mma_f16(s_[2 * pr],     a0, a1, a2, a3, b0, b1);
                mma_f16(s_[2 * pr + 1], a0, a1, a2, a3, b2, b3);
            }
        }

        if (t >= 2 * qi) {
#pragma unroll
            for (int nt = 0; nt < 8; nt++) {
                int cb = t * 64 + nt * 8 + 2 * lq;
                if (cb > r0g)     s_[nt][0] = -1e30f;
                if (cb + 1 > r0g) s_[nt][1] = -1e30f;
                if (cb > r1g)     s_[nt][2] = -1e30f;
                if (cb + 1 > r1g) s_[nt][3] = -1e30f;
            }
        }

        float tm0 = -1e30f, tm1 = -1e30f;
#pragma unroll
        for (int nt = 0; nt < 8; nt++) {
            tm0 = fmaxf(tm0, fmaxf(s_[nt][0], s_[nt][1]));
            tm1 = fmaxf(tm1, fmaxf(s_[nt][2], s_[nt][3]));
        }
        tm0 = fmaxf(tm0, __shfl_xor_sync(0xffffffffu, tm0, 1));
        tm0 = fmaxf(tm0, __shfl_xor_sync(0xffffffffu, tm0, 2));
        tm1 = fmaxf(tm1, __shfl_xor_sync(0xffffffffu, tm1, 1));
        tm1 = fmaxf(tm1, __shfl_xor_sync(0xffffffffu, tm1, 2));
        float mn0 = fmaxf(mr0, tm0), mn1 = fmaxf(mr1, tm1);
        float c0 = __expf(mr0 - mn0), c1 = __expf(mr1 - mn1);
        float ps0 = 0.f, ps1 = 0.f;
#pragma unroll
        for (int nt = 0; nt < 8; nt++) {
            s_[nt][0] = __expf(s_[nt][0] - mn0);
            s_[nt][1] = __expf(s_[nt][1] - mn0);
            s_[nt][2] = __expf(s_[nt][2] - mn1);
            s_[nt][3] = __expf(s_[nt][3] - mn1);
            ps0 += s_[nt][0] + s_[nt][1];
            ps1 += s_[nt][2] + s_[nt][3];
        }
        l0 = l0 * c0 + ps0;
        l1 = l1 * c1 + ps1;
#pragma unroll
        for (int nt = 0; nt < 16; nt++) {
            o[nt][0] *= c0; o[nt][1] *= c0;
            o[nt][2] *= c1; o[nt][3] *= c1;
        }
        mr0 = mn0; mr1 = mn1;

#pragma unroll
        for (int nt = 0; nt < 8; nt++) {
            *(__half2*)(smem + APS_OFF + (warp * 16 + lm) * VROWB + (nt * 8 + 2 * lq) * 2)
                = __floats2half2_rn(s_[nt][0], s_[nt][1]);
            *(__half2*)(smem + APS_OFF + (warp * 16 + lm + 8) * VROWB + (nt * 8 + 2 * lq) * 2)
                = __floats2half2_rn(s_[nt][2], s_[nt][3]);
        }
        __syncwarp();

#pragma unroll
        for (int ks = 0; ks < 4; ks++) {
            uint32_t a0, a1, a2, a3;
            LDSM4(a0, a1, a2, a3, pA + ks * 32);
#pragma unroll
            for (int pr = 0; pr < 8; pr++) {
                uint32_t b0, b1, b2, b3;
                LDSM4(b0, b1, b2, b3, vB + pr * 16 * VROWB + ks * 32);
                mma_f16(o[2 * pr],     a0, a1, a2, a3, b0, b1);
                mma_f16(o[2 * pr + 1], a0, a1, a2, a3, b2, b3);
            }
        }
        __syncthreads();
    }

    l0 += __shfl_xor_sync(0xffffffffu, l0, 1);
    l0 += __shfl_xor_sync(0xffffffffu, l0, 2);
    l1 += __shfl_xor_sync(0xffffffffu, l1, 1);
    l1 += __shfl_xor_sync(0xffffffffu, l1, 2);
    float i0 = 1.f / l0, i1 = 1.f / l1;

#pragma unroll
    for (int nt = 0; nt < 16; nt++) {
        int col = nt * 8 + 2 * lq;
        *(__half2*)&ctx[(size_t)(b * SEQ + r0g) * HID + h * HD + col] =
            __floats2half2_rn(o[nt][0] * i0, o[nt][1] * i0);
        *(__half2*)&ctx[(size_t)(b * SEQ + r1g) * HID + h * HD + col] =
            __floats2half2_rn(o[nt][2] * i1, o[nt][3] * i1);
    }
}

// ---------------- launch ----------------
extern "C" void kernel_launch(void* const* d_in, const int* in_sizes, int n_in,
                              void* d_out, int out_size) {
    const float* hidden = (const float*)d_in[0];
    const int*   tt     = (const int*)d_in[1];
    const int*   pos    = (const int*)d_in[2];
    const float* wvq    = (const float*)d_in[3];
    const float* wlq    = (const float*)d_in[4];
    const float* wvd    = (const float*)d_in[5];
    const float* wld    = (const float*)d_in[6];
    float* out = (float*)d_out;

    __half *qkv_p, *q_p, *k_p, *vt_p, *ctx_p, *hidh_p, *wr_p;
    cudaGetSymbolAddress((void**)&qkv_p, g_qkv);
    cudaGetSymbolAddress((void**)&q_p, g_q);
    cudaGetSymbolAddress((void**)&k_p, g_k);
    cudaGetSymbolAddress((void**)&vt_p, g_vt);
    cudaGetSymbolAddress((void**)&ctx_p, g_ctx);
    cudaGetSymbolAddress((void**)&hidh_p, g_hidh);
    cudaGetSymbolAddress((void**)&wr_p, g_wr);

    __half* wr_vq = wr_p + WR_VQ;
    __half* wr_lq = wr_p + WR_LQ;
    __half* wr_vd = wr_p + WR_VD;
    __half* wr_ld = wr_p + WR_LD;

    cudaFuncSetAttribute((const void*)&gemm_tc<__half>, cudaFuncAttributeMaxDynamicSharedMemorySize, GEMM_SMEM);
    cudaFuncSetAttribute((const void*)&gemm_tc<float>, cudaFuncAttributeMaxDynamicSharedMemorySize, GEMM_SMEM);
    cudaFuncSetAttribute(attn_mma, cudaFuncAttributeMaxDynamicSharedMemorySize, ATT_SMEM);

    zero_cnt_kernel<<<1, 32>>>();
    route_kernel<<<MTOK / 256, 256>>>(tt);
    pack_kernel<<<1, 256>>>();

    // merged fp32->fp16 pre-pass (weights + hidden) in one launch
    f2h_all<<<(F4_HALF + 255) / 256, 256>>>((const float4*)wvq, (const float4*)wlq,
                                            (const float4*)wvd, (const float4*)wld,
                                            (const float4*)hidden);

    // QKV projection: merged experts
    {
        dim3 grid(MTOK / BM + 2, QKVN / BN);
        gemm_tc<__half><<<grid, 256, GEMM_SMEM>>>(hidh_p, wr_vq, wr_lq, qkv_p, QKVN);
    }

    // RoPE + V transpose
    rope_kernel<<<(MTOK * NH * 64) / 256, 256>>>(qkv_p, pos, q_p, k_p);
    {
        dim3 gv(SEQ / 32, HD / 32, BATCH * NH);
        vtrans_kernel<<<gv, 256>>>(qkv_p, vt_p);
    }

    // fp16 flash attention
    {
        dim3 grid(SEQ / 128, NH, BATCH);
        attn_mma<<<grid, 256, ATT_SMEM>>>(q_p, k_p, vt_p, ctx_p);
    }

    // Dense projection: merged experts
    {
        dim3 grid(MTOK / BM + 2, HID / BN);
        gemm_tc<float><<<grid, 256, GEMM_SMEM>>>(ctx_p, wr_vd, wr_ld, out, HID);
    }
}

// round 14
// speedup vs baseline: 1.9681x; 1.0083x over previous
#include <cuda_runtime.h>
#include <cuda_fp16.h>
#include <math.h>
#include <stdint.h>

// Problem constants
#define BATCH 2
#define SEQ   2048
#define NH    32
#define HD    128
#define HID   4096           // NH*HD
#define QKVN  12288          // 3*HID
#define MTOK  (BATCH*SEQ)    // 4096 tokens

// GEMM tile config (mma.sync m16n8k16 fp16; A ldmatrix, B ldmatrix.trans)
#define BM 128
#define BN 256
#define BK 64
#define STAGES 4
#define AROWB 144
#define BROWB 528
#define A_TILE_BYTES (128 * AROWB)               // 18432
#define B_TILE_BYTES (64 * BROWB)                // 33792
#define STAGE_BYTES (A_TILE_BYTES + B_TILE_BYTES)// 52224
#define GEMM_SMEM (STAGES * STAGE_BYTES)         // 208896

// Attention smem layout (fp16, K-tile 128, double-buffered K/V)
#define QROWB 272                                // 128 fp16 + pad
#define AQS_OFF 0
#define KV_STAGE (256 * QROWB)                   // 69632 (K 128 rows + V 128 rows)
#define AKV0_OFF (128 * QROWB)                   // 34816
#define AKV1_OFF (AKV0_OFF + KV_STAGE)           // 104448
#define APS_OFF (AKV1_OFF + KV_STAGE)            // 174080
#define ATT_SMEM (APS_OFF + 128 * QROWB)         // 208896

// f2h merged-pass segment boundaries (in float4 units)
#define F4_WQKV  12582912                         // HID*QKVN/4
#define F4_WD    4194304                          // HID*HID/4
#define F4_S0    F4_WQKV
#define F4_S1    (2 * F4_WQKV)
#define F4_S2    (F4_S1 + F4_WD)
#define F4_S3    (F4_S2 + F4_WD)
#define F4_TOT   (F4_S3 + F4_WD)
#define F4_HALF  (F4_TOT / 2)

// ---------------- scratch (device globals) -------------
__device__ __half g_qkv[(size_t)MTOK * QKVN];
__device__ __half g_q[(size_t)MTOK * HID];
__device__ __half g_k[(size_t)MTOK * HID];
__device__ __half g_vt[(size_t)BATCH * NH * HD * SEQ];
__device__ __half g_ctx[(size_t)MTOK * HID];
__device__ __half g_hidh[(size_t)MTOK * HID];
#define WR_VQ 0
#define WR_LQ ((size_t)HID * QKVN)
#define WR_VD (2 * (size_t)HID * QKVN)
#define WR_LD (2 * (size_t)HID * QKVN + (size_t)HID * HID)
__device__ __half g_wr[2 * (size_t)HID * QKVN + 2 * (size_t)HID * HID];
__device__ int    g_cnt[2];
__device__ int    g_idx[2][MTOK];
__device__ int    g_idxc[MTOK + 256];
__device__ int    g_seg[4];

// ---------------- helpers ----------------
__device__ __forceinline__ uint32_t smem_u32(const void* p) {
    uint32_t a;
    asm("{ .reg .u64 t; cvta.to.shared.u64 t, %1; cvt.u32.u64 %0, t; }" : "=r"(a) : "l"(p));
    return a;
}
__device__ __forceinline__ void cp16(uint32_t dst, const void* src) {
    asm volatile("cp.async.cg.shared.global [%0], [%1], 16;" :: "r"(dst), "l"(src));
}
__device__ __forceinline__ void cp_commit() {
    asm volatile("cp.async.commit_group;" ::: "memory");
}
template <int N>
__device__ __forceinline__ void cp_wait() {
    asm volatile("cp.async.wait_group %0;" :: "n"(N) : "memory");
}
__device__ __forceinline__ void mma_f16(float* c, uint32_t a0, uint32_t a1, uint32_t a2, uint32_t a3,
                                        uint32_t b0, uint32_t b1) {
    asm volatile(
        "mma.sync.aligned.m16n8k16.row.col.f32.f16.f16.f32 "
        "{%0,%1,%2,%3}, {%4,%5,%6,%7}, {%8,%9}, {%0,%1,%2,%3};"
        : "+f"(c[0]), "+f"(c[1]), "+f"(c[2]), "+f"(c[3])
        : "r"(a0), "r"(a1), "r"(a2), "r"(a3), "r"(b0), "r"(b1));
}
#define LDSM4(r0, r1, r2, r3, addr)                                               \
    asm volatile("ldmatrix.sync.aligned.m8n8.x4.shared.b16 {%0,%1,%2,%3}, [%4];"   \
        : "=r"(r0), "=r"(r1), "=r"(r2), "=r"(r3) : "r"(addr))
#define LDSM4T(r0, r1, r2, r3, addr)                                              \
    asm volatile("ldmatrix.sync.aligned.m8n8.x4.trans.shared.b16 {%0,%1,%2,%3}, [%4];" \
        : "=r"(r0), "=r"(r1), "=r"(r2), "=r"(r3) : "r"(addr))

__device__ __forceinline__ void store2(float* p, float a, float b) {
    *(float2*)p = make_float2(a, b);
}
__device__ __forceinline__ void store2(__half* p, float a, float b) {
    *(__half2*)p = __floats2half2_rn(a, b);
}

// ---------------- merged pre-pass ----------------
__global__ __launch_bounds__(256)
void f2h_all(const float4* __restrict__ wvq, const float4* __restrict__ wlq,
             const float4* __restrict__ wvd, const float4* __restrict__ wld,
             const float4* __restrict__ hid) {
    int t = blockIdx.x * blockDim.x + threadIdx.x;
    if (t >= F4_HALF) return;
#pragma unroll
    for (int s = 0; s < 2; s++) {
        int i = t + s * F4_HALF;
        const float4* src;
        __half2* dst;
        if (i < F4_S1) {
            src = (i < F4_S0) ? (wvq + i) : (wlq + (i - F4_S0));
            dst = (__half2*)g_wr + 2 * (size_t)i;
        } else if (i < F4_S3) {
            src = (i < F4_S2) ? (wvd + (i - F4_S1)) : (wld + (i - F4_S2));
            dst = (__half2*)g_wr + 2 * (size_t)i;
        } else {
            src = hid + (i - F4_S3);
            dst = (__half2*)g_hidh + 2 * (size_t)(i - F4_S3);
        }
        float4 v = *src;
        dst[0] = __floats2half2_rn(v.x, v.y);
        dst[1] = __floats2half2_rn(v.z, v.w);
    }
}

// V transpose: g_vt[bh][d][s]
__global__ __launch_bounds__(256)
void vtrans_kernel(const __half* __restrict__ qkv, __half* __restrict__ Vt) {
    __shared__ float t[32][33];
    int bh = blockIdx.z;
    int b = bh >> 5, h = bh & 31;
    int s0 = blockIdx.x * 32;
    int d0 = blockIdx.y * 32;
    int x = threadIdx.x & 31;
    int y = threadIdx.x >> 5;
#pragma unroll
    for (int i = 0; i < 32; i += 8)
        t[y + i][x] = __half2float(qkv[(size_t)(b * SEQ + s0 + y + i) * QKVN + 2 * HID + h * HD + d0 + x]);
    __syncthreads();
#pragma unroll
    for (int i = 0; i < 32; i += 8)
        Vt[((size_t)bh * HD + d0 + y + i) * SEQ + s0 + x] = __float2half(t[x][y + i]);
}

// ---------------- mask / routing / packing ----------------
__global__ void zero_cnt_kernel() {
    if (threadIdx.x < 2) g_cnt[threadIdx.x] = 0;
}
__global__ void route_kernel(const int* __restrict__ tt) {
    int idx = blockIdx.x * blockDim.x + threadIdx.x;
    if (idx >= MTOK) return;
    int s = idx & (SEQ - 1);
    int vis = (s + 1 < SEQ) && (tt[idx] == 1) && (tt[idx + 1] == 1);
    int e = vis ? 0 : 1;
    int pos = atomicAdd(&g_cnt[e], 1);
    g_idx[e][pos] = idx;
}
__global__ void pack_kernel() {
    int c0 = g_cnt[0], c1 = g_cnt[1];
    int pad0 = (c0 + 127) & ~127;
    int pad1 = (c1 + 127) & ~127;
    if (threadIdx.x == 0) {
        g_seg[0] = pad0;
        g_seg[1] = pad0 + pad1;
        g_seg[2] = c0;
        g_seg[3] = c1;
    }
    for (int i = threadIdx.x; i < pad0; i += blockDim.x)
        g_idxc[i] = g_idx[0][i < c0 ? i : c0 - 1];
    for (int j = threadIdx.x; j < pad1; j += blockDim.x)
        g_idxc[pad0 + j] = g_idx[1][j < c1 ? j : c1 - 1];
}

// ---------------- merged-expert fp16 GEMM (fragment double-buffered) ----------------
template <typename CT>
__global__ __launch_bounds__(256, 1)
void gemm_tc(const __half* __restrict__ A,
             const __half* __restrict__ Wvis, const __half* __restrict__ Wlang,
             CT* __restrict__ C, int N) {
    __shared__ int idx_s[BM];
    extern __shared__ char smem[];
    const uint32_t sb = smem_u32(smem);
    const int tid = threadIdx.x;
    const int wid = tid >> 5;
    const int lane = tid & 31;
    const int lm = lane >> 2;
    const int lq = lane & 3;
    const int warp_m = wid & 1;
    const int warp_n = wid >> 1;
    const int m0 = blockIdx.x * BM;
    const int n0 = blockIdx.y * BN;

    const int s0 = __ldg(&g_seg[0]);
    const int s1 = __ldg(&g_seg[1]);
    if (m0 >= s1) return;
    const bool is_vis = (m0 < s0);
    const __half* W = is_vis ? Wvis : Wlang;
    const int limit = is_vis ? __ldg(&g_seg[2]) : (s0 + __ldg(&g_seg[3]));

    if (tid < BM) idx_s[tid] = g_idxc[m0 + tid];
    __syncthreads();

    int a_r[4], a_c[4];
#pragma unroll
    for (int i = 0; i < 4; i++) {
        int t = tid + i * 256;
        a_r[i] = t >> 3;
        a_c[i] = t & 7;
    }
    int a_g[4];
#pragma unroll
    for (int i = 0; i < 4; i++) a_g[i] = idx_s[a_r[i]];
    int b_r[8], b_c[8];
#pragma unroll
    for (int i = 0; i < 8; i++) {
        int t = tid + i * 256;
        b_r[i] = t >> 5;
        b_c[i] = t & 31;
    }

    auto load_stage = [&](int stage, int chunk) {
        uint32_t as = sb + stage * STAGE_BYTES;
        uint32_t bs = as + A_TILE_BYTES;
#pragma unroll
        for (int i = 0; i < 4; i++)
            cp16(as + a_r[i] * AROWB + a_c[i] * 16,
                 A + (size_t)a_g[i] * HID + chunk * BK + a_c[i] * 8);
#pragma unroll
        for (int i = 0; i < 8; i++)
            cp16(bs + b_r[i] * BROWB + b_c[i] * 16,
                 W + (size_t)(chunk * BK + b_r[i]) * N + n0 + b_c[i] * 8);
    };

    const uint32_t a_off = (warp_m * 64 + (lane & 15)) * AROWB + (lane >> 4) * 16;
    const uint32_t b_off = (lane & 15) * BROWB + (lane >> 4) * 16 + warp_n * 128;

    float c[4][8][4];
#pragma unroll
    for (int mt = 0; mt < 4; mt++)
#pragma unroll
        for (int nt = 0; nt < 8; nt++)
#pragma unroll
            for (int j = 0; j < 4; j++) c[mt][nt][j] = 0.f;

    const int NC = HID / BK;  // 64

    load_stage(0, 0); cp_commit();
    load_stage(1, 1); cp_commit();
    load_stage(2, 2); cp_commit();

    uint32_t af[2][4][4], bf[2][8][2];

    for (int ch = 0; ch < NC; ch++) {
        cp_wait<2>();
        __syncthreads();
        if (ch + 3 < NC) load_stage((ch + 3) % STAGES, ch + 3);
        cp_commit();

        const uint32_t as = sb + (ch % STAGES) * STAGE_BYTES;
        const uint32_t aL = as + a_off;
        const uint32_t bL = as + A_TILE_BYTES + b_off;

        // prologue: load ks=0 fragments
#pragma unroll
        for (int mt = 0; mt < 4; mt++)
            LDSM4(af[0][mt][0], af[0][mt][1], af[0][mt][2], af[0][mt][3],
                  aL + mt * 16 * AROWB);
#pragma unroll
        for (int pr = 0; pr < 4; pr++)
            LDSM4T(bf[0][2 * pr][0], bf[0][2 * pr][1], bf[0][2 * pr + 1][0], bf[0][2 * pr + 1][1],
                   bL + pr * 32);

#pragma unroll
        for (int ks = 0; ks < 4; ks++) {
            const int cur = ks & 1, nxt = cur ^ 1;
            if (ks < 3) {  // prefetch next k-step's fragments
#pragma unroll
                for (int mt = 0; mt < 4; mt++)
                    LDSM4(af[nxt][mt][0], af[nxt][mt][1], af[nxt][mt][2], af[nxt][mt][3],
                          aL + mt * 16 * AROWB + (ks + 1) * 32);
#pragma unroll
                for (int pr = 0; pr < 4; pr++)
                    LDSM4T(bf[nxt][2 * pr][0], bf[nxt][2 * pr][1],
                           bf[nxt][2 * pr + 1][0], bf[nxt][2 * pr + 1][1],
                           bL + (ks + 1) * 16 * BROWB + pr * 32);
            }
#pragma unroll
            for (int mt = 0; mt < 4; mt++)
#pragma unroll
                for (int nt = 0; nt < 8; nt++)
                    mma_f16(c[mt][nt], af[cur][mt][0], af[cur][mt][1], af[cur][mt][2], af[cur][mt][3],
                            bf[cur][nt][0], bf[cur][nt][1]);
        }
    }

    // epilogue
#pragma unroll
    for (int mt = 0; mt < 4; mt++) {
        int r0 = warp_m * 64 + mt * 16 + lm;
        int r1 = r0 + 8;
        bool on0 = (m0 + r0 < limit);
        bool on1 = (m0 + r1 < limit);
        CT* p0 = C + (size_t)idx_s[r0] * N + n0 + warp_n * 64;
        CT* p1 = C + (size_t)idx_s[r1] * N + n0 + warp_n * 64;
#pragma unroll
        for (int nt = 0; nt < 8; nt++) {
            int col = nt * 8 + 2 * lq;
            if (on0) store2(p0 + col, c[mt][nt][0], c[mt][nt][1]);
            if (on1) store2(p1 + col, c[mt][nt][2], c[mt][nt][3]);
        }
    }
}

// ---------------- RoPE ----------------
__global__ void rope_kernel(const __half* __restrict__ qkv, const int* __restrict__ pos_ids,
                            __half* __restrict__ q, __half* __restrict__ k) {
    int idx = blockIdx.x * blockDim.x + threadIdx.x;
    if (idx >= MTOK * NH * 64) return;
    int i = idx & 63;
    int h = (idx >> 6) & 31;
    int m = idx >> 11;

    float pos = (float)pos_ids[m];
    float freq = expf(-(float)i * (9.210340371976184f / 64.f));
    float ang = pos * freq;
    float cv = cosf(ang);
    float sv = sinf(ang);
    const float scale = 0.088388347648318447f;

    const __half* qs = qkv + (size_t)m * QKVN + h * HD;
    const __half* ks = qs + HID;
    float q0 = __half2float(qs[i]), q1 = __half2float(qs[i + 64]);
    float k0 = __half2float(ks[i]), k1 = __half2float(ks[i + 64]);

    size_t o = (size_t)m * HID + h * HD;
    q[o + i]      = __float2half((q0 * cv - q1 * sv) * scale);
    q[o + i + 64] = __float2half((q1 * cv + q0 * sv) * scale);
    k[o + i]      = __float2half(k0 * cv - k1 * sv);
    k[o + i + 64] = __float2half(k1 * cv + k0 * sv);
}

// ---------------- fp16 flash attention, K-tile 128, double-buffered K/V ----------------
__global__ __launch_bounds__(256)
void attn_mma(const __half* __restrict__ Q, const __half* __restrict__ Kg,
              const __half* __restrict__ Vt, __half* __restrict__ ctx) {
    extern __shared__ char smem[];
    const uint32_t sb = smem_u32(smem);
    const int tid = threadIdx.x;
    const int warp = tid >> 5;
    const int lane = tid & 31;
    const int lm = lane >> 2;
    const int lq = lane & 3;
    const int b = blockIdx.z;
    const int h = blockIdx.y;
    const int qi = (int)gridDim.x - 1 - (int)blockIdx.x;
    const int qb = qi * 128;

    const uint32_t kvb[2] = {sb + AKV0_OFF, sb + AKV1_OFF};

    // K tile: 128 token-rows x 128 d; V tile: 128 d-rows x 128 s. Both 2048 granules -> 8/thread.
    auto load_tile = [&](int t, int buf) {
        uint32_t kb = kvb[buf];
        uint32_t vb = kvb[buf] + 128 * QROWB;
#pragma unroll
        for (int i = 0; i < 8; i++) {
            int g = tid + i * 256;
            int r = g >> 4, c = g & 15;
            cp16(kb + r * QROWB + c * 16,
                 Kg + (size_t)(b * SEQ + t * 128 + r) * HID + h * HD + c * 8);
        }
#pragma unroll
        for (int i = 0; i < 8; i++) {
            int g = tid + i * 256;
            int r = g >> 4, c = g & 15;
            cp16(vb + r * QROWB + c * 16,
                 Vt + ((size_t)(b * NH + h) * HD + r) * SEQ + t * 128 + c * 8);
        }
    };

#pragma unroll
    for (int i = 0; i < 8; i++) {
        int g = tid + i * 256;
        int r = g >> 4, c = g & 15;
        cp16(sb + AQS_OFF + r * QROWB + c * 16,
             Q + (size_t)(b * SEQ + qb + r) * HID + h * HD + c * 8);
    }
    load_tile(0, 0);
    cp_commit();

    const int a_row = lane & 15;
    const int a_hi  = (lane >> 4) * 16;
    const int b_row = (lane & 7) | ((lane >> 1) & 8);
    const int b_hi  = ((lane >> 3) & 1) * 16;
    const uint32_t qA = sb + AQS_OFF + (warp * 16 + a_row) * QROWB + a_hi;
    const uint32_t pA = sb + APS_OFF + (warp * 16 + a_row) * QROWB + a_hi;
    const uint32_t kOff = b_row * QROWB + b_hi;
    const uint32_t vOff = 128 * QROWB + b_row * QROWB + b_hi;

    float o[16][4];
#pragma unroll
    for (int nt = 0; nt < 16; nt++)
#pragma unroll
        for (int j = 0; j < 4; j++) o[nt][j] = 0.f;
    float mr0 = -1e30f, mr1 = -1e30f, l0 = 0.f, l1 = 0.f;
    const int r0g = qb + warp * 16 + lm;
    const int r1g = r0g + 8;

    const int ntiles = qi + 1;
    for (int t = 0; t < ntiles; t++) {
        const int buf = t & 1;
        if (t + 1 < ntiles) {
            load_tile(t + 1, buf ^ 1);
            cp_commit();
            cp_wait<1>();
        } else {
            cp_wait<0>();
        }
        __syncthreads();

        const uint32_t kB = kvb[buf] + kOff;
        const uint32_t vB = kvb[buf] + vOff;

        // QK scores: 16 rows x 128 cols per warp
        float s_[16][4];
#pragma unroll
        for (int nt = 0; nt < 16; nt++)
#pragma unroll
            for (int j = 0; j < 4; j++) s_[nt][j] = 0.f;

#pragma unroll
        for (int ks = 0; ks < 8; ks++) {
            uint32_t a0, a1, a2, a3;
            LDSM4(a0, a1, a2, a3, qA + ks * 32);
#pragma unroll
            for (int pr = 0; pr < 8; pr++) {
                uint32_t b0, b1, b2, b3;
                LDSM4(b0, b1, b2, b3, kB + pr * 16 * QROWB + ks * 32);
                mma_f16(s_[2 * pr],     a0, a1, a2, a3, b0, b1);
                mma_f16(s_[2 * pr + 1], a0, a1, a2, a3, b2, b3);
            }
        }

        // causal mask (last tile only)
        if (t == qi) {
#pragma unroll
            for (int nt = 0; nt < 16; nt++) {
                int cb = t * 128 + nt * 8 + 2 * lq;
                if (cb > r0g)     s_[nt][0] = -1e30f;
                if (cb + 1 > r0g) s_[nt][1] = -1e30f;
                if (cb > r1g)     s_[nt][2] = -1e30f;
                if (cb + 1 > r1g) s_[nt][3] = -1e30f;
            }
        }

        float tm0 = -1e30f, tm1 = -1e30f;
#pragma unroll
        for (int nt = 0; nt < 16; nt++) {
            tm0 = fmaxf(tm0, fmaxf(s_[nt][0], s_[nt][1]));
            tm1 = fmaxf(tm1, fmaxf(s_[nt][2], s_[nt][3]));
        }
        tm0 = fmaxf(tm0, __shfl_xor_sync(0xffffffffu, tm0, 1));
        tm0 = fmaxf(tm0, __shfl_xor_sync(0xffffffffu, tm0, 2));
        tm1 = fmaxf(tm1, __shfl_xor_sync(0xffffffffu, tm1, 1));
        tm1 = fmaxf(tm1, __shfl_xor_sync(0xffffffffu, tm1, 2));
        float mn0 = fmaxf(mr0, tm0), mn1 = fmaxf(mr1, tm1);
        float c0 = __expf(mr0 - mn0), c1 = __expf(mr1 - mn1);
        float ps0 = 0.f, ps1 = 0.f;
#pragma unroll
        for (int nt = 0; nt < 16; nt++) {
            s_[nt][0] = __expf(s_[nt][0] - mn0);
            s_[nt][1] = __expf(s_[nt][1] - mn0);
            s_[nt][2] = __expf(s_[nt][2] - mn1);
            s_[nt][3] = __expf(s_[nt][3] - mn1);
            ps0 += s_[nt][0] + s_[nt][1];
            ps1 += s_[nt][2] + s_[nt][3];
        }
        l0 = l0 * c0 + ps0;
        l1 = l1 * c1 + ps1;
#pragma unroll
        for (int nt = 0; nt < 16; nt++) {
            o[nt][0] *= c0; o[nt][1] *= c0;
            o[nt][2] *= c1; o[nt][3] *= c1;
        }
        mr0 = mn0; mr1 = mn1;

        // P -> smem fp16 (warp-private rows)
#pragma unroll
        for (int nt = 0; nt < 16; nt++) {
            *(__half2*)(smem + APS_OFF + (warp * 16 + lm) * QROWB + (nt * 8 + 2 * lq) * 2)
                = __floats2half2_rn(s_[nt][0], s_[nt][1]);
            *(__half2*)(smem + APS_OFF + (warp * 16 + lm + 8) * QROWB + (nt * 8 + 2 * lq) * 2)
                = __floats2half2_rn(s_[nt][2], s_[nt][3]);
        }
        __syncwarp();

        // PV: O[16x128] += P[16x128] * V[128x128]
#pragma unroll
        for (int ks = 0; ks < 8; ks++) {
            uint32_t a0, a1, a2, a3;
            LDSM4(a0, a1, a2, a3, pA + ks * 32);
#pragma unroll
            for (int pr = 0; pr < 8; pr++) {
                uint32_t b0, b1, b2, b3;
                LDSM4(b0, b1, b2, b3, vB + pr * 16 * QROWB + ks * 32);
                mma_f16(o[2 * pr],     a0, a1, a2, a3, b0, b1);
                mma_f16(o[2 * pr + 1], a0, a1, a2, a3, b2, b3);
            }
        }
        __syncthreads();
    }

    l0 += __shfl_xor_sync(0xffffffffu, l0, 1);
    l0 += __shfl_xor_sync(0xffffffffu, l0, 2);
    l1 += __shfl_xor_sync(0xffffffffu, l1, 1);
    l1 += __shfl_xor_sync(0xffffffffu, l1, 2);
    float i0 = 1.f / l0, i1 = 1.f / l1;

#pragma unroll
    for (int nt = 0; nt < 16; nt++) {
        int col = nt * 8 + 2 * lq;
        *(__half2*)&ctx[(size_t)(b * SEQ + r0g) * HID + h * HD + col] =
            __floats2half2_rn(o[nt][0] * i0, o[nt][1] * i0);
        *(__half2*)&ctx[(size_t)(b * SEQ + r1g) * HID + h * HD + col] =
            __floats2half2_rn(o[nt][2] * i1, o[nt][3] * i1);
    }
}

// ---------------- launch ----------------
extern "C" void kernel_launch(void* const* d_in, const int* in_sizes, int n_in,
                              void* d_out, int out_size) {
    const float* hidden = (const float*)d_in[0];
    const int*   tt     = (const int*)d_in[1];
    const int*   pos    = (const int*)d_in[2];
    const float* wvq    = (const float*)d_in[3];
    const float* wlq    = (const float*)d_in[4];
    const float* wvd    = (const float*)d_in[5];
    const float* wld    = (const float*)d_in[6];
    float* out = (float*)d_out;

    __half *qkv_p, *q_p, *k_p, *vt_p, *ctx_p, *hidh_p, *wr_p;
    cudaGetSymbolAddress((void**)&qkv_p, g_qkv);
    cudaGetSymbolAddress((void**)&q_p, g_q);
    cudaGetSymbolAddress((void**)&k_p, g_k);
    cudaGetSymbolAddress((void**)&vt_p, g_vt);
    cudaGetSymbolAddress((void**)&ctx_p, g_ctx);
    cudaGetSymbolAddress((void**)&hidh_p, g_hidh);
    cudaGetSymbolAddress((void**)&wr_p, g_wr);

    __half* wr_vq = wr_p + WR_VQ;
    __half* wr_lq = wr_p + WR_LQ;
    __half* wr_vd = wr_p + WR_VD;
    __half* wr_ld = wr_p + WR_LD;

    cudaFuncSetAttribute((const void*)&gemm_tc<__half>, cudaFuncAttributeMaxDynamicSharedMemorySize, GEMM_SMEM);
    cudaFuncSetAttribute((const void*)&gemm_tc<float>, cudaFuncAttributeMaxDynamicSharedMemorySize, GEMM_SMEM);
    cudaFuncSetAttribute(attn_mma, cudaFuncAttributeMaxDynamicSharedMemorySize, ATT_SMEM);

    zero_cnt_kernel<<<1, 32>>>();
    route_kernel<<<MTOK / 256, 256>>>(tt);
    pack_kernel<<<1, 256>>>();

    f2h_all<<<(F4_HALF + 255) / 256, 256>>>((const float4*)wvq, (const float4*)wlq,
                                            (const float4*)wvd, (const float4*)wld,
                                            (const float4*)hidden);

    // QKV projection: merged experts
    {
        dim3 grid(MTOK / BM + 2, QKVN / BN);
        gemm_tc<__half><<<grid, 256, GEMM_SMEM>>>(hidh_p, wr_vq, wr_lq, qkv_p, QKVN);
    }

    // RoPE + V transpose
    rope_kernel<<<(MTOK * NH * 64) / 256, 256>>>(qkv_p, pos, q_p, k_p);
    {
        dim3 gv(SEQ / 32, HD / 32, BATCH * NH);
        vtrans_kernel<<<gv, 256>>>(qkv_p, vt_p);
    }

    // fp16 flash attention (K-tile 128)
    {
        dim3 grid(SEQ / 128, NH, BATCH);
        attn_mma<<<grid, 256, ATT_SMEM>>>(q_p, k_p, vt_p, ctx_p);
    }

    // Dense projection: merged experts
    {
        dim3 grid(MTOK / BM + 2, HID / BN);
        gemm_tc<float><<<grid, 256, GEMM_SMEM>>>(ctx_p, wr_vd, wr_ld, out, HID);
    }
}

// round 15
// speedup vs baseline: 1.9718x; 1.0019x over previous
#include <cuda_runtime.h>
#include <cuda_fp16.h>
#include <math.h>
#include <stdint.h>

// Problem constants
#define BATCH 2
#define SEQ   2048
#define NH    32
#define HD    128
#define HID   4096           // NH*HD
#define QKVN  12288          // 3*HID
#define MTOK  (BATCH*SEQ)    // 4096 tokens

// GEMM tile config (mma.sync m16n8k16 fp16; A ldmatrix, B ldmatrix.trans)
#define BM 128
#define BN 256
#define BK 64
#define STAGES 4
#define AROWB 144
#define BROWB 528
#define A_TILE_BYTES (128 * AROWB)
#define B_TILE_BYTES (64 * BROWB)
#define STAGE_BYTES (A_TILE_BYTES + B_TILE_BYTES)
#define GEMM_SMEM (STAGES * STAGE_BYTES)         // 208896

// Attention smem layout (fp16, K-tile 128, double-buffered K/V)
#define QROWB 272
#define AQS_OFF 0
#define KV_STAGE (256 * QROWB)
#define AKV0_OFF (128 * QROWB)
#define AKV1_OFF (AKV0_OFF + KV_STAGE)
#define APS_OFF (AKV1_OFF + KV_STAGE)
#define ATT_SMEM (APS_OFF + 128 * QROWB)         // 208896

// ---------------- scratch (device globals) -------------
__device__ __half g_qkv[(size_t)MTOK * QKVN];
__device__ __half g_q[(size_t)MTOK * HID];
__device__ __half g_k[(size_t)MTOK * HID];
__device__ __half g_vt[(size_t)BATCH * NH * HD * SEQ];
__device__ __half g_ctx[(size_t)MTOK * HID];
__device__ __half g_hidh[(size_t)MTOK * HID];
#define WR_VQ 0
#define WR_LQ ((size_t)HID * QKVN)
#define WR_VD (2 * (size_t)HID * QKVN)
#define WR_LD (2 * (size_t)HID * QKVN + (size_t)HID * HID)
__device__ __half g_wr[2 * (size_t)HID * QKVN + 2 * (size_t)HID * HID];
__device__ int    g_cnt[2];
__device__ int    g_idx[2][MTOK];
__device__ int    g_idxc[MTOK + 256];
__device__ int    g_seg[4];

// ---------------- helpers ----------------
__device__ __forceinline__ uint32_t smem_u32(const void* p) {
    uint32_t a;
    asm("{ .reg .u64 t; cvta.to.shared.u64 t, %1; cvt.u32.u64 %0, t; }" : "=r"(a) : "l"(p));
    return a;
}
__device__ __forceinline__ void cp16(uint32_t dst, const void* src) {
    asm volatile("cp.async.cg.shared.global [%0], [%1], 16;" :: "r"(dst), "l"(src));
}
__device__ __forceinline__ void cp_commit() {
    asm volatile("cp.async.commit_group;" ::: "memory");
}
template <int N>
__device__ __forceinline__ void cp_wait() {
    asm volatile("cp.async.wait_group %0;" :: "n"(N) : "memory");
}
__device__ __forceinline__ void mma_f16(float* c, uint32_t a0, uint32_t a1, uint32_t a2, uint32_t a3,
                                        uint32_t b0, uint32_t b1) {
    asm volatile(
        "mma.sync.aligned.m16n8k16.row.col.f32.f16.f16.f32 "
        "{%0,%1,%2,%3}, {%4,%5,%6,%7}, {%8,%9}, {%0,%1,%2,%3};"
        : "+f"(c[0]), "+f"(c[1]), "+f"(c[2]), "+f"(c[3])
        : "r"(a0), "r"(a1), "r"(a2), "r"(a3), "r"(b0), "r"(b1));
}
#define LDSM4(r0, r1, r2, r3, addr)                                               \
    asm volatile("ldmatrix.sync.aligned.m8n8.x4.shared.b16 {%0,%1,%2,%3}, [%4];"   \
        : "=r"(r0), "=r"(r1), "=r"(r2), "=r"(r3) : "r"(addr))
#define LDSM4T(r0, r1, r2, r3, addr)                                              \
    asm volatile("ldmatrix.sync.aligned.m8n8.x4.trans.shared.b16 {%0,%1,%2,%3}, [%4];" \
        : "=r"(r0), "=r"(r1), "=r"(r2), "=r"(r3) : "r"(addr))

__device__ __forceinline__ void store2(float* p, float a, float b) {
    *(float2*)p = make_float2(a, b);
}
__device__ __forceinline__ void store2(__half* p, float a, float b) {
    *(__half2*)p = __floats2half2_rn(a, b);
}

// ---------------- fp32 -> fp16 convert (single tensor) ----------------
__global__ __launch_bounds__(256)
void f2h_kernel(const float4* __restrict__ in, __half2* __restrict__ out, int n4) {
    int i = blockIdx.x * blockDim.x + threadIdx.x;
    if (i >= n4) return;
    float4 v = in[i];
    out[2 * i]     = __floats2half2_rn(v.x, v.y);
    out[2 * i + 1] = __floats2half2_rn(v.z, v.w);
}

// V transpose: g_vt[bh][d][s]
__global__ __launch_bounds__(256)
void vtrans_kernel(const __half* __restrict__ qkv, __half* __restrict__ Vt) {
    __shared__ float t[32][33];
    int bh = blockIdx.z;
    int b = bh >> 5, h = bh & 31;
    int s0 = blockIdx.x * 32;
    int d0 = blockIdx.y * 32;
    int x = threadIdx.x & 31;
    int y = threadIdx.x >> 5;
#pragma unroll
    for (int i = 0; i < 32; i += 8)
        t[y + i][x] = __half2float(qkv[(size_t)(b * SEQ + s0 + y + i) * QKVN + 2 * HID + h * HD + d0 + x]);
    __syncthreads();
#pragma unroll
    for (int i = 0; i < 32; i += 8)
        Vt[((size_t)bh * HD + d0 + y + i) * SEQ + s0 + x] = __float2half(t[x][y + i]);
}

// ---------------- mask / routing / packing ----------------
__global__ void zero_cnt_kernel() {
    if (threadIdx.x < 2) g_cnt[threadIdx.x] = 0;
}
__global__ void route_kernel(const int* __restrict__ tt) {
    int idx = blockIdx.x * blockDim.x + threadIdx.x;
    if (idx >= MTOK) return;
    int s = idx & (SEQ - 1);
    int vis = (s + 1 < SEQ) && (tt[idx] == 1) && (tt[idx + 1] == 1);
    int e = vis ? 0 : 1;
    int pos = atomicAdd(&g_cnt[e], 1);
    g_idx[e][pos] = idx;
}
__global__ void pack_kernel() {
    int c0 = g_cnt[0], c1 = g_cnt[1];
    int pad0 = (c0 + 127) & ~127;
    int pad1 = (c1 + 127) & ~127;
    if (threadIdx.x == 0) {
        g_seg[0] = pad0;
        g_seg[1] = pad0 + pad1;
        g_seg[2] = c0;
        g_seg[3] = c1;
    }
    for (int i = threadIdx.x; i < pad0; i += blockDim.x)
        g_idxc[i] = g_idx[0][i < c0 ? i : c0 - 1];
    for (int j = threadIdx.x; j < pad1; j += blockDim.x)
        g_idxc[pad0 + j] = g_idx[1][j < c1 ? j : c1 - 1];
}

// ---------------- merged-expert fp16 GEMM (fragment double-buffered) ----------------
template <typename CT>
__global__ __launch_bounds__(256, 1)
void gemm_tc(const __half* __restrict__ A,
             const __half* __restrict__ Wvis, const __half* __restrict__ Wlang,
             CT* __restrict__ C, int N) {
    __shared__ int idx_s[BM];
    extern __shared__ char smem[];
    const uint32_t sb = smem_u32(smem);
    const int tid = threadIdx.x;
    const int wid = tid >> 5;
    const int lane = tid & 31;
    const int lm = lane >> 2;
    const int lq = lane & 3;
    const int warp_m = wid & 1;
    const int warp_n = wid >> 1;
    const int m0 = blockIdx.x * BM;
    const int n0 = blockIdx.y * BN;

    const int s0 = __ldg(&g_seg[0]);
    const int s1 = __ldg(&g_seg[1]);
    if (m0 >= s1) return;
    const bool is_vis = (m0 < s0);
    const __half* W = is_vis ? Wvis : Wlang;
    const int limit = is_vis ? __ldg(&g_seg[2]) : (s0 + __ldg(&g_seg[3]));

    if (tid < BM) idx_s[tid] = g_idxc[m0 + tid];
    __syncthreads();

    int a_r[4], a_c[4];
#pragma unroll
    for (int i = 0; i < 4; i++) {
        int t = tid + i * 256;
        a_r[i] = t >> 3;
        a_c[i] = t & 7;
    }
    int a_g[4];
#pragma unroll
    for (int i = 0; i < 4; i++) a_g[i] = idx_s[a_r[i]];
    int b_r[8], b_c[8];
#pragma unroll
    for (int i = 0; i < 8; i++) {
        int t = tid + i * 256;
        b_r[i] = t >> 5;
        b_c[i] = t & 31;
    }

    auto load_stage = [&](int stage, int chunk) {
        uint32_t as = sb + stage * STAGE_BYTES;
        uint32_t bs = as + A_TILE_BYTES;
#pragma unroll
        for (int i = 0; i < 4; i++)
            cp16(as + a_r[i] * AROWB + a_c[i] * 16,
                 A + (size_t)a_g[i] * HID + chunk * BK + a_c[i] * 8);
#pragma unroll
        for (int i = 0; i < 8; i++)
            cp16(bs + b_r[i] * BROWB + b_c[i] * 16,
                 W + (size_t)(chunk * BK + b_r[i]) * N + n0 + b_c[i] * 8);
    };

    const uint32_t a_off = (warp_m * 64 + (lane & 15)) * AROWB + (lane >> 4) * 16;
    const uint32_t b_off = (lane & 15) * BROWB + (lane >> 4) * 16 + warp_n * 128;

    float c[4][8][4];
#pragma unroll
    for (int mt = 0; mt < 4; mt++)
#pragma unroll
        for (int nt = 0; nt < 8; nt++)
#pragma unroll
            for (int j = 0; j < 4; j++) c[mt][nt][j] = 0.f;

    const int NC = HID / BK;  // 64

    load_stage(0, 0); cp_commit();
    load_stage(1, 1); cp_commit();
    load_stage(2, 2); cp_commit();

    uint32_t af[2][4][4], bf[2][8][2];

    for (int ch = 0; ch < NC; ch++) {
        cp_wait<2>();
        __syncthreads();
        if (ch + 3 < NC) load_stage((ch + 3) % STAGES, ch + 3);
        cp_commit();

        const uint32_t as = sb + (ch % STAGES) * STAGE_BYTES;
        const uint32_t aL = as + a_off;
        const uint32_t bL = as + A_TILE_BYTES + b_off;

#pragma unroll
        for (int mt = 0; mt < 4; mt++)
            LDSM4(af[0][mt][0], af[0][mt][1], af[0][mt][2], af[0][mt][3],
                  aL + mt * 16 * AROWB);
#pragma unroll
        for (int pr = 0; pr < 4; pr++)
            LDSM4T(bf[0][2 * pr][0], bf[0][2 * pr][1], bf[0][2 * pr + 1][0], bf[0][2 * pr + 1][1],
                   bL + pr * 32);

#pragma unroll
        for (int ks = 0; ks < 4; ks++) {
            const int cur = ks & 1, nxt = cur ^ 1;
            if (ks < 3) {
#pragma unroll
                for (int mt = 0; mt < 4; mt++)
                    LDSM4(af[nxt][mt][0], af[nxt][mt][1], af[nxt][mt][2], af[nxt][mt][3],
                          aL + mt * 16 * AROWB + (ks + 1) * 32);
#pragma unroll
                for (int pr = 0; pr < 4; pr++)
                    LDSM4T(bf[nxt][2 * pr][0], bf[nxt][2 * pr][1],
                           bf[nxt][2 * pr + 1][0], bf[nxt][2 * pr + 1][1],
                           bL + (ks + 1) * 16 * BROWB + pr * 32);
            }
#pragma unroll
            for (int mt = 0; mt < 4; mt++)
#pragma unroll
                for (int nt = 0; nt < 8; nt++)
                    mma_f16(c[mt][nt], af[cur][mt][0], af[cur][mt][1], af[cur][mt][2], af[cur][mt][3],
                            bf[cur][nt][0], bf[cur][nt][1]);
        }
    }

#pragma unroll
    for (int mt = 0; mt < 4; mt++) {
        int r0 = warp_m * 64 + mt * 16 + lm;
        int r1 = r0 + 8;
        bool on0 = (m0 + r0 < limit);
        bool on1 = (m0 + r1 < limit);
        CT* p0 = C + (size_t)idx_s[r0] * N + n0 + warp_n * 64;
        CT* p1 = C + (size_t)idx_s[r1] * N + n0 + warp_n * 64;
#pragma unroll
        for (int nt = 0; nt < 8; nt++) {
            int col = nt * 8 + 2 * lq;
            if (on0) store2(p0 + col, c[mt][nt][0], c[mt][nt][1]);
            if (on1) store2(p1 + col, c[mt][nt][2], c[mt][nt][3]);
        }
    }
}

// ---------------- RoPE ----------------
__global__ void rope_kernel(const __half* __restrict__ qkv, const int* __restrict__ pos_ids,
                            __half* __restrict__ q, __half* __restrict__ k) {
    int idx = blockIdx.x * blockDim.x + threadIdx.x;
    if (idx >= MTOK * NH * 64) return;
    int i = idx & 63;
    int h = (idx >> 6) & 31;
    int m = idx >> 11;

    float pos = (float)pos_ids[m];
    float freq = expf(-(float)i * (9.210340371976184f / 64.f));
    float ang = pos * freq;
    float cv = cosf(ang);
    float sv = sinf(ang);
    const float scale = 0.088388347648318447f;

    const __half* qs = qkv + (size_t)m * QKVN + h * HD;
    const __half* ks = qs + HID;
    float q0 = __half2float(qs[i]), q1 = __half2float(qs[i + 64]);
    float k0 = __half2float(ks[i]), k1 = __half2float(ks[i + 64]);

    size_t o = (size_t)m * HID + h * HD;
    q[o + i]      = __float2half((q0 * cv - q1 * sv) * scale);
    q[o + i + 64] = __float2half((q1 * cv + q0 * sv) * scale);
    k[o + i]      = __float2half(k0 * cv - k1 * sv);
    k[o + i + 64] = __float2half(k1 * cv + k0 * sv);
}

// ---------------- fp16 flash attention, K-tile 128, double-buffered K/V ----------------
__global__ __launch_bounds__(256)
void attn_mma(const __half* __restrict__ Q, const __half* __restrict__ Kg,
              const __half* __restrict__ Vt, __half* __restrict__ ctx) {
    extern __shared__ char smem[];
    const uint32_t sb = smem_u32(smem);
    const int tid = threadIdx.x;
    const int warp = tid >> 5;
    const int lane = tid & 31;
    const int lm = lane >> 2;
    const int lq = lane & 3;
    const int b = blockIdx.z;
    const int h = blockIdx.y;
    const int qi = (int)gridDim.x - 1 - (int)blockIdx.x;
    const int qb = qi * 128;

    const uint32_t kvb[2] = {sb + AKV0_OFF, sb + AKV1_OFF};

    auto load_tile = [&](int t, int buf) {
        uint32_t kb = kvb[buf];
        uint32_t vb = kvb[buf] + 128 * QROWB;
#pragma unroll
        for (int i = 0; i < 8; i++) {
            int g = tid + i * 256;
            int r = g >> 4, c = g & 15;
            cp16(kb + r * QROWB + c * 16,
                 Kg + (size_t)(b * SEQ + t * 128 + r) * HID + h * HD + c * 8);
        }
#pragma unroll
        for (int i = 0; i < 8; i++) {
            int g = tid + i * 256;
            int r = g >> 4, c = g & 15;
            cp16(vb + r * QROWB + c * 16,
                 Vt + ((size_t)(b * NH + h) * HD + r) * SEQ + t * 128 + c * 8);
        }
    };

#pragma unroll
    for (int i = 0; i < 8; i++) {
        int g = tid + i * 256;
        int r = g >> 4, c = g & 15;
        cp16(sb + AQS_OFF + r * QROWB + c * 16,
             Q + (size_t)(b * SEQ + qb + r) * HID + h * HD + c * 8);
    }
    load_tile(0, 0);
    cp_commit();

    const int a_row = lane & 15;
    const int a_hi  = (lane >> 4) * 16;
    const int b_row = (lane & 7) | ((lane >> 1) & 8);
    const int b_hi  = ((lane >> 3) & 1) * 16;
    const uint32_t qA = sb + AQS_OFF + (warp * 16 + a_row) * QROWB + a_hi;
    const uint32_t pA = sb + APS_OFF + (warp * 16 + a_row) * QROWB + a_hi;
    const uint32_t kOff = b_row * QROWB + b_hi;
    const uint32_t vOff = 128 * QROWB + b_row * QROWB + b_hi;

    float o[16][4];
#pragma unroll
    for (int nt = 0; nt < 16; nt++)
#pragma unroll
        for (int j = 0; j < 4; j++) o[nt][j] = 0.f;
    float mr0 = -1e30f, mr1 = -1e30f, l0 = 0.f, l1 = 0.f;
    const int r0g = qb + warp * 16 + lm;
    const int r1g = r0g + 8;

    const int ntiles = qi + 1;
    for (int t = 0; t < ntiles; t++) {
        const int buf = t & 1;
        if (t + 1 < ntiles) {
            load_tile(t + 1, buf ^ 1);
            cp_commit();
            cp_wait<1>();
        } else {
            cp_wait<0>();
        }
        __syncthreads();

        const uint32_t kB = kvb[buf] + kOff;
        const uint32_t vB = kvb[buf] + vOff;

        float s_[16][4];
#pragma unroll
        for (int nt = 0; nt < 16; nt++)
#pragma unroll
            for (int j = 0; j < 4; j++) s_[nt][j] = 0.f;

#pragma unroll
        for (int ks = 0; ks < 8; ks++) {
            uint32_t a0, a1, a2, a3;
            LDSM4(a0, a1, a2, a3, qA + ks * 32);
#pragma unroll
            for (int pr = 0; pr < 8; pr++) {
                uint32_t b0, b1, b2, b3;
                LDSM4(b0, b1, b2, b3, kB + pr * 16 * QROWB + ks * 32);
                mma_f16(s_[2 * pr],     a0, a1, a2, a3, b0, b1);
                mma_f16(s_[2 * pr + 1], a0, a1, a2, a3, b2, b3);
            }
        }

        if (t == qi) {
#pragma unroll
            for (int nt = 0; nt < 16; nt++) {
                int cb = t * 128 + nt * 8 + 2 * lq;
                if (cb > r0g)     s_[nt][0] = -1e30f;
                if (cb + 1 > r0g) s_[nt][1] = -1e30f;
                if (cb > r1g)     s_[nt][2] = -1e30f;
                if (cb + 1 > r1g) s_[nt][3] = -1e30f;
            }
        }

        float tm0 = -1e30f, tm1 = -1e30f;
#pragma unroll
        for (int nt = 0; nt < 16; nt++) {
            tm0 = fmaxf(tm0, fmaxf(s_[nt][0], s_[nt][1]));
            tm1 = fmaxf(tm1, fmaxf(s_[nt][2], s_[nt][3]));
        }
        tm0 = fmaxf(tm0, __shfl_xor_sync(0xffffffffu, tm0, 1));
        tm0 = fmaxf(tm0, __shfl_xor_sync(0xffffffffu, tm0, 2));
        tm1 = fmaxf(tm1, __shfl_xor_sync(0xffffffffu, tm1, 1));
        tm1 = fmaxf(tm1, __shfl_xor_sync(0xffffffffu, tm1, 2));
        float mn0 = fmaxf(mr0, tm0), mn1 = fmaxf(mr1, tm1);
        float c0 = __expf(mr0 - mn0), c1 = __expf(mr1 - mn1);
        float ps0 = 0.f, ps1 = 0.f;
#pragma unroll
        for (int nt = 0; nt < 16; nt++) {
            s_[nt][0] = __expf(s_[nt][0] - mn0);
            s_[nt][1] = __expf(s_[nt][1] - mn0);
            s_[nt][2] = __expf(s_[nt][2] - mn1);
            s_[nt][3] = __expf(s_[nt][3] - mn1);
            ps0 += s_[nt][0] + s_[nt][1];
            ps1 += s_[nt][2] + s_[nt][3];
        }
        l0 = l0 * c0 + ps0;
        l1 = l1 * c1 + ps1;
#pragma unroll
        for (int nt = 0; nt < 16; nt++) {
            o[nt][0] *= c0; o[nt][1] *= c0;
            o[nt][2] *= c1; o[nt][3] *= c1;
        }
        mr0 = mn0; mr1 = mn1;

#pragma unroll
        for (int nt = 0; nt < 16; nt++) {
            *(__half2*)(smem + APS_OFF + (warp * 16 + lm) * QROWB + (nt * 8 + 2 * lq) * 2)
                = __floats2half2_rn(s_[nt][0], s_[nt][1]);
            *(__half2*)(smem + APS_OFF + (warp * 16 + lm + 8) * QROWB + (nt * 8 + 2 * lq) * 2)
                = __floats2half2_rn(s_[nt][2], s_[nt][3]);
        }
        __syncwarp();

#pragma unroll
        for (int ks = 0; ks < 8; ks++) {
            uint32_t a0, a1, a2, a3;
            LDSM4(a0, a1, a2, a3, pA + ks * 32);
#pragma unroll
            for (int pr = 0; pr < 8; pr++) {
                uint32_t b0, b1, b2, b3;
                LDSM4(b0, b1, b2, b3, vB + pr * 16 * QROWB + ks * 32);
                mma_f16(o[2 * pr],     a0, a1, a2, a3, b0, b1);
                mma_f16(o[2 * pr + 1], a0, a1, a2, a3, b2, b3);
            }
        }
        __syncthreads();
    }

    l0 += __shfl_xor_sync(0xffffffffu, l0, 1);
    l0 += __shfl_xor_sync(0xffffffffu, l0, 2);
    l1 += __shfl_xor_sync(0xffffffffu, l1, 1);
    l1 += __shfl_xor_sync(0xffffffffu, l1, 2);
    float i0 = 1.f / l0, i1 = 1.f / l1;

#pragma unroll
    for (int nt = 0; nt < 16; nt++) {
        int col = nt * 8 + 2 * lq;
        *(__half2*)&ctx[(size_t)(b * SEQ + r0g) * HID + h * HD + col] =
            __floats2half2_rn(o[nt][0] * i0, o[nt][1] * i0);
        *(__half2*)&ctx[(size_t)(b * SEQ + r1g) * HID + h * HD + col] =
            __floats2half2_rn(o[nt][2] * i1, o[nt][3] * i1);
    }
}

// ---------------- launch ----------------
extern "C" void kernel_launch(void* const* d_in, const int* in_sizes, int n_in,
                              void* d_out, int out_size) {
    const float* hidden = (const float*)d_in[0];
    const int*   tt     = (const int*)d_in[1];
    const int*   pos    = (const int*)d_in[2];
    const float* wvq    = (const float*)d_in[3];
    const float* wlq    = (const float*)d_in[4];
    const float* wvd    = (const float*)d_in[5];
    const float* wld    = (const float*)d_in[6];
    float* out = (float*)d_out;

    __half *qkv_p, *q_p, *k_p, *vt_p, *ctx_p, *hidh_p, *wr_p;
    cudaGetSymbolAddress((void**)&qkv_p, g_qkv);
    cudaGetSymbolAddress((void**)&q_p, g_q);
    cudaGetSymbolAddress((void**)&k_p, g_k);
    cudaGetSymbolAddress((void**)&vt_p, g_vt);
    cudaGetSymbolAddress((void**)&ctx_p, g_ctx);
    cudaGetSymbolAddress((void**)&hidh_p, g_hidh);
    cudaGetSymbolAddress((void**)&wr_p, g_wr);

    __half* wr_vq = wr_p + WR_VQ;
    __half* wr_lq = wr_p + WR_LQ;
    __half* wr_vd = wr_p + WR_VD;
    __half* wr_ld = wr_p + WR_LD;

    cudaFuncSetAttribute((const void*)&gemm_tc<__half>, cudaFuncAttributeMaxDynamicSharedMemorySize, GEMM_SMEM);
    cudaFuncSetAttribute((const void*)&gemm_tc<float>, cudaFuncAttributeMaxDynamicSharedMemorySize, GEMM_SMEM);
    cudaFuncSetAttribute(attn_mma, cudaFuncAttributeMaxDynamicSharedMemorySize, ATT_SMEM);

    // lazy one-time creation of side stream + events (first call is the
    // uncaptured correctness run; creation does identical work every call path
    // after that: the same fork/join topology is recorded).
    static cudaStream_t s2 = nullptr;
    static cudaEvent_t ev0 = nullptr, evR = nullptr, ev1 = nullptr, evA = nullptr, evB = nullptr;
    if (s2 == nullptr) {
        cudaStreamCreateWithFlags(&s2, cudaStreamNonBlocking);
        cudaEventCreateWithFlags(&ev0, cudaEventDisableTiming);
        cudaEventCreateWithFlags(&evR, cudaEventDisableTiming);
        cudaEventCreateWithFlags(&ev1, cudaEventDisableTiming);
        cudaEventCreateWithFlags(&evA, cudaEventDisableTiming);
        cudaEventCreateWithFlags(&evB, cudaEventDisableTiming);
    }

    const int n4w = (int)((size_t)HID * QKVN / 4);
    const int n4d = (int)((size_t)HID * HID / 4);
    const int n4h = (int)((size_t)MTOK * HID / 4);

    // fork s2 from the main (legacy) stream
    cudaEventRecord(ev0, 0);
    cudaStreamWaitEvent(s2, ev0, 0);

    // s2 branch: routing + dense-weight conversion (hidden under QKV GEMM)
    zero_cnt_kernel<<<1, 32, 0, s2>>>();
    route_kernel<<<MTOK / 256, 256, 0, s2>>>(tt);
    pack_kernel<<<1, 256, 0, s2>>>();
    cudaEventRecord(evR, s2);
    f2h_kernel<<<(n4d + 255) / 256, 256, 0, s2>>>((const float4*)wvd, (__half2*)wr_vd, n4d);
    f2h_kernel<<<(n4d + 255) / 256, 256, 0, s2>>>((const float4*)wld, (__half2*)wr_ld, n4d);
    cudaEventRecord(evA, s2);

    // main: qkv weights + hidden conversion
    f2h_kernel<<<(n4w + 255) / 256, 256>>>((const float4*)wvq, (__half2*)wr_vq, n4w);
    f2h_kernel<<<(n4w + 255) / 256, 256>>>((const float4*)wlq, (__half2*)wr_lq, n4w);
    f2h_kernel<<<(n4h + 255) / 256, 256>>>((const float4*)hidden, (__half2*)hidh_p, n4h);

    // QKV projection (needs routing from s2)
    cudaStreamWaitEvent(0, evR, 0);
    {
        dim3 grid(MTOK / BM + 2, QKVN / BN);
        gemm_tc<__half><<<grid, 256, GEMM_SMEM>>>(hidh_p, wr_vq, wr_lq, qkv_p, QKVN);
    }
    cudaEventRecord(ev1, 0);

    // rope on main; vtrans in parallel on s2
    rope_kernel<<<(MTOK * NH * 64) / 256, 256>>>(qkv_p, pos, q_p, k_p);
    cudaStreamWaitEvent(s2, ev1, 0);
    {
        dim3 gv(SEQ / 32, HD / 32, BATCH * NH);
        vtrans_kernel<<<gv, 256, 0, s2>>>(qkv_p, vt_p);
    }
    cudaEventRecord(evB, s2);

    // attention (needs rope [main-ordered] + vtrans [evB])
    cudaStreamWaitEvent(0, evB, 0);
    {
        dim3 grid(SEQ / 128, NH, BATCH);
        attn_mma<<<grid, 256, ATT_SMEM>>>(q_p, k_p, vt_p, ctx_p);
    }

    // dense projection (needs dense weights [evA] + ctx [main-ordered])
    cudaStreamWaitEvent(0, evA, 0);
    {
        dim3 grid(MTOK / BM + 2, HID / BN);
        gemm_tc<float><<<grid, 256, GEMM_SMEM>>>(ctx_p, wr_vd, wr_ld, out, HID);
    }
}

// round 16
// speedup vs baseline: 1.9736x; 1.0009x over previous
#include <cuda_runtime.h>
#include <cuda_fp16.h>
#include <math.h>
#include <stdint.h>

// Problem constants
#define BATCH 2
#define SEQ   2048
#define NH    32
#define HD    128
#define HID   4096           // NH*HD
#define QKVN  12288          // 3*HID
#define MTOK  (BATCH*SEQ)    // 4096 tokens

// GEMM tile config (mma.sync m16n8k16 fp16; A ldmatrix, B ldmatrix.trans)
#define BM 128
#define BN 256
#define BK 64
#define STAGES 4
#define AROWB 144
#define BROWB 528
#define A_TILE_BYTES (128 * AROWB)
#define B_TILE_BYTES (64 * BROWB)
#define STAGE_BYTES (A_TILE_BYTES + B_TILE_BYTES)
#define GEMM_SMEM (STAGES * STAGE_BYTES)         // 208896

// Attention smem layout (fp16, K-tile 128, double-buffered K/V)
#define QROWB 272
#define AQS_OFF 0
#define KV_STAGE (256 * QROWB)
#define AKV0_OFF (128 * QROWB)
#define AKV1_OFF (AKV0_OFF + KV_STAGE)
#define APS_OFF (AKV1_OFF + KV_STAGE)
#define ATT_SMEM (APS_OFF + 128 * QROWB)         // 208896

// ---------------- scratch (device globals) -------------
__device__ __half g_qkv[(size_t)MTOK * QKVN];
__device__ __half g_q[(size_t)MTOK * HID];
__device__ __half g_k[(size_t)MTOK * HID];
__device__ __half g_vt[(size_t)BATCH * NH * HD * SEQ];
__device__ __half g_ctx[(size_t)MTOK * HID];
__device__ __half g_hidh[(size_t)MTOK * HID];
#define WR_VQ 0
#define WR_LQ ((size_t)HID * QKVN)
#define WR_VD (2 * (size_t)HID * QKVN)
#define WR_LD (2 * (size_t)HID * QKVN + (size_t)HID * HID)
__device__ __half g_wr[2 * (size_t)HID * QKVN + 2 * (size_t)HID * HID];
__device__ int    g_cnt[2];
__device__ int    g_idx[2][MTOK];
__device__ int    g_idxc[MTOK + 256];
__device__ int    g_seg[4];

// ---------------- helpers ----------------
__device__ __forceinline__ uint32_t smem_u32(const void* p) {
    uint32_t a;
    asm("{ .reg .u64 t; cvta.to.shared.u64 t, %1; cvt.u32.u64 %0, t; }" : "=r"(a) : "l"(p));
    return a;
}
__device__ __forceinline__ void cp16(uint32_t dst, const void* src) {
    asm volatile("cp.async.cg.shared.global [%0], [%1], 16;" :: "r"(dst), "l"(src));
}
__device__ __forceinline__ void cp_commit() {
    asm volatile("cp.async.commit_group;" ::: "memory");
}
template <int N>
__device__ __forceinline__ void cp_wait() {
    asm volatile("cp.async.wait_group %0;" :: "n"(N) : "memory");
}
__device__ __forceinline__ void mma_f16(float* c, uint32_t a0, uint32_t a1, uint32_t a2, uint32_t a3,
                                        uint32_t b0, uint32_t b1) {
    asm volatile(
        "mma.sync.aligned.m16n8k16.row.col.f32.f16.f16.f32 "
        "{%0,%1,%2,%3}, {%4,%5,%6,%7}, {%8,%9}, {%0,%1,%2,%3};"
        : "+f"(c[0]), "+f"(c[1]), "+f"(c[2]), "+f"(c[3])
        : "r"(a0), "r"(a1), "r"(a2), "r"(a3), "r"(b0), "r"(b1));
}
#define LDSM4(r0, r1, r2, r3, addr)                                               \
    asm volatile("ldmatrix.sync.aligned.m8n8.x4.shared.b16 {%0,%1,%2,%3}, [%4];"   \
        : "=r"(r0), "=r"(r1), "=r"(r2), "=r"(r3) : "r"(addr))
#define LDSM4T(r0, r1, r2, r3, addr)                                              \
    asm volatile("ldmatrix.sync.aligned.m8n8.x4.trans.shared.b16 {%0,%1,%2,%3}, [%4];" \
        : "=r"(r0), "=r"(r1), "=r"(r2), "=r"(r3) : "r"(addr))

__device__ __forceinline__ void store2(float* p, float a, float b) {
    *(float2*)p = make_float2(a, b);
}
__device__ __forceinline__ void store2(__half* p, float a, float b) {
    *(__half2*)p = __floats2half2_rn(a, b);
}

// ---------------- fp32 -> fp16 convert (single tensor) ----------------
__global__ __launch_bounds__(256)
void f2h_kernel(const float4* __restrict__ in, __half2* __restrict__ out, int n4) {
    int i = blockIdx.x * blockDim.x + threadIdx.x;
    if (i >= n4) return;
    float4 v = in[i];
    out[2 * i]     = __floats2half2_rn(v.x, v.y);
    out[2 * i + 1] = __floats2half2_rn(v.z, v.w);
}

// V transpose: g_vt[bh][d][s]
__global__ __launch_bounds__(256)
void vtrans_kernel(const __half* __restrict__ qkv, __half* __restrict__ Vt) {
    __shared__ float t[32][33];
    int bh = blockIdx.z;
    int b = bh >> 5, h = bh & 31;
    int s0 = blockIdx.x * 32;
    int d0 = blockIdx.y * 32;
    int x = threadIdx.x & 31;
    int y = threadIdx.x >> 5;
#pragma unroll
    for (int i = 0; i < 32; i += 8)
        t[y + i][x] = __half2float(qkv[(size_t)(b * SEQ + s0 + y + i) * QKVN + 2 * HID + h * HD + d0 + x]);
    __syncthreads();
#pragma unroll
    for (int i = 0; i < 32; i += 8)
        Vt[((size_t)bh * HD + d0 + y + i) * SEQ + s0 + x] = __float2half(t[x][y + i]);
}

// ---------------- mask / routing / packing ----------------
__global__ void zero_cnt_kernel() {
    if (threadIdx.x < 2) g_cnt[threadIdx.x] = 0;
}
__global__ void route_kernel(const int* __restrict__ tt) {
    int idx = blockIdx.x * blockDim.x + threadIdx.x;
    if (idx >= MTOK) return;
    int s = idx & (SEQ - 1);
    int vis = (s + 1 < SEQ) && (tt[idx] == 1) && (tt[idx + 1] == 1);
    int e = vis ? 0 : 1;
    int pos = atomicAdd(&g_cnt[e], 1);
    g_idx[e][pos] = idx;
}
__global__ void pack_kernel() {
    int c0 = g_cnt[0], c1 = g_cnt[1];
    int pad0 = (c0 + 127) & ~127;
    int pad1 = (c1 + 127) & ~127;
    if (threadIdx.x == 0) {
        g_seg[0] = pad0;
        g_seg[1] = pad0 + pad1;
        g_seg[2] = c0;
        g_seg[3] = c1;
    }
    for (int i = threadIdx.x; i < pad0; i += blockDim.x)
        g_idxc[i] = g_idx[0][i < c0 ? i : c0 - 1];
    for (int j = threadIdx.x; j < pad1; j += blockDim.x)
        g_idxc[pad0 + j] = g_idx[1][j < c1 ? j : c1 - 1];
}

// ---------------- merged-expert fp16 GEMM (fragment double-buffered) ----------------
template <typename CT>
__global__ __launch_bounds__(256, 1)
void gemm_tc(const __half* __restrict__ A,
             const __half* __restrict__ Wvis, const __half* __restrict__ Wlang,
             CT* __restrict__ C, int N) {
    __shared__ int idx_s[BM];
    extern __shared__ char smem[];
    const uint32_t sb = smem_u32(smem);
    const int tid = threadIdx.x;
    const int wid = tid >> 5;
    const int lane = tid & 31;
    const int lm = lane >> 2;
    const int lq = lane & 3;
    const int warp_m = wid & 1;
    const int warp_n = wid >> 1;
    const int m0 = blockIdx.x * BM;
    const int n0 = blockIdx.y * BN;

    const int s0 = __ldg(&g_seg[0]);
    const int s1 = __ldg(&g_seg[1]);
    if (m0 >= s1) return;
    const bool is_vis = (m0 < s0);
    const __half* W = is_vis ? Wvis : Wlang;
    const int limit = is_vis ? __ldg(&g_seg[2]) : (s0 + __ldg(&g_seg[3]));

    if (tid < BM) idx_s[tid] = g_idxc[m0 + tid];
    __syncthreads();

    int a_r[4], a_c[4];
#pragma unroll
    for (int i = 0; i < 4; i++) {
        int t = tid + i * 256;
        a_r[i] = t >> 3;
        a_c[i] = t & 7;
    }
    int a_g[4];
#pragma unroll
    for (int i = 0; i < 4; i++) a_g[i] = idx_s[a_r[i]];
    int b_r[8], b_c[8];
#pragma unroll
    for (int i = 0; i < 8; i++) {
        int t = tid + i * 256;
        b_r[i] = t >> 5;
        b_c[i] = t & 31;
    }

    auto load_stage = [&](int stage, int chunk) {
        uint32_t as = sb + stage * STAGE_BYTES;
        uint32_t bs = as + A_TILE_BYTES;
#pragma unroll
        for (int i = 0; i < 4; i++)
            cp16(as + a_r[i] * AROWB + a_c[i] * 16,
                 A + (size_t)a_g[i] * HID + chunk * BK + a_c[i] * 8);
#pragma unroll
        for (int i = 0; i < 8; i++)
            cp16(bs + b_r[i] * BROWB + b_c[i] * 16,
                 W + (size_t)(chunk * BK + b_r[i]) * N + n0 + b_c[i] * 8);
    };

    const uint32_t a_off = (warp_m * 64 + (lane & 15)) * AROWB + (lane >> 4) * 16;
    const uint32_t b_off = (lane & 15) * BROWB + (lane >> 4) * 16 + warp_n * 128;

    float c[4][8][4];
#pragma unroll
    for (int mt = 0; mt < 4; mt++)
#pragma unroll
        for (int nt = 0; nt < 8; nt++)
#pragma unroll
            for (int j = 0; j < 4; j++) c[mt][nt][j] = 0.f;

    const int NC = HID / BK;  // 64

    load_stage(0, 0); cp_commit();
    load_stage(1, 1); cp_commit();
    load_stage(2, 2); cp_commit();

    uint32_t af[2][4][4], bf[2][8][2];

    for (int ch = 0; ch < NC; ch++) {
        cp_wait<2>();
        __syncthreads();
        if (ch + 3 < NC) load_stage((ch + 3) % STAGES, ch + 3);
        cp_commit();

        const uint32_t as = sb + (ch % STAGES) * STAGE_BYTES;
        const uint32_t aL = as + a_off;
        const uint32_t bL = as + A_TILE_BYTES + b_off;

#pragma unroll
        for (int mt = 0; mt < 4; mt++)
            LDSM4(af[0][mt][0], af[0][mt][1], af[0][mt][2], af[0][mt][3],
                  aL + mt * 16 * AROWB);
#pragma unroll
        for (int pr = 0; pr < 4; pr++)
            LDSM4T(bf[0][2 * pr][0], bf[0][2 * pr][1], bf[0][2 * pr + 1][0], bf[0][2 * pr + 1][1],
                   bL + pr * 32);

#pragma unroll
        for (int ks = 0; ks < 4; ks++) {
            const int cur = ks & 1, nxt = cur ^ 1;
            if (ks < 3) {
#pragma unroll
                for (int mt = 0; mt < 4; mt++)
                    LDSM4(af[nxt][mt][0], af[nxt][mt][1], af[nxt][mt][2], af[nxt][mt][3],
                          aL + mt * 16 * AROWB + (ks + 1) * 32);
#pragma unroll
                for (int pr = 0; pr < 4; pr++)
                    LDSM4T(bf[nxt][2 * pr][0], bf[nxt][2 * pr][1],
                           bf[nxt][2 * pr + 1][0], bf[nxt][2 * pr + 1][1],
                           bL + (ks + 1) * 16 * BROWB + pr * 32);
            }
#pragma unroll
            for (int mt = 0; mt < 4; mt++)
#pragma unroll
                for (int nt = 0; nt < 8; nt++)
                    mma_f16(c[mt][nt], af[cur][mt][0], af[cur][mt][1], af[cur][mt][2], af[cur][mt][3],
                            bf[cur][nt][0], bf[cur][nt][1]);
        }
    }

#pragma unroll
    for (int mt = 0; mt < 4; mt++) {
        int r0 = warp_m * 64 + mt * 16 + lm;
        int r1 = r0 + 8;
        bool on0 = (m0 + r0 < limit);
        bool on1 = (m0 + r1 < limit);
        CT* p0 = C + (size_t)idx_s[r0] * N + n0 + warp_n * 64;
        CT* p1 = C + (size_t)idx_s[r1] * N + n0 + warp_n * 64;
#pragma unroll
        for (int nt = 0; nt < 8; nt++) {
            int col = nt * 8 + 2 * lq;
            if (on0) store2(p0 + col, c[mt][nt][0], c[mt][nt][1]);
            if (on1) store2(p1 + col, c[mt][nt][2], c[mt][nt][3]);
        }
    }
}

// ---------------- RoPE ----------------
__global__ void rope_kernel(const __half* __restrict__ qkv, const int* __restrict__ pos_ids,
                            __half* __restrict__ q, __half* __restrict__ k) {
    int idx = blockIdx.x * blockDim.x + threadIdx.x;
    if (idx >= MTOK * NH * 64) return;
    int i = idx & 63;
    int h = (idx >> 6) & 31;
    int m = idx >> 11;

    float pos = (float)pos_ids[m];
    float freq = expf(-(float)i * (9.210340371976184f / 64.f));
    float ang = pos * freq;
    float cv = cosf(ang);
    float sv = sinf(ang);
    const float scale = 0.088388347648318447f;

    const __half* qs = qkv + (size_t)m * QKVN + h * HD;
    const __half* ks = qs + HID;
    float q0 = __half2float(qs[i]), q1 = __half2float(qs[i + 64]);
    float k0 = __half2float(ks[i]), k1 = __half2float(ks[i + 64]);

    size_t o = (size_t)m * HID + h * HD;
    q[o + i]      = __float2half((q0 * cv - q1 * sv) * scale);
    q[o + i + 64] = __float2half((q1 * cv + q0 * sv) * scale);
    k[o + i]      = __float2half(k0 * cv - k1 * sv);
    k[o + i + 64] = __float2half(k1 * cv + k0 * sv);
}

// ---------------- fp16 flash attention, K-tile 128, double-buffered K/V ----------------
__global__ __launch_bounds__(256)
void attn_mma(const __half* __restrict__ Q, const __half* __restrict__ Kg,
              const __half* __restrict__ Vt, __half* __restrict__ ctx) {
    extern __shared__ char smem[];
    const uint32_t sb = smem_u32(smem);
    const int tid = threadIdx.x;
    const int warp = tid >> 5;
    const int lane = tid & 31;
    const int lm = lane >> 2;
    const int lq = lane & 3;
    const int b = blockIdx.z;
    const int h = blockIdx.y;
    const int qi = (int)gridDim.x - 1 - (int)blockIdx.x;
    const int qb = qi * 128;

    const uint32_t kvb[2] = {sb + AKV0_OFF, sb + AKV1_OFF};

    auto load_tile = [&](int t, int buf) {
        uint32_t kb = kvb[buf];
        uint32_t vb = kvb[buf] + 128 * QROWB;
#pragma unroll
        for (int i = 0; i < 8; i++) {
            int g = tid + i * 256;
            int r = g >> 4, c = g & 15;
            cp16(kb + r * QROWB + c * 16,
                 Kg + (size_t)(b * SEQ + t * 128 + r) * HID + h * HD + c * 8);
        }
#pragma unroll
        for (int i = 0; i < 8; i++) {
            int g = tid + i * 256;
            int r = g >> 4, c = g & 15;
            cp16(vb + r * QROWB + c * 16,
                 Vt + ((size_t)(b * NH + h) * HD + r) * SEQ + t * 128 + c * 8);
        }
    };

#pragma unroll
    for (int i = 0; i < 8; i++) {
        int g = tid + i * 256;
        int r = g >> 4, c = g & 15;
        cp16(sb + AQS_OFF + r * QROWB + c * 16,
             Q + (size_t)(b * SEQ + qb + r) * HID + h * HD + c * 8);
    }
    load_tile(0, 0);
    cp_commit();

    const int a_row = lane & 15;
    const int a_hi  = (lane >> 4) * 16;
    const int b_row = (lane & 7) | ((lane >> 1) & 8);
    const int b_hi  = ((lane >> 3) & 1) * 16;
    const uint32_t qA = sb + AQS_OFF + (warp * 16 + a_row) * QROWB + a_hi;
    const uint32_t pA = sb + APS_OFF + (warp * 16 + a_row) * QROWB + a_hi;
    const uint32_t kOff = b_row * QROWB + b_hi;
    const uint32_t vOff = 128 * QROWB + b_row * QROWB + b_hi;

    float o[16][4];
#pragma unroll
    for (int nt = 0; nt < 16; nt++)
#pragma unroll
        for (int j = 0; j < 4; j++) o[nt][j] = 0.f;
    float mr0 = -1e30f, mr1 = -1e30f, l0 = 0.f, l1 = 0.f;
    const int r0g = qb + warp * 16 + lm;
    const int r1g = r0g + 8;

    const int ntiles = qi + 1;
    for (int t = 0; t < ntiles; t++) {
        const int buf = t & 1;
        if (t + 1 < ntiles) {
            load_tile(t + 1, buf ^ 1);
            cp_commit();
            cp_wait<1>();
        } else {
            cp_wait<0>();
        }
        __syncthreads();

        const uint32_t kB = kvb[buf] + kOff;
        const uint32_t vB = kvb[buf] + vOff;

        float s_[16][4];
#pragma unroll
        for (int nt = 0; nt < 16; nt++)
#pragma unroll
            for (int j = 0; j < 4; j++) s_[nt][j] = 0.f;

#pragma unroll
        for (int ks = 0; ks < 8; ks++) {
            uint32_t a0, a1, a2, a3;
            LDSM4(a0, a1, a2, a3, qA + ks * 32);
#pragma unroll
            for (int pr = 0; pr < 8; pr++) {
                uint32_t b0, b1, b2, b3;
                LDSM4(b0, b1, b2, b3, kB + pr * 16 * QROWB + ks * 32);
                mma_f16(s_[2 * pr],     a0, a1, a2, a3, b0, b1);
                mma_f16(s_[2 * pr + 1], a0, a1, a2, a3, b2, b3);
            }
        }

        if (t == qi) {
#pragma unroll
            for (int nt = 0; nt < 16; nt++) {
                int cb = t * 128 + nt * 8 + 2 * lq;
                if (cb > r0g)     s_[nt][0] = -1e30f;
                if (cb + 1 > r0g) s_[nt][1] = -1e30f;
                if (cb > r1g)     s_[nt][2] = -1e30f;
                if (cb + 1 > r1g) s_[nt][3] = -1e30f;
            }
        }

        float tm0 = -1e30f, tm1 = -1e30f;
#pragma unroll
        for (int nt = 0; nt < 16; nt++) {
            tm0 = fmaxf(tm0, fmaxf(s_[nt][0], s_[nt][1]));
            tm1 = fmaxf(tm1, fmaxf(s_[nt][2], s_[nt][3]));
        }
        tm0 = fmaxf(tm0, __shfl_xor_sync(0xffffffffu, tm0, 1));
        tm0 = fmaxf(tm0, __shfl_xor_sync(0xffffffffu, tm0, 2));
        tm1 = fmaxf(tm1, __shfl_xor_sync(0xffffffffu, tm1, 1));
        tm1 = fmaxf(tm1, __shfl_xor_sync(0xffffffffu, tm1, 2));
        float mn0 = fmaxf(mr0, tm0), mn1 = fmaxf(mr1, tm1);
        float c0 = __expf(mr0 - mn0), c1 = __expf(mr1 - mn1);
        float ps0 = 0.f, ps1 = 0.f;
#pragma unroll
        for (int nt = 0; nt < 16; nt++) {
            s_[nt][0] = __expf(s_[nt][0] - mn0);
            s_[nt][1] = __expf(s_[nt][1] - mn0);
            s_[nt][2] = __expf(s_[nt][2] - mn1);
            s_[nt][3] = __expf(s_[nt][3] - mn1);
            ps0 += s_[nt][0] + s_[nt][1];
            ps1 += s_[nt][2] + s_[nt][3];
        }
        l0 = l0 * c0 + ps0;
        l1 = l1 * c1 + ps1;
#pragma unroll
        for (int nt = 0; nt < 16; nt++) {
            o[nt][0] *= c0; o[nt][1] *= c0;
            o[nt][2] *= c1; o[nt][3] *= c1;
        }
        mr0 = mn0; mr1 = mn1;

#pragma unroll
        for (int nt = 0; nt < 16; nt++) {
            *(__half2*)(smem + APS_OFF + (warp * 16 + lm) * QROWB + (nt * 8 + 2 * lq) * 2)
                = __floats2half2_rn(s_[nt][0], s_[nt][1]);
            *(__half2*)(smem + APS_OFF + (warp * 16 + lm + 8) * QROWB + (nt * 8 + 2 * lq) * 2)
                = __floats2half2_rn(s_[nt][2], s_[nt][3]);
        }
        __syncwarp();

#pragma unroll
        for (int ks = 0; ks < 8; ks++) {
            uint32_t a0, a1, a2, a3;
            LDSM4(a0, a1, a2, a3, pA + ks * 32);
#pragma unroll
            for (int pr = 0; pr < 8; pr++) {
                uint32_t b0, b1, b2, b3;
                LDSM4(b0, b1, b2, b3, vB + pr * 16 * QROWB + ks * 32);
                mma_f16(o[2 * pr],     a0, a1, a2, a3, b0, b1);
                mma_f16(o[2 * pr + 1], a0, a1, a2, a3, b2, b3);
            }
        }
        __syncthreads();
    }

    l0 += __shfl_xor_sync(0xffffffffu, l0, 1);
    l0 += __shfl_xor_sync(0xffffffffu, l0, 2);
    l1 += __shfl_xor_sync(0xffffffffu, l1, 1);
    l1 += __shfl_xor_sync(0xffffffffu, l1, 2);
    float i0 = 1.f / l0, i1 = 1.f / l1;

#pragma unroll
    for (int nt = 0; nt < 16; nt++) {
        int col = nt * 8 + 2 * lq;
        *(__half2*)&ctx[(size_t)(b * SEQ + r0g) * HID + h * HD + col] =
            __floats2half2_rn(o[nt][0] * i0, o[nt][1] * i0);
        *(__half2*)&ctx[(size_t)(b * SEQ + r1g) * HID + h * HD + col] =
            __floats2half2_rn(o[nt][2] * i1, o[nt][3] * i1);
    }
}

// ---------------- launch ----------------
extern "C" void kernel_launch(void* const* d_in, const int* in_sizes, int n_in,
                              void* d_out, int out_size) {
    const float* hidden = (const float*)d_in[0];
    const int*   tt     = (const int*)d_in[1];
    const int*   pos    = (const int*)d_in[2];
    const float* wvq    = (const float*)d_in[3];
    const float* wlq    = (const float*)d_in[4];
    const float* wvd    = (const float*)d_in[5];
    const float* wld    = (const float*)d_in[6];
    float* out = (float*)d_out;

    __half *qkv_p, *q_p, *k_p, *vt_p, *ctx_p, *hidh_p, *wr_p;
    cudaGetSymbolAddress((void**)&qkv_p, g_qkv);
    cudaGetSymbolAddress((void**)&q_p, g_q);
    cudaGetSymbolAddress((void**)&k_p, g_k);
    cudaGetSymbolAddress((void**)&vt_p, g_vt);
    cudaGetSymbolAddress((void**)&ctx_p, g_ctx);
    cudaGetSymbolAddress((void**)&hidh_p, g_hidh);
    cudaGetSymbolAddress((void**)&wr_p, g_wr);

    __half* wr_vq = wr_p + WR_VQ;
    __half* wr_lq = wr_p + WR_LQ;
    __half* wr_vd = wr_p + WR_VD;
    __half* wr_ld = wr_p + WR_LD;

    cudaFuncSetAttribute((const void*)&gemm_tc<__half>, cudaFuncAttributeMaxDynamicSharedMemorySize, GEMM_SMEM);
    cudaFuncSetAttribute((const void*)&gemm_tc<float>, cudaFuncAttributeMaxDynamicSharedMemorySize, GEMM_SMEM);
    cudaFuncSetAttribute(attn_mma, cudaFuncAttributeMaxDynamicSharedMemorySize, ATT_SMEM);

    // lazy one-time creation of side stream + events (first call is the
    // uncaptured correctness run; creation does identical work every call path
    // after that: the same fork/join topology is recorded).
    static cudaStream_t s2 = nullptr;
    static cudaEvent_t ev0 = nullptr, evR = nullptr, ev1 = nullptr, evA = nullptr, evB = nullptr;
    if (s2 == nullptr) {
        cudaStreamCreateWithFlags(&s2, cudaStreamNonBlocking);
        cudaEventCreateWithFlags(&ev0, cudaEventDisableTiming);
        cudaEventCreateWithFlags(&evR, cudaEventDisableTiming);
        cudaEventCreateWithFlags(&ev1, cudaEventDisableTiming);
        cudaEventCreateWithFlags(&evA, cudaEventDisableTiming);
        cudaEventCreateWithFlags(&evB, cudaEventDisableTiming);
    }

    const int n4w = (int)((size_t)HID * QKVN / 4);
    const int n4d = (int)((size_t)HID * HID / 4);
    const int n4h = (int)((size_t)MTOK * HID / 4);

    // fork s2 from the main (legacy) stream
    cudaEventRecord(ev0, 0);
    cudaStreamWaitEvent(s2, ev0, 0);

    // s2 branch: routing + dense-weight conversion (hidden under QKV GEMM)
    zero_cnt_kernel<<<1, 32, 0, s2>>>();
    route_kernel<<<MTOK / 256, 256, 0, s2>>>(tt);
    pack_kernel<<<1, 256, 0, s2>>>();
    cudaEventRecord(evR, s2);
    f2h_kernel<<<(n4d + 255) / 256, 256, 0, s2>>>((const float4*)wvd, (__half2*)wr_vd, n4d);
    f2h_kernel<<<(n4d + 255) / 256, 256, 0, s2>>>((const float4*)wld, (__half2*)wr_ld, n4d);
    cudaEventRecord(evA, s2);

    // main: qkv weights + hidden conversion
    f2h_kernel<<<(n4w + 255) / 256, 256>>>((const float4*)wvq, (__half2*)wr_vq, n4w);
    f2h_kernel<<<(n4w + 255) / 256, 256>>>((const float4*)wlq, (__half2*)wr_lq, n4w);
    f2h_kernel<<<(n4h + 255) / 256, 256>>>((const float4*)hidden, (__half2*)hidh_p, n4h);

    // QKV projection (needs routing from s2)
    cudaStreamWaitEvent(0, evR, 0);
    {
        dim3 grid(MTOK / BM + 2, QKVN / BN);
        gemm_tc<__half><<<grid, 256, GEMM_SMEM>>>(hidh_p, wr_vq, wr_lq, qkv_p, QKVN);
    }
    cudaEventRecord(ev1, 0);

    // rope on main; vtrans in parallel on s2
    rope_kernel<<<(MTOK * NH * 64) / 256, 256>>>(qkv_p, pos, q_p, k_p);
    cudaStreamWaitEvent(s2, ev1, 0);
    {
        dim3 gv(SEQ / 32, HD / 32, BATCH * NH);
        vtrans_kernel<<<gv, 256, 0, s2>>>(qkv_p, vt_p);
    }
    cudaEventRecord(evB, s2);

    // attention (needs rope [main-ordered] + vtrans [evB])
    cudaStreamWaitEvent(0, evB, 0);
    {
        dim3 grid(SEQ / 128, NH, BATCH);
        attn_mma<<<grid, 256, ATT_SMEM>>>(q_p, k_p, vt_p, ctx_p);
    }

    // dense projection (needs dense weights [evA] + ctx [main-ordered])
    cudaStreamWaitEvent(0, evA, 0);
    {
        dim3 grid(MTOK / BM + 2, HID / BN);
        gemm_tc<float><<<grid, 256, GEMM_SMEM>>>(ctx_p, wr_vd, wr_ld, out, HID);
    }
}

// round 17
// speedup vs baseline: 1.9946x; 1.0106x over previous
#include <cuda_runtime.h>
#include <cuda_fp16.h>
#include <math.h>
#include <stdint.h>

// Problem constants
#define BATCH 2
#define SEQ   2048
#define NH    32
#define HD    128
#define HID   4096           // NH*HD
#define QKVN  12288          // 3*HID
#define MTOK  (BATCH*SEQ)    // 4096 tokens

// GEMM tile config (mma.sync m16n8k16 fp16; A ldmatrix, B ldmatrix.trans)
#define BM 128
#define BN 256
#define BK 64
#define STAGES 4
#define AROWB 144
#define BROWB 528
#define A_TILE_BYTES (128 * AROWB)
#define B_TILE_BYTES (64 * BROWB)
#define STAGE_BYTES (A_TILE_BYTES + B_TILE_BYTES)
#define GEMM_SMEM (STAGES * STAGE_BYTES)         // 208896

// Attention smem layout (fp16, K-tile 128, double-buffered K/V)
#define QROWB 272
#define AQS_OFF 0
#define KV_STAGE (256 * QROWB)
#define AKV0_OFF (128 * QROWB)
#define AKV1_OFF (AKV0_OFF + KV_STAGE)
#define APS_OFF (AKV1_OFF + KV_STAGE)
#define ATT_SMEM (APS_OFF + 128 * QROWB)         // 208896

// ---------------- scratch (device globals) -------------
__device__ __half g_qkv[(size_t)MTOK * QKVN];
__device__ __half g_q[(size_t)MTOK * HID];
__device__ __half g_k[(size_t)MTOK * HID];
__device__ __half g_vt[(size_t)BATCH * NH * HD * SEQ];
__device__ __half g_ctx[(size_t)MTOK * HID];
__device__ __half g_hidh[(size_t)MTOK * HID];
#define WR_VQ 0
#define WR_LQ ((size_t)HID * QKVN)
#define WR_VD (2 * (size_t)HID * QKVN)
#define WR_LD (2 * (size_t)HID * QKVN + (size_t)HID * HID)
__device__ __half g_wr[2 * (size_t)HID * QKVN + 2 * (size_t)HID * HID];
__device__ int    g_cnt[2];
__device__ int    g_idx[2][MTOK];
__device__ int    g_idxc[MTOK + 256];
__device__ int    g_seg[4];

// ---------------- helpers ----------------
__device__ __forceinline__ uint32_t smem_u32(const void* p) {
    uint32_t a;
    asm("{ .reg .u64 t; cvta.to.shared.u64 t, %1; cvt.u32.u64 %0, t; }" : "=r"(a) : "l"(p));
    return a;
}
__device__ __forceinline__ void cp16(uint32_t dst, const void* src) {
    asm volatile("cp.async.cg.shared.global [%0], [%1], 16;" :: "r"(dst), "l"(src));
}
__device__ __forceinline__ void cp_commit() {
    asm volatile("cp.async.commit_group;" ::: "memory");
}
template <int N>
__device__ __forceinline__ void cp_wait() {
    asm volatile("cp.async.wait_group %0;" :: "n"(N) : "memory");
}
__device__ __forceinline__ void mma_f16(float* c, uint32_t a0, uint32_t a1, uint32_t a2, uint32_t a3,
                                        uint32_t b0, uint32_t b1) {
    asm volatile(
        "mma.sync.aligned.m16n8k16.row.col.f32.f16.f16.f32 "
        "{%0,%1,%2,%3}, {%4,%5,%6,%7}, {%8,%9}, {%0,%1,%2,%3};"
        : "+f"(c[0]), "+f"(c[1]), "+f"(c[2]), "+f"(c[3])
        : "r"(a0), "r"(a1), "r"(a2), "r"(a3), "r"(b0), "r"(b1));
}
#define LDSM4(r0, r1, r2, r3, addr)                                               \
    asm volatile("ldmatrix.sync.aligned.m8n8.x4.shared.b16 {%0,%1,%2,%3}, [%4];"   \
        : "=r"(r0), "=r"(r1), "=r"(r2), "=r"(r3) : "r"(addr))
#define LDSM4T(r0, r1, r2, r3, addr)                                              \
    asm volatile("ldmatrix.sync.aligned.m8n8.x4.trans.shared.b16 {%0,%1,%2,%3}, [%4];" \
        : "=r"(r0), "=r"(r1), "=r"(r2), "=r"(r3) : "r"(addr))

__device__ __forceinline__ void store2(float* p, float a, float b) {
    *(float2*)p = make_float2(a, b);
}
__device__ __forceinline__ void store2(__half* p, float a, float b) {
    *(__half2*)p = __floats2half2_rn(a, b);
}

// ---------------- fp32 -> fp16 convert (single tensor) ----------------
__global__ __launch_bounds__(256)
void f2h_kernel(const float4* __restrict__ in, __half2* __restrict__ out, int n4) {
    int i = blockIdx.x * blockDim.x + threadIdx.x;
    if (i >= n4) return;
    float4 v = in[i];
    out[2 * i]     = __floats2half2_rn(v.x, v.y);
    out[2 * i + 1] = __floats2half2_rn(v.z, v.w);
}

// V transpose: g_vt[bh][d][s]
__global__ __launch_bounds__(256)
void vtrans_kernel(const __half* __restrict__ qkv, __half* __restrict__ Vt) {
    __shared__ float t[32][33];
    int bh = blockIdx.z;
    int b = bh >> 5, h = bh & 31;
    int s0 = blockIdx.x * 32;
    int d0 = blockIdx.y * 32;
    int x = threadIdx.x & 31;
    int y = threadIdx.x >> 5;
#pragma unroll
    for (int i = 0; i < 32; i += 8)
        t[y + i][x] = __half2float(qkv[(size_t)(b * SEQ + s0 + y + i) * QKVN + 2 * HID + h * HD + d0 + x]);
    __syncthreads();
#pragma unroll
    for (int i = 0; i < 32; i += 8)
        Vt[((size_t)bh * HD + d0 + y + i) * SEQ + s0 + x] = __float2half(t[x][y + i]);
}

// ---------------- mask / routing / packing ----------------
__global__ void zero_cnt_kernel() {
    if (threadIdx.x < 2) g_cnt[threadIdx.x] = 0;
}
__global__ void route_kernel(const int* __restrict__ tt) {
    int idx = blockIdx.x * blockDim.x + threadIdx.x;
    if (idx >= MTOK) return;
    int s = idx & (SEQ - 1);
    int vis = (s + 1 < SEQ) && (tt[idx] == 1) && (tt[idx + 1] == 1);
    int e = vis ? 0 : 1;
    int pos = atomicAdd(&g_cnt[e], 1);
    g_idx[e][pos] = idx;
}
__global__ void pack_kernel() {
    int c0 = g_cnt[0], c1 = g_cnt[1];
    int pad0 = (c0 + 127) & ~127;
    int pad1 = (c1 + 127) & ~127;
    if (threadIdx.x == 0) {
        g_seg[0] = pad0;
        g_seg[1] = pad0 + pad1;
        g_seg[2] = c0;
        g_seg[3] = c1;
    }
    for (int i = threadIdx.x; i < pad0; i += blockDim.x)
        g_idxc[i] = g_idx[0][i < c0 ? i : c0 - 1];
    for (int j = threadIdx.x; j < pad1; j += blockDim.x)
        g_idxc[pad0 + j] = g_idx[1][j < c1 ? j : c1 - 1];
}

// ---------------- merged-expert fp16 GEMM (fragment double-buffered) ----------------
template <typename CT>
__global__ __launch_bounds__(256, 1)
void gemm_tc(const __half* __restrict__ A,
             const __half* __restrict__ Wvis, const __half* __restrict__ Wlang,
             CT* __restrict__ C, int N) {
    __shared__ int idx_s[BM];
    extern __shared__ char smem[];
    const uint32_t sb = smem_u32(smem);
    const int tid = threadIdx.x;
    const int wid = tid >> 5;
    const int lane = tid & 31;
    const int lm = lane >> 2;
    const int lq = lane & 3;
    const int warp_m = wid & 1;
    const int warp_n = wid >> 1;
    const int m0 = blockIdx.x * BM;
    const int n0 = blockIdx.y * BN;

    const int s0 = __ldg(&g_seg[0]);
    const int s1 = __ldg(&g_seg[1]);
    if (m0 >= s1) return;
    const bool is_vis = (m0 < s0);
    const __half* W = is_vis ? Wvis : Wlang;
    const int limit = is_vis ? __ldg(&g_seg[2]) : (s0 + __ldg(&g_seg[3]));

    if (tid < BM) idx_s[tid] = g_idxc[m0 + tid];
    __syncthreads();

    int a_r[4], a_c[4];
#pragma unroll
    for (int i = 0; i < 4; i++) {
        int t = tid + i * 256;
        a_r[i] = t >> 3;
        a_c[i] = t & 7;
    }
    int a_g[4];
#pragma unroll
    for (int i = 0; i < 4; i++) a_g[i] = idx_s[a_r[i]];
    int b_r[8], b_c[8];
#pragma unroll
    for (int i = 0; i < 8; i++) {
        int t = tid + i * 256;
        b_r[i] = t >> 5;
        b_c[i] = t & 31;
    }

    auto load_stage = [&](int stage, int chunk) {
        uint32_t as = sb + stage * STAGE_BYTES;
        uint32_t bs = as + A_TILE_BYTES;
#pragma unroll
        for (int i = 0; i < 4; i++)
            cp16(as + a_r[i] * AROWB + a_c[i] * 16,
                 A + (size_t)a_g[i] * HID + chunk * BK + a_c[i] * 8);
#pragma unroll
        for (int i = 0; i < 8; i++)
            cp16(bs + b_r[i] * BROWB + b_c[i] * 16,
                 W + (size_t)(chunk * BK + b_r[i]) * N + n0 + b_c[i] * 8);
    };

    const uint32_t a_off = (warp_m * 64 + (lane & 15)) * AROWB + (lane >> 4) * 16;
    const uint32_t b_off = (lane & 15) * BROWB + (lane >> 4) * 16 + warp_n * 128;

    float c[4][8][4];
#pragma unroll
    for (int mt = 0; mt < 4; mt++)
#pragma unroll
        for (int nt = 0; nt < 8; nt++)
#pragma unroll
            for (int j = 0; j < 4; j++) c[mt][nt][j] = 0.f;

    const int NC = HID / BK;  // 64

    load_stage(0, 0); cp_commit();
    load_stage(1, 1); cp_commit();
    load_stage(2, 2); cp_commit();

    uint32_t af[2][4][4], bf[2][8][2];

    for (int ch = 0; ch < NC; ch++) {
        cp_wait<2>();
        __syncthreads();
        if (ch + 3 < NC) load_stage((ch + 3) % STAGES, ch + 3);
        cp_commit();

        const uint32_t as = sb + (ch % STAGES) * STAGE_BYTES;
        const uint32_t aL = as + a_off;
        const uint32_t bL = as + A_TILE_BYTES + b_off;

#pragma unroll
        for (int mt = 0; mt < 4; mt++)
            LDSM4(af[0][mt][0], af[0][mt][1], af[0][mt][2], af[0][mt][3],
                  aL + mt * 16 * AROWB);
#pragma unroll
        for (int pr = 0; pr < 4; pr++)
            LDSM4T(bf[0][2 * pr][0], bf[0][2 * pr][1], bf[0][2 * pr + 1][0], bf[0][2 * pr + 1][1],
                   bL + pr * 32);

#pragma unroll
        for (int ks = 0; ks < 4; ks++) {
            const int cur = ks & 1, nxt = cur ^ 1;
            if (ks < 3) {
#pragma unroll
                for (int mt = 0; mt < 4; mt++)
                    LDSM4(af[nxt][mt][0], af[nxt][mt][1], af[nxt][mt][2], af[nxt][mt][3],
                          aL + mt * 16 * AROWB + (ks + 1) * 32);
#pragma unroll
                for (int pr = 0; pr < 4; pr++)
                    LDSM4T(bf[nxt][2 * pr][0], bf[nxt][2 * pr][1],
                           bf[nxt][2 * pr + 1][0], bf[nxt][2 * pr + 1][1],
                           bL + (ks + 1) * 16 * BROWB + pr * 32);
            }
#pragma unroll
            for (int mt = 0; mt < 4; mt++)
#pragma unroll
                for (int nt = 0; nt < 8; nt++)
                    mma_f16(c[mt][nt], af[cur][mt][0], af[cur][mt][1], af[cur][mt][2], af[cur][mt][3],
                            bf[cur][nt][0], bf[cur][nt][1]);
        }
    }

#pragma unroll
    for (int mt = 0; mt < 4; mt++) {
        int r0 = warp_m * 64 + mt * 16 + lm;
        int r1 = r0 + 8;
        bool on0 = (m0 + r0 < limit);
        bool on1 = (m0 + r1 < limit);
        CT* p0 = C + (size_t)idx_s[r0] * N + n0 + warp_n * 64;
        CT* p1 = C + (size_t)idx_s[r1] * N + n0 + warp_n * 64;
#pragma unroll
        for (int nt = 0; nt < 8; nt++) {
            int col = nt * 8 + 2 * lq;
            if (on0) store2(p0 + col, c[mt][nt][0], c[mt][nt][1]);
            if (on1) store2(p1 + col, c[mt][nt][2], c[mt][nt][3]);
        }
    }
}

// ---------------- RoPE ----------------
__global__ void rope_kernel(const __half* __restrict__ qkv, const int* __restrict__ pos_ids,
                            __half* __restrict__ q, __half* __restrict__ k) {
    int idx = blockIdx.x * blockDim.x + threadIdx.x;
    if (idx >= MTOK * NH * 64) return;
    int i = idx & 63;
    int h = (idx >> 6) & 31;
    int m = idx >> 11;

    float pos = (float)pos_ids[m];
    float freq = expf(-(float)i * (9.210340371976184f / 64.f));
    float ang = pos * freq;
    float cv = cosf(ang);
    float sv = sinf(ang);
    const float scale = 0.088388347648318447f;

    const __half* qs = qkv + (size_t)m * QKVN + h * HD;
    const __half* ks = qs + HID;
    float q0 = __half2float(qs[i]), q1 = __half2float(qs[i + 64]);
    float k0 = __half2float(ks[i]), k1 = __half2float(ks[i + 64]);

    size_t o = (size_t)m * HID + h * HD;
    q[o + i]      = __float2half((q0 * cv - q1 * sv) * scale);
    q[o + i + 64] = __float2half((q1 * cv + q0 * sv) * scale);
    k[o + i]      = __float2half(k0 * cv - k1 * sv);
    k[o + i + 64] = __float2half(k1 * cv + k0 * sv);
}

// ---------------- fp16 flash attention, K-tile 128, double-buffered K/V ----------------
__global__ __launch_bounds__(256)
void attn_mma(const __half* __restrict__ Q, const __half* __restrict__ Kg,
              const __half* __restrict__ Vt, __half* __restrict__ ctx) {
    extern __shared__ char smem[];
    const uint32_t sb = smem_u32(smem);
    const int tid = threadIdx.x;
    const int warp = tid >> 5;
    const int lane = tid & 31;
    const int lm = lane >> 2;
    const int lq = lane & 3;
    const int b = blockIdx.z;
    const int h = blockIdx.y;
    const int qi = (int)gridDim.x - 1 - (int)blockIdx.x;
    const int qb = qi * 128;

    const uint32_t kvb[2] = {sb + AKV0_OFF, sb + AKV1_OFF};

    auto load_tile = [&](int t, int buf) {
        uint32_t kb = kvb[buf];
        uint32_t vb = kvb[buf] + 128 * QROWB;
#pragma unroll
        for (int i = 0; i < 8; i++) {
            int g = tid + i * 256;
            int r = g >> 4, c = g & 15;
            cp16(kb + r * QROWB + c * 16,
                 Kg + (size_t)(b * SEQ + t * 128 + r) * HID + h * HD + c * 8);
        }
#pragma unroll
        for (int i = 0; i < 8; i++) {
            int g = tid + i * 256;
            int r = g >> 4, c = g & 15;
            cp16(vb + r * QROWB + c * 16,
                 Vt + ((size_t)(b * NH + h) * HD + r) * SEQ + t * 128 + c * 8);
        }
    };

#pragma unroll
    for (int i = 0; i < 8; i++) {
        int g = tid + i * 256;
        int r = g >> 4, c = g & 15;
        cp16(sb + AQS_OFF + r * QROWB + c * 16,
             Q + (size_t)(b * SEQ + qb + r) * HID + h * HD + c * 8);
    }
    load_tile(0, 0);
    cp_commit();

    const int a_row = lane & 15;
    const int a_hi  = (lane >> 4) * 16;
    const int b_row = (lane & 7) | ((lane >> 1) & 8);
    const int b_hi  = ((lane >> 3) & 1) * 16;
    const uint32_t qA = sb + AQS_OFF + (warp * 16 + a_row) * QROWB + a_hi;
    const uint32_t pA = sb + APS_OFF + (warp * 16 + a_row) * QROWB + a_hi;
    const uint32_t kOff = b_row * QROWB + b_hi;
    const uint32_t vOff = 128 * QROWB + b_row * QROWB + b_hi;

    float o[16][4];
#pragma unroll
    for (int nt = 0; nt < 16; nt++)
#pragma unroll
        for (int j = 0; j < 4; j++) o[nt][j] = 0.f;
    float mr0 = -1e30f, mr1 = -1e30f, l0 = 0.f, l1 = 0.f;
    const int r0g = qb + warp * 16 + lm;
    const int r1g = r0g + 8;

    const int ntiles = qi + 1;
    for (int t = 0; t < ntiles; t++) {
        const int buf = t & 1;
        if (t + 1 < ntiles) {
            load_tile(t + 1, buf ^ 1);
            cp_commit();
            cp_wait<1>();
        } else {
            cp_wait<0>();
        }
        __syncthreads();

        const uint32_t kB = kvb[buf] + kOff;
        const uint32_t vB = kvb[buf] + vOff;

        float s_[16][4];
#pragma unroll
        for (int nt = 0; nt < 16; nt++)
#pragma unroll
            for (int j = 0; j < 4; j++) s_[nt][j] = 0.f;

#pragma unroll
        for (int ks = 0; ks < 8; ks++) {
            uint32_t a0, a1, a2, a3;
            LDSM4(a0, a1, a2, a3, qA + ks * 32);
#pragma unroll
            for (int pr = 0; pr < 8; pr++) {
                uint32_t b0, b1, b2, b3;
                LDSM4(b0, b1, b2, b3, kB + pr * 16 * QROWB + ks * 32);
                mma_f16(s_[2 * pr],     a0, a1, a2, a3, b0, b1);
                mma_f16(s_[2 * pr + 1], a0, a1, a2, a3, b2, b3);
            }
        }

        if (t == qi) {
#pragma unroll
            for (int nt = 0; nt < 16; nt++) {
                int cb = t * 128 + nt * 8 + 2 * lq;
                if (cb > r0g)     s_[nt][0] = -1e30f;
                if (cb + 1 > r0g) s_[nt][1] = -1e30f;
                if (cb > r1g)     s_[nt][2] = -1e30f;
                if (cb + 1 > r1g) s_[nt][3] = -1e30f;
            }
        }

        float tm0 = -1e30f, tm1 = -1e30f;
#pragma unroll
        for (int nt = 0; nt < 16; nt++) {
            tm0 = fmaxf(tm0, fmaxf(s_[nt][0], s_[nt][1]));
            tm1 = fmaxf(tm1, fmaxf(s_[nt][2], s_[nt][3]));
        }
        tm0 = fmaxf(tm0, __shfl_xor_sync(0xffffffffu, tm0, 1));
        tm0 = fmaxf(tm0, __shfl_xor_sync(0xffffffffu, tm0, 2));
        tm1 = fmaxf(tm1, __shfl_xor_sync(0xffffffffu, tm1, 1));
        tm1 = fmaxf(tm1, __shfl_xor_sync(0xffffffffu, tm1, 2));
        float mn0 = fmaxf(mr0, tm0), mn1 = fmaxf(mr1, tm1);
        float c0 = __expf(mr0 - mn0), c1 = __expf(mr1 - mn1);
        float ps0 = 0.f, ps1 = 0.f;
#pragma unroll
        for (int nt = 0; nt < 16; nt++) {
            s_[nt][0] = __expf(s_[nt][0] - mn0);
            s_[nt][1] = __expf(s_[nt][1] - mn0);
            s_[nt][2] = __expf(s_[nt][2] - mn1);
            s_[nt][3] = __expf(s_[nt][3] - mn1);
            ps0 += s_[nt][0] + s_[nt][1];
            ps1 += s_[nt][2] + s_[nt][3];
        }
        l0 = l0 * c0 + ps0;
        l1 = l1 * c1 + ps1;
#pragma unroll
        for (int nt = 0; nt < 16; nt++) {
            o[nt][0] *= c0; o[nt][1] *= c0;
            o[nt][2] *= c1; o[nt][3] *= c1;
        }
        mr0 = mn0; mr1 = mn1;

#pragma unroll
        for (int nt = 0; nt < 16; nt++) {
            *(__half2*)(smem + APS_OFF + (warp * 16 + lm) * QROWB + (nt * 8 + 2 * lq) * 2)
                = __floats2half2_rn(s_[nt][0], s_[nt][1]);
            *(__half2*)(smem + APS_OFF + (warp * 16 + lm + 8) * QROWB + (nt * 8 + 2 * lq) * 2)
                = __floats2half2_rn(s_[nt][2], s_[nt][3]);
        }
        __syncwarp();

#pragma unroll
        for (int ks = 0; ks < 8; ks++) {
            uint32_t a0, a1, a2, a3;
            LDSM4(a0, a1, a2, a3, pA + ks * 32);
#pragma unroll
            for (int pr = 0; pr < 8; pr++) {
                uint32_t b0, b1, b2, b3;
                LDSM4(b0, b1, b2, b3, vB + pr * 16 * QROWB + ks * 32);
                mma_f16(o[2 * pr],     a0, a1, a2, a3, b0, b1);
                mma_f16(o[2 * pr + 1], a0, a1, a2, a3, b2, b3);
            }
        }
        __syncthreads();
    }

    l0 += __shfl_xor_sync(0xffffffffu, l0, 1);
    l0 += __shfl_xor_sync(0xffffffffu, l0, 2);
    l1 += __shfl_xor_sync(0xffffffffu, l1, 1);
    l1 += __shfl_xor_sync(0xffffffffu, l1, 2);
    float i0 = 1.f / l0, i1 = 1.f / l1;

#pragma unroll
    for (int nt = 0; nt < 16; nt++) {
        int col = nt * 8 + 2 * lq;
        *(__half2*)&ctx[(size_t)(b * SEQ + r0g) * HID + h * HD + col] =
            __floats2half2_rn(o[nt][0] * i0, o[nt][1] * i0);
        *(__half2*)&ctx[(size_t)(b * SEQ + r1g) * HID + h * HD + col] =
            __floats2half2_rn(o[nt][2] * i1, o[nt][3] * i1);
    }
}

// ---------------- launch ----------------
extern "C" void kernel_launch(void* const* d_in, const int* in_sizes, int n_in,
                              void* d_out, int out_size) {
    const float* hidden = (const float*)d_in[0];
    const int*   tt     = (const int*)d_in[1];
    const int*   pos    = (const int*)d_in[2];
    const float* wvq    = (const float*)d_in[3];
    const float* wlq    = (const float*)d_in[4];
    const float* wvd    = (const float*)d_in[5];
    const float* wld    = (const float*)d_in[6];
    float* out = (float*)d_out;

    __half *qkv_p, *q_p, *k_p, *vt_p, *ctx_p, *hidh_p, *wr_p;
    cudaGetSymbolAddress((void**)&qkv_p, g_qkv);
    cudaGetSymbolAddress((void**)&q_p, g_q);
    cudaGetSymbolAddress((void**)&k_p, g_k);
    cudaGetSymbolAddress((void**)&vt_p, g_vt);
    cudaGetSymbolAddress((void**)&ctx_p, g_ctx);
    cudaGetSymbolAddress((void**)&hidh_p, g_hidh);
    cudaGetSymbolAddress((void**)&wr_p, g_wr);

    __half* wr_vq = wr_p + WR_VQ;
    __half* wr_lq = wr_p + WR_LQ;
    __half* wr_vd = wr_p + WR_VD;
    __half* wr_ld = wr_p + WR_LD;

    cudaFuncSetAttribute((const void*)&gemm_tc<__half>, cudaFuncAttributeMaxDynamicSharedMemorySize, GEMM_SMEM);
    cudaFuncSetAttribute((const void*)&gemm_tc<float>, cudaFuncAttributeMaxDynamicSharedMemorySize, GEMM_SMEM);
    cudaFuncSetAttribute(attn_mma, cudaFuncAttributeMaxDynamicSharedMemorySize, ATT_SMEM);

    static cudaStream_t s2 = nullptr;
    static cudaEvent_t ev0 = nullptr, evR = nullptr, evF = nullptr, ev1 = nullptr,
                       evA = nullptr, evB = nullptr;
    if (s2 == nullptr) {
        cudaStreamCreateWithFlags(&s2, cudaStreamNonBlocking);
        cudaEventCreateWithFlags(&ev0, cudaEventDisableTiming);
        cudaEventCreateWithFlags(&evR, cudaEventDisableTiming);
        cudaEventCreateWithFlags(&evF, cudaEventDisableTiming);
        cudaEventCreateWithFlags(&ev1, cudaEventDisableTiming);
        cudaEventCreateWithFlags(&evA, cudaEventDisableTiming);
        cudaEventCreateWithFlags(&evB, cudaEventDisableTiming);
    }

    const int n4w = (int)((size_t)HID * QKVN / 4);
    const int n4d = (int)((size_t)HID * HID / 4);
    const int n4h = (int)((size_t)MTOK * HID / 4);

    // fork s2 from the main (legacy) stream
    cudaEventRecord(ev0, 0);
    cudaStreamWaitEvent(s2, ev0, 0);

    // s2 branch: routing only (tiny, ALU-bound, harmless alongside f2h)
    zero_cnt_kernel<<<1, 32, 0, s2>>>();
    route_kernel<<<MTOK / 256, 256, 0, s2>>>(tt);
    pack_kernel<<<1, 256, 0, s2>>>();
    cudaEventRecord(evR, s2);

    // main: qkv weights + hidden conversion (DRAM-bound, exclusive)
    f2h_kernel<<<(n4w + 255) / 256, 256>>>((const float4*)wvq, (__half2*)wr_vq, n4w);
    f2h_kernel<<<(n4w + 255) / 256, 256>>>((const float4*)wlq, (__half2*)wr_lq, n4w);
    f2h_kernel<<<(n4h + 255) / 256, 256>>>((const float4*)hidden, (__half2*)hidh_p, n4h);
    cudaEventRecord(evF, 0);

    // s2: dense-weight conversion AFTER main f2h done -> runs under the
    // compute-bound QKV GEMM whose DRAM is mostly idle
    cudaStreamWaitEvent(s2, evF, 0);
    f2h_kernel<<<(n4d + 255) / 256, 256, 0, s2>>>((const float4*)wvd, (__half2*)wr_vd, n4d);
    f2h_kernel<<<(n4d + 255) / 256, 256, 0, s2>>>((const float4*)wld, (__half2*)wr_ld, n4d);
    cudaEventRecord(evA, s2);

    // QKV projection (needs routing from s2)
    cudaStreamWaitEvent(0, evR, 0);
    {
        dim3 grid(MTOK / BM + 2, QKVN / BN);
        gemm_tc<__half><<<grid, 256, GEMM_SMEM>>>(hidh_p, wr_vq, wr_lq, qkv_p, QKVN);
    }
    cudaEventRecord(ev1, 0);

    // rope on main; vtrans in parallel on s2
    rope_kernel<<<(MTOK * NH * 64) / 256, 256>>>(qkv_p, pos, q_p, k_p);
    cudaStreamWaitEvent(s2, ev1, 0);
    {
        dim3 gv(SEQ / 32, HD / 32, BATCH * NH);
        vtrans_kernel<<<gv, 256, 0, s2>>>(qkv_p, vt_p);
    }
    cudaEventRecord(evB, s2);

    // attention (needs rope [main-ordered] + vtrans [evB])
    cudaStreamWaitEvent(0, evB, 0);
    {
        dim3 grid(SEQ / 128, NH, BATCH);
        attn_mma<<<grid, 256, ATT_SMEM>>>(q_p, k_p, vt_p, ctx_p);
    }

    // dense projection (needs dense weights [evA] + ctx [main-ordered])
    cudaStreamWaitEvent(0, evA, 0);
    {
        dim3 grid(MTOK / BM + 2, HID / BN);
        gemm_tc<float><<<grid, 256, GEMM_SMEM>>>(ctx_p, wr_vd, wr_ld, out, HID);
    }
}